// round 1
// baseline (speedup 1.0000x reference)
#include <cuda_runtime.h>
#include <math.h>
#include <stdint.h>

#define BB 2
#define SS 2048
#define DD 1024
#define NH 16
#define HD 64
#define TT (BB*SS)        // 4096 tokens
#define INNER 4096

// ------------------------- scratch (device globals; no cudaMalloc allowed) ---
__device__ float g_h[(size_t)TT*DD];          // 16 MB : rmsnorm out, later attn out
__device__ float g_q[(size_t)TT*DD];          // 16 MB : q, later hf
__device__ float g_k[(size_t)TT*DD];          // 16 MB
__device__ float g_v[(size_t)TT*DD];          // 16 MB
__device__ float g_scores[(size_t)BB*NH*SS*SS]; // 536 MB
__device__ float g_gate[(size_t)TT*INNER];    // 64 MB
__device__ float g_up[(size_t)TT*INNER];      // 64 MB

// ------------------------------------------------------------------ rmsnorm --
__global__ void rmsnorm_kernel(const float* __restrict__ x,
                               const float* __restrict__ w,
                               float* __restrict__ o) {
    __shared__ float red[8];
    const int row = blockIdx.x;
    const float* xr = x + (size_t)row * DD;
    float vals[4];
    float ss = 0.f;
#pragma unroll
    for (int i = 0; i < 4; i++) {
        vals[i] = xr[threadIdx.x + i * 256];
        ss += vals[i] * vals[i];
    }
#pragma unroll
    for (int off = 16; off; off >>= 1) ss += __shfl_xor_sync(0xffffffffu, ss, off);
    if ((threadIdx.x & 31) == 0) red[threadIdx.x >> 5] = ss;
    __syncthreads();
    if (threadIdx.x < 32) {
        float s2 = (threadIdx.x < 8) ? red[threadIdx.x] : 0.f;
#pragma unroll
        for (int off = 4; off; off >>= 1) s2 += __shfl_xor_sync(0xffffffffu, s2, off);
        if (threadIdx.x == 0) red[0] = s2;
    }
    __syncthreads();
    const float rms = rsqrtf(red[0] * (1.0f / DD) + 1e-6f);
    float* orow = o + (size_t)row * DD;
#pragma unroll
    for (int i = 0; i < 4; i++) {
        const int c = threadIdx.x + i * 256;
        orow[c] = vals[i] * rms * w[c];
    }
}

// --------------------------------------------------------------- dense GEMM --
// C[M,N] = A[M,K] @ B[K,N]  (+ residual R if WITH_RES). M%128==0, N%128==0, K%16==0.
template <bool WITH_RES>
__global__ void __launch_bounds__(256) sgemm_nn(const float* __restrict__ A,
                                                const float* __restrict__ Bm,
                                                const float* __restrict__ R,
                                                float* __restrict__ C,
                                                int M, int N, int K) {
    __shared__ float As[16][132];
    __shared__ float Bs[16][132];
    const int tid = threadIdx.x;
    const int bm = blockIdx.y * 128, bn = blockIdx.x * 128;
    const int tx = tid & 15, ty = tid >> 4;
    float acc[8][8] = {};
    for (int k0 = 0; k0 < K; k0 += 16) {
#pragma unroll
        for (int i = 0; i < 2; i++) {
            const int idx = (tid + i * 256) << 2;           // 0..2044
            const int m  = idx >> 4, kk = idx & 15;
            const float4 a = *reinterpret_cast<const float4*>(A + (size_t)(bm + m) * K + k0 + kk);
            As[kk + 0][m] = a.x; As[kk + 1][m] = a.y; As[kk + 2][m] = a.z; As[kk + 3][m] = a.w;
            const int kb = idx >> 7, nb = idx & 127;
            const float4 b = *reinterpret_cast<const float4*>(Bm + (size_t)(k0 + kb) * N + bn + nb);
            *reinterpret_cast<float4*>(&Bs[kb][nb]) = b;
        }
        __syncthreads();
#pragma unroll
        for (int kk = 0; kk < 16; kk++) {
            float ra[8], rb[8];
#pragma unroll
            for (int i = 0; i < 8; i++) ra[i] = As[kk][ty * 8 + i];
#pragma unroll
            for (int j = 0; j < 8; j++) rb[j] = Bs[kk][tx * 8 + j];
#pragma unroll
            for (int i = 0; i < 8; i++)
#pragma unroll
                for (int j = 0; j < 8; j++) acc[i][j] = fmaf(ra[i], rb[j], acc[i][j]);
        }
        __syncthreads();
    }
#pragma unroll
    for (int i = 0; i < 8; i++) {
        const size_t off = (size_t)(bm + ty * 8 + i) * N + bn + tx * 8;
#pragma unroll
        for (int j = 0; j < 8; j++) {
            float vv = acc[i][j];
            if (WITH_RES) vv += R[off + j];
            C[off + j] = vv;
        }
    }
}

// ---------------------------------------------------------------------- rope --
// X laid out (t, h, d) with d contiguous (row stride DD). rf: (S, HD/2, 2) cos/sin.
__global__ void rope_kernel(float* __restrict__ X, const float* __restrict__ rf) {
    const int idx = blockIdx.x * blockDim.x + threadIdx.x;   // TT*NH*32
    if (idx >= TT * NH * (HD / 2)) return;
    const int i = idx & 31;
    const int hh = (idx >> 5) & (NH - 1);
    const int t = idx >> 9;
    const int s = t & (SS - 1);
    const float2 cs = *reinterpret_cast<const float2*>(rf + ((size_t)s * 32 + i) * 2);
    float2* p = reinterpret_cast<float2*>(X + (size_t)t * DD + hh * HD + 2 * i);
    const float2 xv = *p;
    float2 ov;
    ov.x = xv.x * cs.x - xv.y * cs.y;
    ov.y = xv.x * cs.y + xv.y * cs.x;
    *p = ov;
}

// -------------------------------------------------------------- attn scores --
// P[bh, s, t] = scale * q[b,s,h,:]·k[b,t,h,:]; masked (-inf) for t>s; blocks with
// all t>s are skipped entirely (never read downstream).
__global__ void __launch_bounds__(256) attn_scores(const float* __restrict__ Q,
                                                   const float* __restrict__ Kt,
                                                   float* __restrict__ P) {
    const int bh = blockIdx.z;
    const int bm = blockIdx.y * 128, bn = blockIdx.x * 128;
    if (bn > bm + 127) return;                         // fully above diagonal
    const int b = bh >> 4, hh = bh & 15;
    __shared__ float As[16][132];
    __shared__ float Bs[16][132];
    const float* Qb = Q + (size_t)b * SS * DD + hh * HD;
    const float* Kb = Kt + (size_t)b * SS * DD + hh * HD;
    const int tid = threadIdx.x, tx = tid & 15, ty = tid >> 4;
    float acc[8][8] = {};
    for (int k0 = 0; k0 < HD; k0 += 16) {
#pragma unroll
        for (int i = 0; i < 2; i++) {
            const int idx = (tid + i * 256) << 2;
            const int m = idx >> 4, kk = idx & 15;
            const float4 a = *reinterpret_cast<const float4*>(Qb + (size_t)(bm + m) * DD + k0 + kk);
            As[kk + 0][m] = a.x; As[kk + 1][m] = a.y; As[kk + 2][m] = a.z; As[kk + 3][m] = a.w;
            const float4 bv = *reinterpret_cast<const float4*>(Kb + (size_t)(bn + m) * DD + k0 + kk);
            Bs[kk + 0][m] = bv.x; Bs[kk + 1][m] = bv.y; Bs[kk + 2][m] = bv.z; Bs[kk + 3][m] = bv.w;
        }
        __syncthreads();
#pragma unroll
        for (int kk = 0; kk < 16; kk++) {
            float ra[8], rb[8];
#pragma unroll
            for (int i = 0; i < 8; i++) ra[i] = As[kk][ty * 8 + i];
#pragma unroll
            for (int j = 0; j < 8; j++) rb[j] = Bs[kk][tx * 8 + j];
#pragma unroll
            for (int i = 0; i < 8; i++)
#pragma unroll
                for (int j = 0; j < 8; j++) acc[i][j] = fmaf(ra[i], rb[j], acc[i][j]);
        }
        __syncthreads();
    }
    float* Pb = P + (size_t)bh * SS * SS;
    const float scale = 0.125f;                        // 1/sqrt(64)
#pragma unroll
    for (int i = 0; i < 8; i++) {
        const int s = bm + ty * 8 + i;
#pragma unroll
        for (int j = 0; j < 8; j++) {
            const int t = bn + tx * 8 + j;
            Pb[(size_t)s * SS + t] = (t <= s) ? acc[i][j] * scale : -INFINITY;
        }
    }
}

// ------------------------------------------------------------------ softmax --
// One block per (bh, s) row; valid cols [0, s], zeros written beyond.
__global__ void softmax_kernel(float* __restrict__ P) {
    __shared__ float red[8];
    const size_t row = blockIdx.x;
    const int s = (int)(row & (SS - 1));
    float* p = P + row * SS;
    float v[8];
    float mx = -INFINITY;
#pragma unroll
    for (int i = 0; i < 8; i++) {
        const int t = threadIdx.x + i * 256;
        v[i] = (t <= s) ? p[t] : -INFINITY;
        mx = fmaxf(mx, v[i]);
    }
#pragma unroll
    for (int off = 16; off; off >>= 1) mx = fmaxf(mx, __shfl_xor_sync(0xffffffffu, mx, off));
    if ((threadIdx.x & 31) == 0) red[threadIdx.x >> 5] = mx;
    __syncthreads();
    if (threadIdx.x < 32) {
        float m2 = (threadIdx.x < 8) ? red[threadIdx.x] : -INFINITY;
#pragma unroll
        for (int off = 4; off; off >>= 1) m2 = fmaxf(m2, __shfl_xor_sync(0xffffffffu, m2, off));
        if (threadIdx.x == 0) red[0] = m2;
    }
    __syncthreads();
    mx = red[0];
    __syncthreads();
    float sum = 0.f;
#pragma unroll
    for (int i = 0; i < 8; i++) {
        const int t = threadIdx.x + i * 256;
        v[i] = (t <= s) ? __expf(v[i] - mx) : 0.f;
        sum += v[i];
    }
#pragma unroll
    for (int off = 16; off; off >>= 1) sum += __shfl_xor_sync(0xffffffffu, sum, off);
    if ((threadIdx.x & 31) == 0) red[threadIdx.x >> 5] = sum;
    __syncthreads();
    if (threadIdx.x < 32) {
        float s2 = (threadIdx.x < 8) ? red[threadIdx.x] : 0.f;
#pragma unroll
        for (int off = 4; off; off >>= 1) s2 += __shfl_xor_sync(0xffffffffu, s2, off);
        if (threadIdx.x == 0) red[0] = s2;
    }
    __syncthreads();
    const float inv = 1.0f / red[0];
#pragma unroll
    for (int i = 0; i < 8; i++) p[threadIdx.x + i * 256] = v[i] * inv;
}

// ----------------------------------------------------------------- P @ V -----
// O[b,s,h,:] = sum_t P[bh,s,t] * v[b,t,h,:]; K-loop bounded by causality.
__global__ void __launch_bounds__(256) attn_pv(const float* __restrict__ P,
                                               const float* __restrict__ V,
                                               float* __restrict__ O) {
    const int bh = blockIdx.z, b = bh >> 4, hh = bh & 15;
    const int bm = blockIdx.y * 128;
    __shared__ float As[16][132];
    __shared__ float Bs[16][68];
    const float* Pb = P + (size_t)bh * SS * SS;
    const float* Vb = V + (size_t)b * SS * DD + hh * HD;
    const int tid = threadIdx.x, tx = tid & 15, ty = tid >> 4;
    float acc[8][4] = {};
    const int kmax = bm + 128;                // rows t>s are exact zeros already
    for (int k0 = 0; k0 < kmax; k0 += 16) {
#pragma unroll
        for (int i = 0; i < 2; i++) {
            const int idx = (tid + i * 256) << 2;
            const int m = idx >> 4, kk = idx & 15;
            const float4 a = *reinterpret_cast<const float4*>(Pb + (size_t)(bm + m) * SS + k0 + kk);
            As[kk + 0][m] = a.x; As[kk + 1][m] = a.y; As[kk + 2][m] = a.z; As[kk + 3][m] = a.w;
        }
        {
            const int idx = tid << 2;         // 0..1020
            const int kk = idx >> 6, n = idx & 63;
            const float4 bv = *reinterpret_cast<const float4*>(Vb + (size_t)(k0 + kk) * DD + n);
            *reinterpret_cast<float4*>(&Bs[kk][n]) = bv;
        }
        __syncthreads();
#pragma unroll
        for (int kk = 0; kk < 16; kk++) {
            float ra[8], rb[4];
#pragma unroll
            for (int i = 0; i < 8; i++) ra[i] = As[kk][ty * 8 + i];
#pragma unroll
            for (int j = 0; j < 4; j++) rb[j] = Bs[kk][tx * 4 + j];
#pragma unroll
            for (int i = 0; i < 8; i++)
#pragma unroll
                for (int j = 0; j < 4; j++) acc[i][j] = fmaf(ra[i], rb[j], acc[i][j]);
        }
        __syncthreads();
    }
    float* Ob = O + (size_t)b * SS * DD + hh * HD;
#pragma unroll
    for (int i = 0; i < 8; i++) {
        const size_t off = (size_t)(bm + ty * 8 + i) * DD + tx * 4;
#pragma unroll
        for (int j = 0; j < 4; j++) Ob[off + j] = acc[i][j];
    }
}

// ----------------------------------------------------------------- silu*up ---
__global__ void silu_mul_kernel(float* __restrict__ g, const float* __restrict__ u) {
    const size_t i = (size_t)blockIdx.x * blockDim.x + threadIdx.x;
    const float gv = g[i];
    g[i] = gv / (1.f + __expf(-gv)) * u[i];
}

// ------------------------------------------------------------------- launch --
extern "C" void kernel_launch(void* const* d_in, const int* in_sizes, int n_in,
                              void* d_out, int out_size) {
    const float* x   = (const float*)d_in[0];
    const float* rf  = (const float*)d_in[1];
    // d_in[2] = mask (ignored; causality applied analytically)
    const float* anw = (const float*)d_in[3];
    const float* fnw = (const float*)d_in[4];
    const float* wq  = (const float*)d_in[5];
    const float* wk  = (const float*)d_in[6];
    const float* wv  = (const float*)d_in[7];
    const float* wo  = (const float*)d_in[8];
    const float* wg  = (const float*)d_in[9];
    const float* wu  = (const float*)d_in[10];
    const float* wd  = (const float*)d_in[11];
    float* out = (float*)d_out;

    float *h, *q, *k, *v, *sc, *gt, *up;
    cudaGetSymbolAddress((void**)&h,  g_h);
    cudaGetSymbolAddress((void**)&q,  g_q);
    cudaGetSymbolAddress((void**)&k,  g_k);
    cudaGetSymbolAddress((void**)&v,  g_v);
    cudaGetSymbolAddress((void**)&sc, g_scores);
    cudaGetSymbolAddress((void**)&gt, g_gate);
    cudaGetSymbolAddress((void**)&up, g_up);

    // 1) attn rmsnorm
    rmsnorm_kernel<<<TT, 256>>>(x, anw, h);
    // 2) QKV projections
    sgemm_nn<false><<<dim3(DD / 128, TT / 128), 256>>>(h, wq, nullptr, q, TT, DD, DD);
    sgemm_nn<false><<<dim3(DD / 128, TT / 128), 256>>>(h, wk, nullptr, k, TT, DD, DD);
    sgemm_nn<false><<<dim3(DD / 128, TT / 128), 256>>>(h, wv, nullptr, v, TT, DD, DD);
    // 3) rope on q, k
    const int nrope = TT * NH * (HD / 2);
    rope_kernel<<<nrope / 256, 256>>>(q, rf);
    rope_kernel<<<nrope / 256, 256>>>(k, rf);
    // 4) attention
    attn_scores<<<dim3(SS / 128, SS / 128, BB * NH), 256>>>(q, k, sc);
    softmax_kernel<<<BB * NH * SS, 256>>>(sc);
    attn_pv<<<dim3(1, SS / 128, BB * NH), 256>>>(sc, v, h);   // h reused as attn out
    // 5) output projection + residual -> out holds x_after_attn
    sgemm_nn<true><<<dim3(DD / 128, TT / 128), 256>>>(h, wo, x, out, TT, DD, DD);
    // 6) ffn rmsnorm (q reused as hf)
    rmsnorm_kernel<<<TT, 256>>>(out, fnw, q);
    // 7) gate / up
    sgemm_nn<false><<<dim3(INNER / 128, TT / 128), 256>>>(q, wg, nullptr, gt, TT, INNER, DD);
    sgemm_nn<false><<<dim3(INNER / 128, TT / 128), 256>>>(q, wu, nullptr, up, TT, INNER, DD);
    // 8) silu(gate) * up (in-place into gt)
    silu_mul_kernel<<<(TT * (size_t)INNER) / 256, 256>>>(gt, up);
    // 9) down projection + residual
    sgemm_nn<true><<<dim3(DD / 128, TT / 128), 256>>>(gt, wd, out, out, TT, DD, INNER);
}

// round 5
// speedup vs baseline: 1.6262x; 1.6262x over previous
#include <cuda_runtime.h>
#include <cuda_bf16.h>
#include <math.h>
#include <stdint.h>

#define BB 2
#define SS 2048
#define DD 1024
#define NH 16
#define HD 64
#define TT (BB*SS)        // 4096 tokens
#define INNER 4096

// ===================== scratch (device globals; no cudaMalloc) ===============
__device__ __align__(256) float g_q[(size_t)TT*DD];            // 16 MB
__device__ __align__(256) float g_k[(size_t)TT*DD];            // 16 MB
__device__ __align__(256) float g_v[(size_t)TT*DD];            // 16 MB
__device__ __align__(256) float g_scores[(size_t)BB*NH*SS*SS]; // 536 MB
__device__ __align__(256) float g_gate[(size_t)TT*INNER];      // 64 MB
__device__ __align__(256) float g_up[(size_t)TT*INNER];        // 64 MB
// split-bf16 activation buffers (A operand of GEMMs), max K = 4096
__device__ __align__(256) __nv_bfloat16 g_ahi[(size_t)TT*INNER];
__device__ __align__(256) __nv_bfloat16 g_alo[(size_t)TT*INNER];
// split-bf16 transposed weights [N,K]
__device__ __align__(256) __nv_bfloat16 g_wqh[1024*1024], g_wql[1024*1024];
__device__ __align__(256) __nv_bfloat16 g_wkh[1024*1024], g_wkl[1024*1024];
__device__ __align__(256) __nv_bfloat16 g_wvh[1024*1024], g_wvl[1024*1024];
__device__ __align__(256) __nv_bfloat16 g_woh[1024*1024], g_wol[1024*1024];
__device__ __align__(256) __nv_bfloat16 g_wgh[(size_t)4096*1024], g_wgl[(size_t)4096*1024];
__device__ __align__(256) __nv_bfloat16 g_wuh[(size_t)4096*1024], g_wul[(size_t)4096*1024];
__device__ __align__(256) __nv_bfloat16 g_wdh[(size_t)1024*4096], g_wdl[(size_t)1024*4096];

// ============================== PTX helpers ==================================
__device__ __forceinline__ uint32_t smem_u32(const void* p) {
    uint32_t a;
    asm("{ .reg .u64 t; cvta.to.shared.u64 t, %1; cvt.u32.u64 %0, t; }" : "=r"(a) : "l"(p));
    return a;
}
__device__ __forceinline__ void cp16(uint32_t dst, const void* src) {
    asm volatile("cp.async.cg.shared.global [%0], [%1], 16;\n" :: "r"(dst), "l"(src));
}
__device__ __forceinline__ void cp_commit() { asm volatile("cp.async.commit_group;\n" ::: "memory"); }
template <int N> __device__ __forceinline__ void cp_wait() {
    asm volatile("cp.async.wait_group %0;\n" :: "n"(N) : "memory");
}
__device__ __forceinline__ void ldm4(uint32_t* r, uint32_t addr) {
    asm volatile("ldmatrix.sync.aligned.m8n8.x4.shared.b16 {%0,%1,%2,%3}, [%4];"
        : "=r"(r[0]), "=r"(r[1]), "=r"(r[2]), "=r"(r[3]) : "r"(addr));
}
__device__ __forceinline__ void mma16816(float* c, const uint32_t* a, uint32_t b0, uint32_t b1) {
    asm volatile("mma.sync.aligned.m16n8k16.row.col.f32.bf16.bf16.f32 "
        "{%0,%1,%2,%3}, {%4,%5,%6,%7}, {%8,%9}, {%0,%1,%2,%3};"
        : "+f"(c[0]), "+f"(c[1]), "+f"(c[2]), "+f"(c[3])
        : "r"(a[0]), "r"(a[1]), "r"(a[2]), "r"(a[3]), "r"(b0), "r"(b1));
}

// ====================== HMMA split-bf16 GEMM =================================
// C[M,N] = (Ahi+Alo)[M,K] @ (Bhi+Blo)[N,K]^T + R, fp32 accum.
// 3 terms: hi*hi + hi*lo + lo*hi. CTA tile 128x128, warp tile 32x64, Kc=32.
#define KC 32
#define LDA 40                       // padded row (bf16): 80B, conflict-free ldmatrix
#define TILE_B (128*LDA*2)           // 10240 B
#define HSTAGE_B (4*TILE_B)          // Ahi,Alo,Bhi,Blo = 40960 B
#define HG_DSM (2*HSTAGE_B)          // 81920 B

__global__ void __launch_bounds__(256, 1) hgemm_split(
    const __nv_bfloat16* __restrict__ Ahi, const __nv_bfloat16* __restrict__ Alo,
    const __nv_bfloat16* __restrict__ Bhi, const __nv_bfloat16* __restrict__ Blo,
    const float* __restrict__ R, float* __restrict__ C, int M, int N, int K)
{
    extern __shared__ __align__(16) char smem[];
    const int tid = threadIdx.x;
    const int lane = tid & 31, wid = tid >> 5;
    const int wm = wid >> 1, wn = wid & 1;          // 4x2 warp grid
    const int bm = blockIdx.x * 128, bn = blockIdx.y * 128;
    const uint32_t sbase = smem_u32(smem);

    float acc[2][8][4] = {};

    // ---- loader mapping: each tile = 512 16B chunks; thread does chunks
    // tid and tid+256. chunk c: row = c>>2, 16B column = c&3.
    const int r0_ = tid >> 2,            c0_ = tid & 3;
    const int r1_ = (tid + 256) >> 2,    c1_ = c0_;           // (tid+256)&3 == tid&3
    const uint32_t d0 = (uint32_t)(r0_ * LDA * 2 + c0_ * 16);
    const uint32_t d1 = (uint32_t)(r1_ * LDA * 2 + c1_ * 16);
    const size_t a0 = (size_t)(bm + r0_) * K + c0_ * 8;
    const size_t a1 = (size_t)(bm + r1_) * K + c1_ * 8;
    const size_t b0 = (size_t)(bn + r0_) * K + c0_ * 8;
    const size_t b1 = (size_t)(bn + r1_) * K + c1_ * 8;

#define LOAD_STAGE(st, k0)                                              \
    do {                                                                \
        const uint32_t sb_ = sbase + (st) * HSTAGE_B;                   \
        cp16(sb_ + d0,              Ahi + a0 + (k0));                   \
        cp16(sb_ + d1,              Ahi + a1 + (k0));                   \
        cp16(sb_ + TILE_B + d0,     Alo + a0 + (k0));                   \
        cp16(sb_ + TILE_B + d1,     Alo + a1 + (k0));                   \
        cp16(sb_ + 2*TILE_B + d0,   Bhi + b0 + (k0));                   \
        cp16(sb_ + 2*TILE_B + d1,   Bhi + b1 + (k0));                   \
        cp16(sb_ + 3*TILE_B + d0,   Blo + b0 + (k0));                   \
        cp16(sb_ + 3*TILE_B + d1,   Blo + b1 + (k0));                   \
        cp_commit();                                                    \
    } while (0)

    const int NCK = K / KC;
    LOAD_STAGE(0, 0);
    LOAD_STAGE(1, KC);

    // ldmatrix lane offset (row = lane&15, col8 = lane>>4)
    const uint32_t lmoff = (uint32_t)((lane & 15) * LDA + (lane >> 4) * 8) * 2;
    const uint32_t aRowOff = (uint32_t)(wm * 32) * LDA * 2;
    const uint32_t bRowOff = (uint32_t)(wn * 64) * LDA * 2;

    for (int kc = 0; kc < NCK; kc++) {
        if (kc < NCK - 1) cp_wait<1>(); else cp_wait<0>();
        __syncthreads();
        const uint32_t sb = sbase + (kc & 1) * HSTAGE_B;
#pragma unroll
        for (int kk = 0; kk < 2; kk++) {
            const uint32_t koff = kk * 32;     // 16 bf16 = 32 B
            uint32_t ah[2][4], al[2][4], bh[4][4], bl[4][4];
#pragma unroll
            for (int mf = 0; mf < 2; mf++) {
                const uint32_t a = sb + aRowOff + (uint32_t)(mf * 16) * LDA * 2 + koff + lmoff;
                ldm4(ah[mf], a);
                ldm4(al[mf], a + TILE_B);
            }
#pragma unroll
            for (int np = 0; np < 4; np++) {
                const uint32_t b = sb + 2 * TILE_B + bRowOff + (uint32_t)(np * 16) * LDA * 2 + koff + lmoff;
                ldm4(bh[np], b);
                ldm4(bl[np], b + TILE_B);
            }
#pragma unroll
            for (int mf = 0; mf < 2; mf++)
#pragma unroll
                for (int np = 0; np < 4; np++) {
                    mma16816(acc[mf][2*np],   ah[mf], bh[np][0], bh[np][2]);
                    mma16816(acc[mf][2*np+1], ah[mf], bh[np][1], bh[np][3]);
                    mma16816(acc[mf][2*np],   ah[mf], bl[np][0], bl[np][2]);
                    mma16816(acc[mf][2*np+1], ah[mf], bl[np][1], bl[np][3]);
                    mma16816(acc[mf][2*np],   al[mf], bh[np][0], bh[np][2]);
                    mma16816(acc[mf][2*np+1], al[mf], bh[np][1], bh[np][3]);
                }
        }
        __syncthreads();
        if (kc + 2 < NCK) LOAD_STAGE(kc & 1, (kc + 2) * KC);
    }
#undef LOAD_STAGE

    // ---- epilogue ----
#pragma unroll
    for (int mf = 0; mf < 2; mf++)
#pragma unroll
        for (int nf = 0; nf < 8; nf++) {
            const int row0 = bm + wm * 32 + mf * 16 + (lane >> 2);
            const int col  = bn + wn * 64 + nf * 8 + (lane & 3) * 2;
            const size_t o0 = (size_t)row0 * N + col;
            const size_t o1 = o0 + (size_t)8 * N;
            float2 v0 = make_float2(acc[mf][nf][0], acc[mf][nf][1]);
            float2 v1 = make_float2(acc[mf][nf][2], acc[mf][nf][3]);
            if (R) {
                const float2 r0 = *reinterpret_cast<const float2*>(R + o0);
                const float2 r1 = *reinterpret_cast<const float2*>(R + o1);
                v0.x += r0.x; v0.y += r0.y; v1.x += r1.x; v1.y += r1.y;
            }
            *reinterpret_cast<float2*>(C + o0) = v0;
            *reinterpret_cast<float2*>(C + o1) = v1;
        }
}

// =================== weight transpose + bf16 split ===========================
// W[K,N] f32 -> hi/lo [N,K] bf16
__global__ void __launch_bounds__(256) wconv_kernel(const float* __restrict__ W,
        __nv_bfloat16* __restrict__ hi, __nv_bfloat16* __restrict__ lo, int K, int N) {
    __shared__ float t[32][33];
    const int bx = blockIdx.x * 32;   // N dir
    const int by = blockIdx.y * 32;   // K dir
    const int tx = threadIdx.x & 31, ty = threadIdx.x >> 5;
#pragma unroll
    for (int i = 0; i < 4; i++) {
        const int ky = ty + i * 8;
        t[ky][tx] = W[(size_t)(by + ky) * N + bx + tx];
    }
    __syncthreads();
#pragma unroll
    for (int i = 0; i < 4; i++) {
        const int ny = ty + i * 8;
        const float v = t[tx][ny];
        const __nv_bfloat16 h = __float2bfloat16(v);
        const size_t o = (size_t)(bx + ny) * K + by + tx;
        hi[o] = h;
        lo[o] = __float2bfloat16(v - __bfloat162float(h));
    }
}

// ============================ rmsnorm -> bf16 split ==========================
__global__ void rmsnorm_split(const float* __restrict__ x, const float* __restrict__ w,
                              __nv_bfloat16* __restrict__ hi, __nv_bfloat16* __restrict__ lo) {
    __shared__ float red[8];
    const int row = blockIdx.x;
    const float* xr = x + (size_t)row * DD;
    float vals[4];
    float ss = 0.f;
#pragma unroll
    for (int i = 0; i < 4; i++) {
        vals[i] = xr[threadIdx.x + i * 256];
        ss += vals[i] * vals[i];
    }
#pragma unroll
    for (int off = 16; off; off >>= 1) ss += __shfl_xor_sync(0xffffffffu, ss, off);
    if ((threadIdx.x & 31) == 0) red[threadIdx.x >> 5] = ss;
    __syncthreads();
    if (threadIdx.x < 32) {
        float s2 = (threadIdx.x < 8) ? red[threadIdx.x] : 0.f;
#pragma unroll
        for (int off = 4; off; off >>= 1) s2 += __shfl_xor_sync(0xffffffffu, s2, off);
        if (threadIdx.x == 0) red[0] = s2;
    }
    __syncthreads();
    const float rms = rsqrtf(red[0] * (1.0f / DD) + 1e-6f);
#pragma unroll
    for (int i = 0; i < 4; i++) {
        const int c = threadIdx.x + i * 256;
        const float v = vals[i] * rms * w[c];
        const __nv_bfloat16 h = __float2bfloat16(v);
        const size_t o = (size_t)row * DD + c;
        hi[o] = h;
        lo[o] = __float2bfloat16(v - __bfloat162float(h));
    }
}

// ================================= rope ======================================
__global__ void rope_kernel(float* __restrict__ X, const float* __restrict__ rf) {
    const int idx = blockIdx.x * blockDim.x + threadIdx.x;
    if (idx >= TT * NH * (HD / 2)) return;
    const int i = idx & 31;
    const int hh = (idx >> 5) & (NH - 1);
    const int t = idx >> 9;
    const int s = t & (SS - 1);
    const float2 cs = *reinterpret_cast<const float2*>(rf + ((size_t)s * 32 + i) * 2);
    float2* p = reinterpret_cast<float2*>(X + (size_t)t * DD + hh * HD + 2 * i);
    const float2 xv = *p;
    float2 ov;
    ov.x = xv.x * cs.x - xv.y * cs.y;
    ov.y = xv.x * cs.y + xv.y * cs.x;
    *p = ov;
}

// ============================= attn scores (fp32) ============================
__global__ void __launch_bounds__(256) attn_scores(const float* __restrict__ Q,
                                                   const float* __restrict__ Kt,
                                                   float* __restrict__ P) {
    const int bh = blockIdx.z;
    const int bm = blockIdx.y * 128, bn = blockIdx.x * 128;
    if (bn > bm + 127) return;
    const int b = bh >> 4, hh = bh & 15;
    __shared__ float As[16][132];
    __shared__ float Bs[16][132];
    const float* Qb = Q + (size_t)b * SS * DD + hh * HD;
    const float* Kb = Kt + (size_t)b * SS * DD + hh * HD;
    const int tid = threadIdx.x, tx = tid & 15, ty = tid >> 4;
    float acc[8][8] = {};
    for (int k0 = 0; k0 < HD; k0 += 16) {
#pragma unroll
        for (int i = 0; i < 2; i++) {
            const int idx = (tid + i * 256) << 2;
            const int m = idx >> 4, kk = idx & 15;
            const float4 a = *reinterpret_cast<const float4*>(Qb + (size_t)(bm + m) * DD + k0 + kk);
            As[kk + 0][m] = a.x; As[kk + 1][m] = a.y; As[kk + 2][m] = a.z; As[kk + 3][m] = a.w;
            const float4 bv = *reinterpret_cast<const float4*>(Kb + (size_t)(bn + m) * DD + k0 + kk);
            Bs[kk + 0][m] = bv.x; Bs[kk + 1][m] = bv.y; Bs[kk + 2][m] = bv.z; Bs[kk + 3][m] = bv.w;
        }
        __syncthreads();
#pragma unroll
        for (int kk = 0; kk < 16; kk++) {
            float ra[8], rb[8];
#pragma unroll
            for (int i = 0; i < 8; i++) ra[i] = As[kk][ty * 8 + i];
#pragma unroll
            for (int j = 0; j < 8; j++) rb[j] = Bs[kk][tx * 8 + j];
#pragma unroll
            for (int i = 0; i < 8; i++)
#pragma unroll
                for (int j = 0; j < 8; j++) acc[i][j] = fmaf(ra[i], rb[j], acc[i][j]);
        }
        __syncthreads();
    }
    float* Pb = P + (size_t)bh * SS * SS;
    const float scale = 0.125f;
#pragma unroll
    for (int i = 0; i < 8; i++) {
        const int s = bm + ty * 8 + i;
#pragma unroll
        for (int j = 0; j < 8; j++) {
            const int t = bn + tx * 8 + j;
            Pb[(size_t)s * SS + t] = (t <= s) ? acc[i][j] * scale : -INFINITY;
        }
    }
}

// ================================ softmax ====================================
__global__ void softmax_kernel(float* __restrict__ P) {
    __shared__ float red[8];
    const size_t row = blockIdx.x;
    const int s = (int)(row & (SS - 1));
    float* p = P + row * SS;
    float v[8];
    float mx = -INFINITY;
#pragma unroll
    for (int i = 0; i < 8; i++) {
        const int t = threadIdx.x + i * 256;
        v[i] = (t <= s) ? p[t] : -INFINITY;
        mx = fmaxf(mx, v[i]);
    }
#pragma unroll
    for (int off = 16; off; off >>= 1) mx = fmaxf(mx, __shfl_xor_sync(0xffffffffu, mx, off));
    if ((threadIdx.x & 31) == 0) red[threadIdx.x >> 5] = mx;
    __syncthreads();
    if (threadIdx.x < 32) {
        float m2 = (threadIdx.x < 8) ? red[threadIdx.x] : -INFINITY;
#pragma unroll
        for (int off = 4; off; off >>= 1) m2 = fmaxf(m2, __shfl_xor_sync(0xffffffffu, m2, off));
        if (threadIdx.x == 0) red[0] = m2;
    }
    __syncthreads();
    mx = red[0];
    __syncthreads();
    float sum = 0.f;
#pragma unroll
    for (int i = 0; i < 8; i++) {
        const int t = threadIdx.x + i * 256;
        v[i] = (t <= s) ? __expf(v[i] - mx) : 0.f;
        sum += v[i];
    }
#pragma unroll
    for (int off = 16; off; off >>= 1) sum += __shfl_xor_sync(0xffffffffu, sum, off);
    if ((threadIdx.x & 31) == 0) red[threadIdx.x >> 5] = sum;
    __syncthreads();
    if (threadIdx.x < 32) {
        float s2 = (threadIdx.x < 8) ? red[threadIdx.x] : 0.f;
#pragma unroll
        for (int off = 4; off; off >>= 1) s2 += __shfl_xor_sync(0xffffffffu, s2, off);
        if (threadIdx.x == 0) red[0] = s2;
    }
    __syncthreads();
    const float inv = 1.0f / red[0];
#pragma unroll
    for (int i = 0; i < 8; i++) p[threadIdx.x + i * 256] = v[i] * inv;
}

// ============================== P @ V (fp32) =================================
// Output written as split-bf16 (A operand of the wo GEMM).
__global__ void __launch_bounds__(256) attn_pv(const float* __restrict__ P,
                                               const float* __restrict__ V,
                                               __nv_bfloat16* __restrict__ Ohi,
                                               __nv_bfloat16* __restrict__ Olo) {
    const int bh = blockIdx.z, b = bh >> 4, hh = bh & 15;
    const int bm = blockIdx.y * 128;
    __shared__ float As[16][132];
    __shared__ float Bs[16][68];
    const float* Pb = P + (size_t)bh * SS * SS;
    const float* Vb = V + (size_t)b * SS * DD + hh * HD;
    const int tid = threadIdx.x, tx = tid & 15, ty = tid >> 4;
    float acc[8][4] = {};
    const int kmax = bm + 128;
    for (int k0 = 0; k0 < kmax; k0 += 16) {
#pragma unroll
        for (int i = 0; i < 2; i++) {
            const int idx = (tid + i * 256) << 2;
            const int m = idx >> 4, kk = idx & 15;
            const float4 a = *reinterpret_cast<const float4*>(Pb + (size_t)(bm + m) * SS + k0 + kk);
            As[kk + 0][m] = a.x; As[kk + 1][m] = a.y; As[kk + 2][m] = a.z; As[kk + 3][m] = a.w;
        }
        {
            const int idx = tid << 2;
            const int kk = idx >> 6, n = idx & 63;
            const float4 bv = *reinterpret_cast<const float4*>(Vb + (size_t)(k0 + kk) * DD + n);
            *reinterpret_cast<float4*>(&Bs[kk][n]) = bv;
        }
        __syncthreads();
#pragma unroll
        for (int kk = 0; kk < 16; kk++) {
            float ra[8], rb[4];
#pragma unroll
            for (int i = 0; i < 8; i++) ra[i] = As[kk][ty * 8 + i];
#pragma unroll
            for (int j = 0; j < 4; j++) rb[j] = Bs[kk][tx * 4 + j];
#pragma unroll
            for (int i = 0; i < 8; i++)
#pragma unroll
                for (int j = 0; j < 4; j++) acc[i][j] = fmaf(ra[i], rb[j], acc[i][j]);
        }
        __syncthreads();
    }
    __nv_bfloat16* Oh = Ohi + (size_t)b * SS * DD + hh * HD;
    __nv_bfloat16* Ol = Olo + (size_t)b * SS * DD + hh * HD;
#pragma unroll
    for (int i = 0; i < 8; i++) {
        const size_t off = (size_t)(bm + ty * 8 + i) * DD + tx * 4;
#pragma unroll
        for (int j = 0; j < 4; j++) {
            const float v = acc[i][j];
            const __nv_bfloat16 h = __float2bfloat16(v);
            Oh[off + j] = h;
            Ol[off + j] = __float2bfloat16(v - __bfloat162float(h));
        }
    }
}

// ========================= silu(gate)*up -> bf16 split =======================
__global__ void silu_mul_split(const float* __restrict__ g, const float* __restrict__ u,
                               __nv_bfloat16* __restrict__ hi, __nv_bfloat16* __restrict__ lo) {
    const size_t i = (size_t)blockIdx.x * blockDim.x + threadIdx.x;
    const float gv = g[i];
    const float r = gv / (1.f + __expf(-gv)) * u[i];
    const __nv_bfloat16 h = __float2bfloat16(r);
    hi[i] = h;
    lo[i] = __float2bfloat16(r - __bfloat162float(h));
}

// ================================= launch ====================================
extern "C" void kernel_launch(void* const* d_in, const int* in_sizes, int n_in,
                              void* d_out, int out_size) {
    const float* x   = (const float*)d_in[0];
    const float* rf  = (const float*)d_in[1];
    // d_in[2] = mask (causality applied analytically)
    const float* anw = (const float*)d_in[3];
    const float* fnw = (const float*)d_in[4];
    const float* wq  = (const float*)d_in[5];
    const float* wk  = (const float*)d_in[6];
    const float* wv  = (const float*)d_in[7];
    const float* wo  = (const float*)d_in[8];
    const float* wg  = (const float*)d_in[9];
    const float* wu  = (const float*)d_in[10];
    const float* wd  = (const float*)d_in[11];
    float* out = (float*)d_out;

    float *q, *k, *v, *sc, *gt, *up;
    __nv_bfloat16 *ahi, *alo;
    __nv_bfloat16 *wqh, *wql, *wkh, *wkl, *wvh, *wvl, *woh, *wol;
    __nv_bfloat16 *wgh, *wgl, *wuh, *wul, *wdh, *wdl;
    cudaGetSymbolAddress((void**)&q,  g_q);
    cudaGetSymbolAddress((void**)&k,  g_k);
    cudaGetSymbolAddress((void**)&v,  g_v);
    cudaGetSymbolAddress((void**)&sc, g_scores);
    cudaGetSymbolAddress((void**)&gt, g_gate);
    cudaGetSymbolAddress((void**)&up, g_up);
    cudaGetSymbolAddress((void**)&ahi, g_ahi);
    cudaGetSymbolAddress((void**)&alo, g_alo);
    cudaGetSymbolAddress((void**)&wqh, g_wqh); cudaGetSymbolAddress((void**)&wql, g_wql);
    cudaGetSymbolAddress((void**)&wkh, g_wkh); cudaGetSymbolAddress((void**)&wkl, g_wkl);
    cudaGetSymbolAddress((void**)&wvh, g_wvh); cudaGetSymbolAddress((void**)&wvl, g_wvl);
    cudaGetSymbolAddress((void**)&woh, g_woh); cudaGetSymbolAddress((void**)&wol, g_wol);
    cudaGetSymbolAddress((void**)&wgh, g_wgh); cudaGetSymbolAddress((void**)&wgl, g_wgl);
    cudaGetSymbolAddress((void**)&wuh, g_wuh); cudaGetSymbolAddress((void**)&wul, g_wul);
    cudaGetSymbolAddress((void**)&wdh, g_wdh); cudaGetSymbolAddress((void**)&wdl, g_wdl);

    cudaFuncSetAttribute(hgemm_split, cudaFuncAttributeMaxDynamicSharedMemorySize, HG_DSM);

    // weight conversion (transpose + split)
    wconv_kernel<<<dim3(1024/32, 1024/32), 256>>>(wq, wqh, wql, 1024, 1024);
    wconv_kernel<<<dim3(1024/32, 1024/32), 256>>>(wk, wkh, wkl, 1024, 1024);
    wconv_kernel<<<dim3(1024/32, 1024/32), 256>>>(wv, wvh, wvl, 1024, 1024);
    wconv_kernel<<<dim3(1024/32, 1024/32), 256>>>(wo, woh, wol, 1024, 1024);
    wconv_kernel<<<dim3(4096/32, 1024/32), 256>>>(wg, wgh, wgl, 1024, 4096);
    wconv_kernel<<<dim3(4096/32, 1024/32), 256>>>(wu, wuh, wul, 1024, 4096);
    wconv_kernel<<<dim3(1024/32, 4096/32), 256>>>(wd, wdh, wdl, 4096, 1024);

    // 1) attn rmsnorm -> split-bf16 activations
    rmsnorm_split<<<TT, 256>>>(x, anw, ahi, alo);
    // 2) QKV projections (HMMA split-bf16)
    hgemm_split<<<dim3(TT/128, 1024/128), 256, HG_DSM>>>(ahi, alo, wqh, wql, nullptr, q, TT, 1024, 1024);
    hgemm_split<<<dim3(TT/128, 1024/128), 256, HG_DSM>>>(ahi, alo, wkh, wkl, nullptr, k, TT, 1024, 1024);
    hgemm_split<<<dim3(TT/128, 1024/128), 256, HG_DSM>>>(ahi, alo, wvh, wvl, nullptr, v, TT, 1024, 1024);
    // 3) rope
    const int nrope = TT * NH * (HD / 2);
    rope_kernel<<<nrope / 256, 256>>>(q, rf);
    rope_kernel<<<nrope / 256, 256>>>(k, rf);
    // 4) attention (fp32 SIMT)
    attn_scores<<<dim3(SS / 128, SS / 128, BB * NH), 256>>>(q, k, sc);
    softmax_kernel<<<BB * NH * SS, 256>>>(sc);
    attn_pv<<<dim3(1, SS / 128, BB * NH), 256>>>(sc, v, ahi, alo);  // attn out -> split bf16
    // 5) output projection + residual
    hgemm_split<<<dim3(TT/128, 1024/128), 256, HG_DSM>>>(ahi, alo, woh, wol, x, out, TT, 1024, 1024);
    // 6) ffn rmsnorm
    rmsnorm_split<<<TT, 256>>>(out, fnw, ahi, alo);
    // 7) gate / up
    hgemm_split<<<dim3(TT/128, 4096/128), 256, HG_DSM>>>(ahi, alo, wgh, wgl, nullptr, gt, TT, 4096, 1024);
    hgemm_split<<<dim3(TT/128, 4096/128), 256, HG_DSM>>>(ahi, alo, wuh, wul, nullptr, up, TT, 4096, 1024);
    // 8) silu * up -> split bf16
    silu_mul_split<<<(int)(((size_t)TT * INNER) / 256), 256>>>(gt, up, ahi, alo);
    // 9) down projection + residual
    hgemm_split<<<dim3(TT/128, 1024/128), 256, HG_DSM>>>(ahi, alo, wdh, wdl, out, out, TT, 1024, 4096);
}

// round 6
// speedup vs baseline: 2.0117x; 1.2371x over previous
#include <cuda_runtime.h>
#include <cuda_bf16.h>
#include <math.h>
#include <stdint.h>

#define BB 2
#define SS 2048
#define DD 1024
#define NH 16
#define HD 64
#define TT (BB*SS)        // 4096 tokens
#define INNER 4096

// ===================== scratch (device globals; no cudaMalloc) ===============
__device__ __align__(256) float g_q[(size_t)TT*DD];            // 16 MB
__device__ __align__(256) float g_k[(size_t)TT*DD];            // 16 MB
__device__ __align__(256) float g_v[(size_t)TT*DD];            // 16 MB
__device__ __align__(256) float g_scores[(size_t)BB*NH*SS*SS]; // 536 MB
__device__ __align__(256) float g_gate[(size_t)TT*INNER];      // 64 MB
__device__ __align__(256) float g_up[(size_t)TT*INNER];        // 64 MB
// split-bf16 activation buffers (A operand of GEMMs), max K = 4096
__device__ __align__(256) __nv_bfloat16 g_ahi[(size_t)TT*INNER];
__device__ __align__(256) __nv_bfloat16 g_alo[(size_t)TT*INNER];
// split-bf16 roped Q/K and transposed V
__device__ __align__(256) __nv_bfloat16 g_qsh[(size_t)TT*DD], g_qsl[(size_t)TT*DD];
__device__ __align__(256) __nv_bfloat16 g_ksh[(size_t)TT*DD], g_ksl[(size_t)TT*DD];
__device__ __align__(256) __nv_bfloat16 g_vth[(size_t)TT*DD], g_vtl[(size_t)TT*DD];
// split-bf16 transposed weights [N,K]
__device__ __align__(256) __nv_bfloat16 g_wqh[1024*1024], g_wql[1024*1024];
__device__ __align__(256) __nv_bfloat16 g_wkh[1024*1024], g_wkl[1024*1024];
__device__ __align__(256) __nv_bfloat16 g_wvh[1024*1024], g_wvl[1024*1024];
__device__ __align__(256) __nv_bfloat16 g_woh[1024*1024], g_wol[1024*1024];
__device__ __align__(256) __nv_bfloat16 g_wgh[(size_t)4096*1024], g_wgl[(size_t)4096*1024];
__device__ __align__(256) __nv_bfloat16 g_wuh[(size_t)4096*1024], g_wul[(size_t)4096*1024];
__device__ __align__(256) __nv_bfloat16 g_wdh[(size_t)1024*4096], g_wdl[(size_t)1024*4096];

// ============================== PTX helpers ==================================
__device__ __forceinline__ uint32_t smem_u32(const void* p) {
    uint32_t a;
    asm("{ .reg .u64 t; cvta.to.shared.u64 t, %1; cvt.u32.u64 %0, t; }" : "=r"(a) : "l"(p));
    return a;
}
__device__ __forceinline__ void cp16(uint32_t dst, const void* src) {
    asm volatile("cp.async.cg.shared.global [%0], [%1], 16;\n" :: "r"(dst), "l"(src));
}
__device__ __forceinline__ void cp_commit() { asm volatile("cp.async.commit_group;\n" ::: "memory"); }
template <int N> __device__ __forceinline__ void cp_wait() {
    asm volatile("cp.async.wait_group %0;\n" :: "n"(N) : "memory");
}
__device__ __forceinline__ void ldm4(uint32_t* r, uint32_t addr) {
    asm volatile("ldmatrix.sync.aligned.m8n8.x4.shared.b16 {%0,%1,%2,%3}, [%4];"
        : "=r"(r[0]), "=r"(r[1]), "=r"(r[2]), "=r"(r[3]) : "r"(addr));
}
__device__ __forceinline__ void mma16816(float* c, const uint32_t* a, uint32_t b0, uint32_t b1) {
    asm volatile("mma.sync.aligned.m16n8k16.row.col.f32.bf16.bf16.f32 "
        "{%0,%1,%2,%3}, {%4,%5,%6,%7}, {%8,%9}, {%0,%1,%2,%3};"
        : "+f"(c[0]), "+f"(c[1]), "+f"(c[2]), "+f"(c[3])
        : "r"(a[0]), "r"(a[1]), "r"(a[2]), "r"(a[3]), "r"(b0), "r"(b1));
}
__device__ __forceinline__ void split_bf16(float v, __nv_bfloat16& h, __nv_bfloat16& l) {
    h = __float2bfloat16(v);
    l = __float2bfloat16(v - __bfloat162float(h));
}

// ====================== HMMA split-bf16 dense GEMM ===========================
// C[M,N] = (Ahi+Alo)[M,K] @ (Bhi+Blo)[N,K]^T + R, fp32 accum.
#define KC 32
#define LDA 40
#define TILE_B (128*LDA*2)           // 10240 B
#define HSTAGE_B (4*TILE_B)          // 40960 B
#define HG_DSM (2*HSTAGE_B)          // 81920 B

__global__ void __launch_bounds__(256, 1) hgemm_split(
    const __nv_bfloat16* __restrict__ Ahi, const __nv_bfloat16* __restrict__ Alo,
    const __nv_bfloat16* __restrict__ Bhi, const __nv_bfloat16* __restrict__ Blo,
    const float* __restrict__ R, float* __restrict__ C, int M, int N, int K)
{
    extern __shared__ __align__(16) char smem[];
    const int tid = threadIdx.x;
    const int lane = tid & 31, wid = tid >> 5;
    const int wm = wid >> 1, wn = wid & 1;
    const int bm = blockIdx.x * 128, bn = blockIdx.y * 128;
    const uint32_t sbase = smem_u32(smem);

    float acc[2][8][4] = {};

    const int r0_ = tid >> 2,            c0_ = tid & 3;
    const int r1_ = (tid + 256) >> 2,    c1_ = c0_;
    const uint32_t d0 = (uint32_t)(r0_ * LDA * 2 + c0_ * 16);
    const uint32_t d1 = (uint32_t)(r1_ * LDA * 2 + c1_ * 16);
    const size_t a0 = (size_t)(bm + r0_) * K + c0_ * 8;
    const size_t a1 = (size_t)(bm + r1_) * K + c1_ * 8;
    const size_t b0 = (size_t)(bn + r0_) * K + c0_ * 8;
    const size_t b1 = (size_t)(bn + r1_) * K + c1_ * 8;

#define LOAD_STAGE(st, k0)                                              \
    do {                                                                \
        const uint32_t sb_ = sbase + (st) * HSTAGE_B;                   \
        cp16(sb_ + d0,              Ahi + a0 + (k0));                   \
        cp16(sb_ + d1,              Ahi + a1 + (k0));                   \
        cp16(sb_ + TILE_B + d0,     Alo + a0 + (k0));                   \
        cp16(sb_ + TILE_B + d1,     Alo + a1 + (k0));                   \
        cp16(sb_ + 2*TILE_B + d0,   Bhi + b0 + (k0));                   \
        cp16(sb_ + 2*TILE_B + d1,   Bhi + b1 + (k0));                   \
        cp16(sb_ + 3*TILE_B + d0,   Blo + b0 + (k0));                   \
        cp16(sb_ + 3*TILE_B + d1,   Blo + b1 + (k0));                   \
        cp_commit();                                                    \
    } while (0)

    const int NCK = K / KC;
    LOAD_STAGE(0, 0);
    LOAD_STAGE(1, KC);

    const uint32_t lmoff = (uint32_t)((lane & 15) * LDA + (lane >> 4) * 8) * 2;
    const uint32_t aRowOff = (uint32_t)(wm * 32) * LDA * 2;
    const uint32_t bRowOff = (uint32_t)(wn * 64) * LDA * 2;

    for (int kc = 0; kc < NCK; kc++) {
        if (kc < NCK - 1) cp_wait<1>(); else cp_wait<0>();
        __syncthreads();
        const uint32_t sb = sbase + (kc & 1) * HSTAGE_B;
#pragma unroll
        for (int kk = 0; kk < 2; kk++) {
            const uint32_t koff = kk * 32;
            uint32_t ah[2][4], al[2][4], bh[4][4], bl[4][4];
#pragma unroll
            for (int mf = 0; mf < 2; mf++) {
                const uint32_t a = sb + aRowOff + (uint32_t)(mf * 16) * LDA * 2 + koff + lmoff;
                ldm4(ah[mf], a);
                ldm4(al[mf], a + TILE_B);
            }
#pragma unroll
            for (int np = 0; np < 4; np++) {
                const uint32_t b = sb + 2 * TILE_B + bRowOff + (uint32_t)(np * 16) * LDA * 2 + koff + lmoff;
                ldm4(bh[np], b);
                ldm4(bl[np], b + TILE_B);
            }
#pragma unroll
            for (int mf = 0; mf < 2; mf++)
#pragma unroll
                for (int np = 0; np < 4; np++) {
                    mma16816(acc[mf][2*np],   ah[mf], bh[np][0], bh[np][2]);
                    mma16816(acc[mf][2*np+1], ah[mf], bh[np][1], bh[np][3]);
                    mma16816(acc[mf][2*np],   ah[mf], bl[np][0], bl[np][2]);
                    mma16816(acc[mf][2*np+1], ah[mf], bl[np][1], bl[np][3]);
                    mma16816(acc[mf][2*np],   al[mf], bh[np][0], bh[np][2]);
                    mma16816(acc[mf][2*np+1], al[mf], bh[np][1], bh[np][3]);
                }
        }
        __syncthreads();
        if (kc + 2 < NCK) LOAD_STAGE(kc & 1, (kc + 2) * KC);
    }
#undef LOAD_STAGE

#pragma unroll
    for (int mf = 0; mf < 2; mf++)
#pragma unroll
        for (int nf = 0; nf < 8; nf++) {
            const int row0 = bm + wm * 32 + mf * 16 + (lane >> 2);
            const int col  = bn + wn * 64 + nf * 8 + (lane & 3) * 2;
            const size_t o0 = (size_t)row0 * N + col;
            const size_t o1 = o0 + (size_t)8 * N;
            float2 v0 = make_float2(acc[mf][nf][0], acc[mf][nf][1]);
            float2 v1 = make_float2(acc[mf][nf][2], acc[mf][nf][3]);
            if (R) {
                const float2 r0 = *reinterpret_cast<const float2*>(R + o0);
                const float2 r1 = *reinterpret_cast<const float2*>(R + o1);
                v0.x += r0.x; v0.y += r0.y; v1.x += r1.x; v1.y += r1.y;
            }
            *reinterpret_cast<float2*>(C + o0) = v0;
            *reinterpret_cast<float2*>(C + o1) = v1;
        }
}

// ===================== HMMA split-bf16 attention scores ======================
// P[bh,s,t] = q·k (q pre-scaled); blocks fully above diagonal skipped.
#define SLDA 72
#define STILE (128*SLDA*2)            // 18432 B
#define SC_DSM (4*STILE)              // 73728 B

__global__ void __launch_bounds__(256, 2) attn_scores_hmma(
    const __nv_bfloat16* __restrict__ qh, const __nv_bfloat16* __restrict__ ql,
    const __nv_bfloat16* __restrict__ kh, const __nv_bfloat16* __restrict__ kl,
    float* __restrict__ P)
{
    const int bh = blockIdx.z;
    const int bm = blockIdx.y * 128, bn = blockIdx.x * 128;
    if (bn > bm + 127) return;
    const int b = bh >> 4, hh = bh & 15;
    extern __shared__ __align__(16) char smem[];
    const uint32_t sb = smem_u32(smem);
    const int tid = threadIdx.x, lane = tid & 31, wid = tid >> 5;
    const int wm = wid >> 1, wn = wid & 1;

    const __nv_bfloat16* Qh = qh + (size_t)b * SS * DD + hh * HD;
    const __nv_bfloat16* Ql = ql + (size_t)b * SS * DD + hh * HD;
    const __nv_bfloat16* Kh = kh + (size_t)b * SS * DD + hh * HD;
    const __nv_bfloat16* Kl = kl + (size_t)b * SS * DD + hh * HD;

#pragma unroll
    for (int i = 0; i < 4; i++) {                 // 1024 chunks per tile
        const int id = tid + (i << 8);
        const int r = id >> 3, c = id & 7;
        const uint32_t d = (uint32_t)(r * SLDA * 2 + c * 16);
        cp16(sb + d,            Qh + (size_t)(bm + r) * DD + c * 8);
        cp16(sb + STILE + d,    Ql + (size_t)(bm + r) * DD + c * 8);
        cp16(sb + 2*STILE + d,  Kh + (size_t)(bn + r) * DD + c * 8);
        cp16(sb + 3*STILE + d,  Kl + (size_t)(bn + r) * DD + c * 8);
    }
    cp_commit();
    cp_wait<0>();
    __syncthreads();

    float acc[2][8][4] = {};
    const uint32_t lmoff = (uint32_t)((lane & 15) * SLDA + (lane >> 4) * 8) * 2;
    const uint32_t aRowOff = (uint32_t)(wm * 32) * SLDA * 2;
    const uint32_t bRowOff = (uint32_t)(wn * 64) * SLDA * 2;
#pragma unroll
    for (int kk = 0; kk < 4; kk++) {
        const uint32_t koff = kk * 32;
        uint32_t ah[2][4], al[2][4], bh4[4][4], bl4[4][4];
#pragma unroll
        for (int mf = 0; mf < 2; mf++) {
            const uint32_t a = sb + aRowOff + (uint32_t)(mf * 16) * SLDA * 2 + koff + lmoff;
            ldm4(ah[mf], a);
            ldm4(al[mf], a + STILE);
        }
#pragma unroll
        for (int np = 0; np < 4; np++) {
            const uint32_t bb = sb + 2*STILE + bRowOff + (uint32_t)(np * 16) * SLDA * 2 + koff + lmoff;
            ldm4(bh4[np], bb);
            ldm4(bl4[np], bb + STILE);
        }
#pragma unroll
        for (int mf = 0; mf < 2; mf++)
#pragma unroll
            for (int np = 0; np < 4; np++) {
                mma16816(acc[mf][2*np],   ah[mf], bh4[np][0], bh4[np][2]);
                mma16816(acc[mf][2*np+1], ah[mf], bh4[np][1], bh4[np][3]);
                mma16816(acc[mf][2*np],   ah[mf], bl4[np][0], bl4[np][2]);
                mma16816(acc[mf][2*np+1], ah[mf], bl4[np][1], bl4[np][3]);
                mma16816(acc[mf][2*np],   al[mf], bh4[np][0], bh4[np][2]);
                mma16816(acc[mf][2*np+1], al[mf], bh4[np][1], bh4[np][3]);
            }
    }

    float* Pb = P + (size_t)bh * SS * SS;
#pragma unroll
    for (int mf = 0; mf < 2; mf++)
#pragma unroll
        for (int nf = 0; nf < 8; nf++) {
            const int r0 = bm + wm * 32 + mf * 16 + (lane >> 2);
            const int col = bn + wn * 64 + nf * 8 + (lane & 3) * 2;
            float2 v0, v1;
            v0.x = (col     <= r0)     ? acc[mf][nf][0] : -INFINITY;
            v0.y = (col + 1 <= r0)     ? acc[mf][nf][1] : -INFINITY;
            v1.x = (col     <= r0 + 8) ? acc[mf][nf][2] : -INFINITY;
            v1.y = (col + 1 <= r0 + 8) ? acc[mf][nf][3] : -INFINITY;
            *reinterpret_cast<float2*>(Pb + (size_t)r0 * SS + col) = v0;
            *reinterpret_cast<float2*>(Pb + (size_t)(r0 + 8) * SS + col) = v1;
        }
}

// ====================== HMMA split-bf16 P @ V^T ==============================
// O[s, hh*64+d] = sum_t P[s,t] Vt[d,t]; P converted+split in smem per chunk.
#define PLDA 72
#define PTILE (128*PLDA*2)            // 18432 B
#define VTILE (64*PLDA*2)             // 9216 B
#define PV_DSM (2*PTILE + 4*VTILE)    // 73728 B

__global__ void __launch_bounds__(256, 2) attn_pv_hmma(
    const float* __restrict__ P,
    const __nv_bfloat16* __restrict__ vth, const __nv_bfloat16* __restrict__ vtl,
    __nv_bfloat16* __restrict__ Oh, __nv_bfloat16* __restrict__ Ol)
{
    const int bh = blockIdx.z, b = bh >> 4, hh = bh & 15;
    const int bm = blockIdx.y * 128;
    extern __shared__ __align__(16) char smem[];
    const uint32_t sb = smem_u32(smem);
    const int tid = threadIdx.x, lane = tid & 31, wid = tid >> 5;

    const float* Pb = P + (size_t)bh * SS * SS;
    const __nv_bfloat16* Vh = vth + (size_t)(bh * HD) * SS;
    const __nv_bfloat16* Vl = vtl + (size_t)(bh * HD) * SS;
    const int nck = bm / 64 + 2;

    // V loader: tile 64 rows(d) x 64 t = 512 chunks; 2 per thread per tile
    const int vr0 = tid >> 3,           vc0 = tid & 7;
    const int vr1 = (tid + 256) >> 3,   vc1 = vc0;
    const uint32_t vd0 = (uint32_t)(vr0 * PLDA * 2 + vc0 * 16);
    const uint32_t vd1 = (uint32_t)(vr1 * PLDA * 2 + vc1 * 16);

#define LOADV(st, kc2)                                                        \
    do {                                                                      \
        const uint32_t vb_ = sb + 2*PTILE + (st) * 2 * VTILE;                 \
        cp16(vb_ + vd0,          Vh + (size_t)vr0 * SS + (kc2) * 64 + vc0*8); \
        cp16(vb_ + vd1,          Vh + (size_t)vr1 * SS + (kc2) * 64 + vc1*8); \
        cp16(vb_ + VTILE + vd0,  Vl + (size_t)vr0 * SS + (kc2) * 64 + vc0*8); \
        cp16(vb_ + VTILE + vd1,  Vl + (size_t)vr1 * SS + (kc2) * 64 + vc1*8); \
        cp_commit();                                                          \
    } while (0)

    LOADV(0, 0);

    float acc[8][4] = {};
    const uint32_t lmoff = (uint32_t)((lane & 15) * PLDA + (lane >> 4) * 8) * 2;
    const uint32_t aRowOff = (uint32_t)(wid * 16) * PLDA * 2;
    const int prow = tid >> 1, phalf = tid & 1;

    for (int kc = 0; kc < nck; kc++) {
        if (kc + 1 < nck) LOADV((kc + 1) & 1, kc + 1);
        // convert P chunk kc into split-bf16 smem
        {
            const float* pr = Pb + (size_t)(bm + prow) * SS + kc * 64 + phalf * 32;
            char* dsth = smem + prow * PLDA * 2 + phalf * 64;
            char* dstl = dsth + PTILE;
#pragma unroll
            for (int j = 0; j < 8; j++) {
                const float4 f = *reinterpret_cast<const float4*>(pr + j * 4);
                __nv_bfloat16 h0, h1, h2, h3, l0, l1, l2, l3;
                split_bf16(f.x, h0, l0); split_bf16(f.y, h1, l1);
                split_bf16(f.z, h2, l2); split_bf16(f.w, h3, l3);
                *reinterpret_cast<__nv_bfloat162*>(dsth + j*8)     = __nv_bfloat162(h0, h1);
                *reinterpret_cast<__nv_bfloat162*>(dsth + j*8 + 4) = __nv_bfloat162(h2, h3);
                *reinterpret_cast<__nv_bfloat162*>(dstl + j*8)     = __nv_bfloat162(l0, l1);
                *reinterpret_cast<__nv_bfloat162*>(dstl + j*8 + 4) = __nv_bfloat162(l2, l3);
            }
        }
        if (kc + 1 < nck) cp_wait<1>(); else cp_wait<0>();
        __syncthreads();

        const uint32_t vb = sb + 2*PTILE + (kc & 1) * 2 * VTILE;
#pragma unroll
        for (int kk = 0; kk < 4; kk++) {
            const uint32_t koff = kk * 32;
            uint32_t ah[4], al[4], bh4[4][4], bl4[4][4];
            const uint32_t a = sb + aRowOff + koff + lmoff;
            ldm4(ah, a);
            ldm4(al, a + PTILE);
#pragma unroll
            for (int np = 0; np < 4; np++) {
                const uint32_t bb = vb + (uint32_t)(np * 16) * PLDA * 2 + koff + lmoff;
                ldm4(bh4[np], bb);
                ldm4(bl4[np], bb + VTILE);
            }
#pragma unroll
            for (int np = 0; np < 4; np++) {
                mma16816(acc[2*np],   ah, bh4[np][0], bh4[np][2]);
                mma16816(acc[2*np+1], ah, bh4[np][1], bh4[np][3]);
                mma16816(acc[2*np],   ah, bl4[np][0], bl4[np][2]);
                mma16816(acc[2*np+1], ah, bl4[np][1], bl4[np][3]);
                mma16816(acc[2*np],   al, bh4[np][0], bh4[np][2]);
                mma16816(acc[2*np+1], al, bh4[np][1], bh4[np][3]);
            }
        }
        __syncthreads();
    }
#undef LOADV

    // epilogue: split-bf16 out, layout [t, 1024]
#pragma unroll
    for (int nf = 0; nf < 8; nf++) {
        const int r0 = bm + wid * 16 + (lane >> 2);
        const int col = hh * HD + nf * 8 + (lane & 3) * 2;
        const size_t o0 = (size_t)(b * SS + r0) * DD + col;
        const size_t o1 = o0 + (size_t)8 * DD;
        __nv_bfloat16 h0, h1, h2, h3, l0, l1, l2, l3;
        split_bf16(acc[nf][0], h0, l0); split_bf16(acc[nf][1], h1, l1);
        split_bf16(acc[nf][2], h2, l2); split_bf16(acc[nf][3], h3, l3);
        *reinterpret_cast<__nv_bfloat162*>(Oh + o0) = __nv_bfloat162(h0, h1);
        *reinterpret_cast<__nv_bfloat162*>(Oh + o1) = __nv_bfloat162(h2, h3);
        *reinterpret_cast<__nv_bfloat162*>(Ol + o0) = __nv_bfloat162(l0, l1);
        *reinterpret_cast<__nv_bfloat162*>(Ol + o1) = __nv_bfloat162(l2, l3);
    }
}

// =================== weight transpose + bf16 split ===========================
__global__ void __launch_bounds__(256) wconv_kernel(const float* __restrict__ W,
        __nv_bfloat16* __restrict__ hi, __nv_bfloat16* __restrict__ lo, int K, int N) {
    __shared__ float t[32][33];
    const int bx = blockIdx.x * 32;
    const int by = blockIdx.y * 32;
    const int tx = threadIdx.x & 31, ty = threadIdx.x >> 5;
#pragma unroll
    for (int i = 0; i < 4; i++) {
        const int ky = ty + i * 8;
        t[ky][tx] = W[(size_t)(by + ky) * N + bx + tx];
    }
    __syncthreads();
#pragma unroll
    for (int i = 0; i < 4; i++) {
        const int ny = ty + i * 8;
        const float v = t[tx][ny];
        __nv_bfloat16 h, l;
        split_bf16(v, h, l);
        const size_t o = (size_t)(bx + ny) * K + by + tx;
        hi[o] = h;
        lo[o] = l;
    }
}

// ============================ rmsnorm -> bf16 split ==========================
__global__ void rmsnorm_split(const float* __restrict__ x, const float* __restrict__ w,
                              __nv_bfloat16* __restrict__ hi, __nv_bfloat16* __restrict__ lo) {
    __shared__ float red[8];
    const int row = blockIdx.x;
    const float* xr = x + (size_t)row * DD;
    float vals[4];
    float ss = 0.f;
#pragma unroll
    for (int i = 0; i < 4; i++) {
        vals[i] = xr[threadIdx.x + i * 256];
        ss += vals[i] * vals[i];
    }
#pragma unroll
    for (int off = 16; off; off >>= 1) ss += __shfl_xor_sync(0xffffffffu, ss, off);
    if ((threadIdx.x & 31) == 0) red[threadIdx.x >> 5] = ss;
    __syncthreads();
    if (threadIdx.x < 32) {
        float s2 = (threadIdx.x < 8) ? red[threadIdx.x] : 0.f;
#pragma unroll
        for (int off = 4; off; off >>= 1) s2 += __shfl_xor_sync(0xffffffffu, s2, off);
        if (threadIdx.x == 0) red[0] = s2;
    }
    __syncthreads();
    const float rms = rsqrtf(red[0] * (1.0f / DD) + 1e-6f);
#pragma unroll
    for (int i = 0; i < 4; i++) {
        const int c = threadIdx.x + i * 256;
        const float v = vals[i] * rms * w[c];
        __nv_bfloat16 h, l;
        split_bf16(v, h, l);
        const size_t o = (size_t)row * DD + c;
        hi[o] = h;
        lo[o] = l;
    }
}

// ======================= rope -> bf16 split (+scale) =========================
__global__ void rope_split(const float* __restrict__ X, const float* __restrict__ rf,
                           __nv_bfloat16* __restrict__ hi, __nv_bfloat16* __restrict__ lo,
                           float scale) {
    const int idx = blockIdx.x * blockDim.x + threadIdx.x;
    if (idx >= TT * NH * (HD / 2)) return;
    const int i = idx & 31;
    const int hh = (idx >> 5) & (NH - 1);
    const int t = idx >> 9;
    const int s = t & (SS - 1);
    const float2 cs = *reinterpret_cast<const float2*>(rf + ((size_t)s * 32 + i) * 2);
    const float2 xv = *reinterpret_cast<const float2*>(X + (size_t)t * DD + hh * HD + 2 * i);
    const float o0 = (xv.x * cs.x - xv.y * cs.y) * scale;
    const float o1 = (xv.x * cs.y + xv.y * cs.x) * scale;
    __nv_bfloat16 h0, h1, l0, l1;
    split_bf16(o0, h0, l0);
    split_bf16(o1, h1, l1);
    const size_t o = (size_t)t * DD + hh * HD + 2 * i;
    *reinterpret_cast<__nv_bfloat162*>(hi + o) = __nv_bfloat162(h0, h1);
    *reinterpret_cast<__nv_bfloat162*>(lo + o) = __nv_bfloat162(l0, l1);
}

// ====================== V transpose -> split bf16 ============================
// v[t, hh*64+d] -> vt[(bh*64+d), t]
__global__ void vtrans_split(const float* __restrict__ V,
                             __nv_bfloat16* __restrict__ vh, __nv_bfloat16* __restrict__ vl) {
    __shared__ float tile[32][33];
    const int bh = blockIdx.z, b = bh >> 4, hh = bh & 15;
    const int t0 = blockIdx.x * 32, d0 = blockIdx.y * 32;
    const int tx = threadIdx.x & 31, ty = threadIdx.x >> 5;
#pragma unroll
    for (int i = 0; i < 4; i++) {
        const int tt = ty + i * 8;
        tile[tt][tx] = V[(size_t)(b * SS + t0 + tt) * DD + hh * HD + d0 + tx];
    }
    __syncthreads();
#pragma unroll
    for (int i = 0; i < 4; i++) {
        const int dd = ty + i * 8;
        const float v = tile[tx][dd];
        __nv_bfloat16 h, l;
        split_bf16(v, h, l);
        const size_t o = (size_t)(bh * HD + d0 + dd) * SS + t0 + tx;
        vh[o] = h;
        vl[o] = l;
    }
}

// ================================ softmax ====================================
__global__ void softmax_kernel(float* __restrict__ P) {
    __shared__ float red[8];
    const size_t row = blockIdx.x;
    const int s = (int)(row & (SS - 1));
    float* p = P + row * SS;
    float v[8];
    float mx = -INFINITY;
#pragma unroll
    for (int i = 0; i < 8; i++) {
        const int t = threadIdx.x + i * 256;
        v[i] = (t <= s) ? p[t] : -INFINITY;
        mx = fmaxf(mx, v[i]);
    }
#pragma unroll
    for (int off = 16; off; off >>= 1) mx = fmaxf(mx, __shfl_xor_sync(0xffffffffu, mx, off));
    if ((threadIdx.x & 31) == 0) red[threadIdx.x >> 5] = mx;
    __syncthreads();
    if (threadIdx.x < 32) {
        float m2 = (threadIdx.x < 8) ? red[threadIdx.x] : -INFINITY;
#pragma unroll
        for (int off = 4; off; off >>= 1) m2 = fmaxf(m2, __shfl_xor_sync(0xffffffffu, m2, off));
        if (threadIdx.x == 0) red[0] = m2;
    }
    __syncthreads();
    mx = red[0];
    __syncthreads();
    float sum = 0.f;
#pragma unroll
    for (int i = 0; i < 8; i++) {
        const int t = threadIdx.x + i * 256;
        v[i] = (t <= s) ? __expf(v[i] - mx) : 0.f;
        sum += v[i];
    }
#pragma unroll
    for (int off = 16; off; off >>= 1) sum += __shfl_xor_sync(0xffffffffu, sum, off);
    if ((threadIdx.x & 31) == 0) red[threadIdx.x >> 5] = sum;
    __syncthreads();
    if (threadIdx.x < 32) {
        float s2 = (threadIdx.x < 8) ? red[threadIdx.x] : 0.f;
#pragma unroll
        for (int off = 4; off; off >>= 1) s2 += __shfl_xor_sync(0xffffffffu, s2, off);
        if (threadIdx.x == 0) red[0] = s2;
    }
    __syncthreads();
    const float inv = 1.0f / red[0];
#pragma unroll
    for (int i = 0; i < 8; i++) p[threadIdx.x + i * 256] = v[i] * inv;
}

// ========================= silu(gate)*up -> bf16 split =======================
__global__ void silu_mul_split(const float* __restrict__ g, const float* __restrict__ u,
                               __nv_bfloat16* __restrict__ hi, __nv_bfloat16* __restrict__ lo) {
    const size_t i = (size_t)blockIdx.x * blockDim.x + threadIdx.x;
    const float gv = g[i];
    const float r = gv / (1.f + __expf(-gv)) * u[i];
    __nv_bfloat16 h, l;
    split_bf16(r, h, l);
    hi[i] = h;
    lo[i] = l;
}

// ================================= launch ====================================
extern "C" void kernel_launch(void* const* d_in, const int* in_sizes, int n_in,
                              void* d_out, int out_size) {
    const float* x   = (const float*)d_in[0];
    const float* rf  = (const float*)d_in[1];
    const float* anw = (const float*)d_in[3];
    const float* fnw = (const float*)d_in[4];
    const float* wq  = (const float*)d_in[5];
    const float* wk  = (const float*)d_in[6];
    const float* wv  = (const float*)d_in[7];
    const float* wo  = (const float*)d_in[8];
    const float* wg  = (const float*)d_in[9];
    const float* wu  = (const float*)d_in[10];
    const float* wd  = (const float*)d_in[11];
    float* out = (float*)d_out;

    float *q, *k, *v, *sc, *gt, *up;
    __nv_bfloat16 *ahi, *alo, *qsh, *qsl, *ksh, *ksl, *vth, *vtl;
    __nv_bfloat16 *wqh, *wql, *wkh, *wkl, *wvh, *wvl, *woh, *wol;
    __nv_bfloat16 *wgh, *wgl, *wuh, *wul, *wdh, *wdl;
    cudaGetSymbolAddress((void**)&q,  g_q);
    cudaGetSymbolAddress((void**)&k,  g_k);
    cudaGetSymbolAddress((void**)&v,  g_v);
    cudaGetSymbolAddress((void**)&sc, g_scores);
    cudaGetSymbolAddress((void**)&gt, g_gate);
    cudaGetSymbolAddress((void**)&up, g_up);
    cudaGetSymbolAddress((void**)&ahi, g_ahi);
    cudaGetSymbolAddress((void**)&alo, g_alo);
    cudaGetSymbolAddress((void**)&qsh, g_qsh); cudaGetSymbolAddress((void**)&qsl, g_qsl);
    cudaGetSymbolAddress((void**)&ksh, g_ksh); cudaGetSymbolAddress((void**)&ksl, g_ksl);
    cudaGetSymbolAddress((void**)&vth, g_vth); cudaGetSymbolAddress((void**)&vtl, g_vtl);
    cudaGetSymbolAddress((void**)&wqh, g_wqh); cudaGetSymbolAddress((void**)&wql, g_wql);
    cudaGetSymbolAddress((void**)&wkh, g_wkh); cudaGetSymbolAddress((void**)&wkl, g_wkl);
    cudaGetSymbolAddress((void**)&wvh, g_wvh); cudaGetSymbolAddress((void**)&wvl, g_wvl);
    cudaGetSymbolAddress((void**)&woh, g_woh); cudaGetSymbolAddress((void**)&wol, g_wol);
    cudaGetSymbolAddress((void**)&wgh, g_wgh); cudaGetSymbolAddress((void**)&wgl, g_wgl);
    cudaGetSymbolAddress((void**)&wuh, g_wuh); cudaGetSymbolAddress((void**)&wul, g_wul);
    cudaGetSymbolAddress((void**)&wdh, g_wdh); cudaGetSymbolAddress((void**)&wdl, g_wdl);

    cudaFuncSetAttribute(hgemm_split, cudaFuncAttributeMaxDynamicSharedMemorySize, HG_DSM);
    cudaFuncSetAttribute(attn_scores_hmma, cudaFuncAttributeMaxDynamicSharedMemorySize, SC_DSM);
    cudaFuncSetAttribute(attn_pv_hmma, cudaFuncAttributeMaxDynamicSharedMemorySize, PV_DSM);

    // weight conversion (transpose + split)
    wconv_kernel<<<dim3(1024/32, 1024/32), 256>>>(wq, wqh, wql, 1024, 1024);
    wconv_kernel<<<dim3(1024/32, 1024/32), 256>>>(wk, wkh, wkl, 1024, 1024);
    wconv_kernel<<<dim3(1024/32, 1024/32), 256>>>(wv, wvh, wvl, 1024, 1024);
    wconv_kernel<<<dim3(1024/32, 1024/32), 256>>>(wo, woh, wol, 1024, 1024);
    wconv_kernel<<<dim3(4096/32, 1024/32), 256>>>(wg, wgh, wgl, 1024, 4096);
    wconv_kernel<<<dim3(4096/32, 1024/32), 256>>>(wu, wuh, wul, 1024, 4096);
    wconv_kernel<<<dim3(1024/32, 4096/32), 256>>>(wd, wdh, wdl, 4096, 1024);

    // 1) attn rmsnorm -> split-bf16 activations
    rmsnorm_split<<<TT, 256>>>(x, anw, ahi, alo);
    // 2) QKV projections
    hgemm_split<<<dim3(TT/128, 1024/128), 256, HG_DSM>>>(ahi, alo, wqh, wql, nullptr, q, TT, 1024, 1024);
    hgemm_split<<<dim3(TT/128, 1024/128), 256, HG_DSM>>>(ahi, alo, wkh, wkl, nullptr, k, TT, 1024, 1024);
    hgemm_split<<<dim3(TT/128, 1024/128), 256, HG_DSM>>>(ahi, alo, wvh, wvl, nullptr, v, TT, 1024, 1024);
    // 3) rope + split (q scaled by 1/sqrt(HD)); V transpose + split
    const int nrope = TT * NH * (HD / 2);
    rope_split<<<nrope / 256, 256>>>(q, rf, qsh, qsl, 0.125f);
    rope_split<<<nrope / 256, 256>>>(k, rf, ksh, ksl, 1.0f);
    vtrans_split<<<dim3(SS/32, HD/32, BB*NH), 256>>>(v, vth, vtl);
    // 4) attention (tensor pipe)
    attn_scores_hmma<<<dim3(SS/128, SS/128, BB*NH), 256, SC_DSM>>>(qsh, qsl, ksh, ksl, sc);
    softmax_kernel<<<BB * NH * SS, 256>>>(sc);
    attn_pv_hmma<<<dim3(1, SS/128, BB*NH), 256, PV_DSM>>>(sc, vth, vtl, ahi, alo);
    // 5) output projection + residual
    hgemm_split<<<dim3(TT/128, 1024/128), 256, HG_DSM>>>(ahi, alo, woh, wol, x, out, TT, 1024, 1024);
    // 6) ffn rmsnorm
    rmsnorm_split<<<TT, 256>>>(out, fnw, ahi, alo);
    // 7) gate / up
    hgemm_split<<<dim3(TT/128, 4096/128), 256, HG_DSM>>>(ahi, alo, wgh, wgl, nullptr, gt, TT, 4096, 1024);
    hgemm_split<<<dim3(TT/128, 4096/128), 256, HG_DSM>>>(ahi, alo, wuh, wul, nullptr, up, TT, 4096, 1024);
    // 8) silu * up -> split bf16
    silu_mul_split<<<(int)(((size_t)TT * INNER) / 256), 256>>>(gt, up, ahi, alo);
    // 9) down projection + residual
    hgemm_split<<<dim3(TT/128, 1024/128), 256, HG_DSM>>>(ahi, alo, wdh, wdl, out, out, TT, 1024, 4096);
}

// round 7
// speedup vs baseline: 2.2436x; 1.1152x over previous
#include <cuda_runtime.h>
#include <cuda_bf16.h>
#include <math.h>
#include <stdint.h>

#define BB 2
#define SS 2048
#define DD 1024
#define NH 16
#define HD 64
#define TT (BB*SS)        // 4096 tokens
#define INNER 4096

// ===================== scratch (device globals; no cudaMalloc) ===============
__device__ __align__(256) float g_q[(size_t)TT*DD];            // 16 MB
__device__ __align__(256) float g_k[(size_t)TT*DD];            // 16 MB
__device__ __align__(256) float g_v[(size_t)TT*DD];            // 16 MB
__device__ __align__(256) float g_gate[(size_t)TT*INNER];      // 64 MB
__device__ __align__(256) float g_up[(size_t)TT*INNER];        // 64 MB
// split-bf16 activation buffers (A operand of GEMMs), max K = 4096
__device__ __align__(256) __nv_bfloat16 g_ahi[(size_t)TT*INNER];
__device__ __align__(256) __nv_bfloat16 g_alo[(size_t)TT*INNER];
// split-bf16 roped Q/K and transposed V
__device__ __align__(256) __nv_bfloat16 g_qsh[(size_t)TT*DD], g_qsl[(size_t)TT*DD];
__device__ __align__(256) __nv_bfloat16 g_ksh[(size_t)TT*DD], g_ksl[(size_t)TT*DD];
__device__ __align__(256) __nv_bfloat16 g_vth[(size_t)TT*DD], g_vtl[(size_t)TT*DD];
// split-bf16 transposed weights [N,K]
__device__ __align__(256) __nv_bfloat16 g_wqh[1024*1024], g_wql[1024*1024];
__device__ __align__(256) __nv_bfloat16 g_wkh[1024*1024], g_wkl[1024*1024];
__device__ __align__(256) __nv_bfloat16 g_wvh[1024*1024], g_wvl[1024*1024];
__device__ __align__(256) __nv_bfloat16 g_woh[1024*1024], g_wol[1024*1024];
__device__ __align__(256) __nv_bfloat16 g_wgh[(size_t)4096*1024], g_wgl[(size_t)4096*1024];
__device__ __align__(256) __nv_bfloat16 g_wuh[(size_t)4096*1024], g_wul[(size_t)4096*1024];
__device__ __align__(256) __nv_bfloat16 g_wdh[(size_t)1024*4096], g_wdl[(size_t)1024*4096];

// ============================== PTX helpers ==================================
__device__ __forceinline__ uint32_t smem_u32(const void* p) {
    uint32_t a;
    asm("{ .reg .u64 t; cvta.to.shared.u64 t, %1; cvt.u32.u64 %0, t; }" : "=r"(a) : "l"(p));
    return a;
}
__device__ __forceinline__ void cp16(uint32_t dst, const void* src) {
    asm volatile("cp.async.cg.shared.global [%0], [%1], 16;\n" :: "r"(dst), "l"(src));
}
__device__ __forceinline__ void cp_commit() { asm volatile("cp.async.commit_group;\n" ::: "memory"); }
template <int N> __device__ __forceinline__ void cp_wait() {
    asm volatile("cp.async.wait_group %0;\n" :: "n"(N) : "memory");
}
__device__ __forceinline__ void ldm4(uint32_t* r, uint32_t addr) {
    asm volatile("ldmatrix.sync.aligned.m8n8.x4.shared.b16 {%0,%1,%2,%3}, [%4];"
        : "=r"(r[0]), "=r"(r[1]), "=r"(r[2]), "=r"(r[3]) : "r"(addr));
}
__device__ __forceinline__ void mma16816(float* c, const uint32_t* a, uint32_t b0, uint32_t b1) {
    asm volatile("mma.sync.aligned.m16n8k16.row.col.f32.bf16.bf16.f32 "
        "{%0,%1,%2,%3}, {%4,%5,%6,%7}, {%8,%9}, {%0,%1,%2,%3};"
        : "+f"(c[0]), "+f"(c[1]), "+f"(c[2]), "+f"(c[3])
        : "r"(a[0]), "r"(a[1]), "r"(a[2]), "r"(a[3]), "r"(b0), "r"(b1));
}
__device__ __forceinline__ void split_bf16(float v, __nv_bfloat16& h, __nv_bfloat16& l) {
    h = __float2bfloat16(v);
    l = __float2bfloat16(v - __bfloat162float(h));
}
__device__ __forceinline__ void pack_split2(float a, float b, uint32_t& h, uint32_t& l) {
    __nv_bfloat16 ha, la, hb, lb;
    split_bf16(a, ha, la);
    split_bf16(b, hb, lb);
    __nv_bfloat162 ph(ha, hb), pl(la, lb);
    h = *reinterpret_cast<uint32_t*>(&ph);
    l = *reinterpret_cast<uint32_t*>(&pl);
}

// ====================== HMMA split-bf16 dense GEMM ===========================
#define KC 32
#define LDA 40
#define TILE_B (128*LDA*2)           // 10240 B
#define HSTAGE_B (4*TILE_B)          // 40960 B
#define HG_DSM (2*HSTAGE_B)          // 81920 B

__global__ void __launch_bounds__(256, 1) hgemm_split(
    const __nv_bfloat16* __restrict__ Ahi, const __nv_bfloat16* __restrict__ Alo,
    const __nv_bfloat16* __restrict__ Bhi, const __nv_bfloat16* __restrict__ Blo,
    const float* __restrict__ R, float* __restrict__ C, int M, int N, int K)
{
    extern __shared__ __align__(16) char smem[];
    const int tid = threadIdx.x;
    const int lane = tid & 31, wid = tid >> 5;
    const int wm = wid >> 1, wn = wid & 1;
    const int bm = blockIdx.x * 128, bn = blockIdx.y * 128;
    const uint32_t sbase = smem_u32(smem);

    float acc[2][8][4] = {};

    const int r0_ = tid >> 2,            c0_ = tid & 3;
    const int r1_ = (tid + 256) >> 2,    c1_ = c0_;
    const uint32_t d0 = (uint32_t)(r0_ * LDA * 2 + c0_ * 16);
    const uint32_t d1 = (uint32_t)(r1_ * LDA * 2 + c1_ * 16);
    const size_t a0 = (size_t)(bm + r0_) * K + c0_ * 8;
    const size_t a1 = (size_t)(bm + r1_) * K + c1_ * 8;
    const size_t b0 = (size_t)(bn + r0_) * K + c0_ * 8;
    const size_t b1 = (size_t)(bn + r1_) * K + c1_ * 8;

#define LOAD_STAGE(st, k0)                                              \
    do {                                                                \
        const uint32_t sb_ = sbase + (st) * HSTAGE_B;                   \
        cp16(sb_ + d0,              Ahi + a0 + (k0));                   \
        cp16(sb_ + d1,              Ahi + a1 + (k0));                   \
        cp16(sb_ + TILE_B + d0,     Alo + a0 + (k0));                   \
        cp16(sb_ + TILE_B + d1,     Alo + a1 + (k0));                   \
        cp16(sb_ + 2*TILE_B + d0,   Bhi + b0 + (k0));                   \
        cp16(sb_ + 2*TILE_B + d1,   Bhi + b1 + (k0));                   \
        cp16(sb_ + 3*TILE_B + d0,   Blo + b0 + (k0));                   \
        cp16(sb_ + 3*TILE_B + d1,   Blo + b1 + (k0));                   \
        cp_commit();                                                    \
    } while (0)

    const int NCK = K / KC;
    LOAD_STAGE(0, 0);
    LOAD_STAGE(1, KC);

    const uint32_t lmoff = (uint32_t)((lane & 15) * LDA + (lane >> 4) * 8) * 2;
    const uint32_t aRowOff = (uint32_t)(wm * 32) * LDA * 2;
    const uint32_t bRowOff = (uint32_t)(wn * 64) * LDA * 2;

    for (int kc = 0; kc < NCK; kc++) {
        if (kc < NCK - 1) cp_wait<1>(); else cp_wait<0>();
        __syncthreads();
        const uint32_t sb = sbase + (kc & 1) * HSTAGE_B;
#pragma unroll
        for (int kk = 0; kk < 2; kk++) {
            const uint32_t koff = kk * 32;
            uint32_t ah[2][4], al[2][4], bh[4][4], bl[4][4];
#pragma unroll
            for (int mf = 0; mf < 2; mf++) {
                const uint32_t a = sb + aRowOff + (uint32_t)(mf * 16) * LDA * 2 + koff + lmoff;
                ldm4(ah[mf], a);
                ldm4(al[mf], a + TILE_B);
            }
#pragma unroll
            for (int np = 0; np < 4; np++) {
                const uint32_t b = sb + 2 * TILE_B + bRowOff + (uint32_t)(np * 16) * LDA * 2 + koff + lmoff;
                ldm4(bh[np], b);
                ldm4(bl[np], b + TILE_B);
            }
#pragma unroll
            for (int mf = 0; mf < 2; mf++)
#pragma unroll
                for (int np = 0; np < 4; np++) {
                    mma16816(acc[mf][2*np],   ah[mf], bh[np][0], bh[np][2]);
                    mma16816(acc[mf][2*np+1], ah[mf], bh[np][1], bh[np][3]);
                    mma16816(acc[mf][2*np],   ah[mf], bl[np][0], bl[np][2]);
                    mma16816(acc[mf][2*np+1], ah[mf], bl[np][1], bl[np][3]);
                    mma16816(acc[mf][2*np],   al[mf], bh[np][0], bh[np][2]);
                    mma16816(acc[mf][2*np+1], al[mf], bh[np][1], bh[np][3]);
                }
        }
        __syncthreads();
        if (kc + 2 < NCK) LOAD_STAGE(kc & 1, (kc + 2) * KC);
    }
#undef LOAD_STAGE

#pragma unroll
    for (int mf = 0; mf < 2; mf++)
#pragma unroll
        for (int nf = 0; nf < 8; nf++) {
            const int row0 = bm + wm * 32 + mf * 16 + (lane >> 2);
            const int col  = bn + wn * 64 + nf * 8 + (lane & 3) * 2;
            const size_t o0 = (size_t)row0 * N + col;
            const size_t o1 = o0 + (size_t)8 * N;
            float2 v0 = make_float2(acc[mf][nf][0], acc[mf][nf][1]);
            float2 v1 = make_float2(acc[mf][nf][2], acc[mf][nf][3]);
            if (R) {
                const float2 r0 = *reinterpret_cast<const float2*>(R + o0);
                const float2 r1 = *reinterpret_cast<const float2*>(R + o1);
                v0.x += r0.x; v0.y += r0.y; v1.x += r1.x; v1.y += r1.y;
            }
            *reinterpret_cast<float2*>(C + o0) = v0;
            *reinterpret_cast<float2*>(C + o1) = v1;
        }
}

// ========================= fused flash attention =============================
// One CTA = 128 query rows of one (b, h). Online softmax; no score matrix.
// smem: Q(hi,lo) persistent + double-buffered K(hi,lo) / V^T(hi,lo) chunks.
#define FLDA 72                         // Q/K row: 64 el -> 72
#define FLDV 136                        // V^T row: 128 el -> 136
#define FQT (128*FLDA*2)                // 18432 B per Q/K tile
#define FVT (64*FLDV*2)                 // 17408 B per V tile
#define FSTAGE (2*FQT + 2*FVT)          // 71680 B
#define FA_DSM (2*FQT + 2*FSTAGE)       // 180224 B

__global__ void __launch_bounds__(256, 1) flash_attn(
    const __nv_bfloat16* __restrict__ qh, const __nv_bfloat16* __restrict__ ql,
    const __nv_bfloat16* __restrict__ kh, const __nv_bfloat16* __restrict__ kl,
    const __nv_bfloat16* __restrict__ vh, const __nv_bfloat16* __restrict__ vl,
    __nv_bfloat16* __restrict__ Oh, __nv_bfloat16* __restrict__ Ol)
{
    const int bh = blockIdx.z, b = bh >> 4, hh = bh & 15;
    const int qb = (int)(gridDim.y - 1 - blockIdx.y);     // big blocks first
    const int bm = qb * 128;
    const int nck = qb + 1;
    extern __shared__ __align__(16) char smem[];
    const uint32_t sbQ = smem_u32(smem);
    const int tid = threadIdx.x, lane = tid & 31, wid = tid >> 5;

    const __nv_bfloat16* Qh = qh + (size_t)(b * SS) * DD + hh * HD;
    const __nv_bfloat16* Ql = ql + (size_t)(b * SS) * DD + hh * HD;
    const __nv_bfloat16* Kh = kh + (size_t)(b * SS) * DD + hh * HD;
    const __nv_bfloat16* Kl = kl + (size_t)(b * SS) * DD + hh * HD;
    const __nv_bfloat16* Vh = vh + (size_t)(bh * HD) * SS;
    const __nv_bfloat16* Vl = vl + (size_t)(bh * HD) * SS;

    // loader indices
    const int qr = tid >> 3, qc = tid & 7;                // Q/K: 1024 chunks, 4/thread
    const uint32_t qd = (uint32_t)(qr * FLDA + qc * 8) * 2;
    const int vr = tid >> 4, vc = tid & 15;               // V: 1024 chunks, 4/thread
    const uint32_t vd = (uint32_t)(vr * FLDV + vc * 8) * 2;

#define FLOADKV(st, kc2)                                                        \
    do {                                                                        \
        const int t0_ = (kc2) * 128;                                            \
        const uint32_t sk_ = sbQ + 2*FQT + (st) * FSTAGE;                       \
        const uint32_t sv_ = sk_ + 2*FQT;                                       \
        _Pragma("unroll")                                                       \
        for (int i_ = 0; i_ < 4; i_++) {                                        \
            const int id_ = tid + (i_ << 8);                                    \
            const int r_ = id_ >> 3, c_ = id_ & 7;                              \
            const uint32_t dd_ = (uint32_t)(r_ * FLDA + c_ * 8) * 2;            \
            const size_t so_ = (size_t)(t0_ + r_) * DD + c_ * 8;                \
            cp16(sk_ + dd_,        Kh + so_);                                   \
            cp16(sk_ + FQT + dd_,  Kl + so_);                                   \
        }                                                                       \
        _Pragma("unroll")                                                       \
        for (int i_ = 0; i_ < 4; i_++) {                                        \
            const int id_ = tid + (i_ << 8);                                    \
            const int r_ = id_ >> 4, c_ = id_ & 15;                             \
            const uint32_t dd_ = (uint32_t)(r_ * FLDV + c_ * 8) * 2;            \
            const size_t so_ = (size_t)r_ * SS + t0_ + c_ * 8;                  \
            cp16(sv_ + dd_,        Vh + so_);                                   \
            cp16(sv_ + FVT + dd_,  Vl + so_);                                   \
        }                                                                       \
        cp_commit();                                                            \
    } while (0)

    // prologue: Q + chunk 0 in group 0
#pragma unroll
    for (int i = 0; i < 4; i++) {
        const int id = tid + (i << 8);
        const int r = id >> 3, c = id & 7;
        const uint32_t dd = (uint32_t)(r * FLDA + c * 8) * 2;
        const size_t so = (size_t)(bm + r) * DD + c * 8;
        cp16(sbQ + dd,        Qh + so);
        cp16(sbQ + FQT + dd,  Ql + so);
    }
    FLOADKV(0, 0);

    const uint32_t lmA = (uint32_t)((lane & 15) * FLDA + (lane >> 4) * 8) * 2;
    const uint32_t lmV = (uint32_t)((lane & 15) * FLDV + (lane >> 4) * 8) * 2;
    const uint32_t aRow = (uint32_t)(wid * 16) * FLDA * 2;
    const int r0 = bm + wid * 16 + (lane >> 2);           // this thread's row pair
    const int cbase = (lane & 3) * 2;

    float o[8][4] = {};
    float m0 = -INFINITY, m1 = -INFINITY, l0 = 0.f, l1 = 0.f;

    for (int kc = 0; kc < nck; kc++) {
        if (kc + 1 < nck) { FLOADKV((kc + 1) & 1, kc + 1); cp_wait<1>(); }
        else cp_wait<0>();
        __syncthreads();
        const uint32_t sk = sbQ + 2*FQT + (kc & 1) * FSTAGE;
        const uint32_t sv = sk + 2*FQT;

        // ---- S = Q K^T (3-term) ----
        float s[16][4] = {};
#pragma unroll
        for (int kk = 0; kk < 4; kk++) {
            const uint32_t koff = kk * 32;
            uint32_t aH[4], aL[4];
            ldm4(aH, sbQ + aRow + koff + lmA);
            ldm4(aL, sbQ + FQT + aRow + koff + lmA);
#pragma unroll
            for (int np = 0; np < 8; np++) {
                uint32_t bH[4], bL[4];
                const uint32_t ba = sk + (uint32_t)(np * 16) * FLDA * 2 + koff + lmA;
                ldm4(bH, ba);
                ldm4(bL, ba + FQT);
                mma16816(s[2*np],   aH, bH[0], bH[2]);
                mma16816(s[2*np+1], aH, bH[1], bH[3]);
                mma16816(s[2*np],   aH, bL[0], bL[2]);
                mma16816(s[2*np+1], aH, bL[1], bL[3]);
                mma16816(s[2*np],   aL, bH[0], bH[2]);
                mma16816(s[2*np+1], aL, bH[1], bH[3]);
            }
        }

        // ---- causal mask (diagonal chunk only) ----
        if (kc == qb) {
            const int t0 = kc * 128;
#pragma unroll
            for (int j = 0; j < 16; j++) {
                const int col = t0 + j * 8 + cbase;
                if (col > r0)         s[j][0] = -INFINITY;
                if (col + 1 > r0)     s[j][1] = -INFINITY;
                if (col > r0 + 8)     s[j][2] = -INFINITY;
                if (col + 1 > r0 + 8) s[j][3] = -INFINITY;
            }
        }

        // ---- online softmax ----
        float cm0 = -INFINITY, cm1 = -INFINITY;
#pragma unroll
        for (int j = 0; j < 16; j++) {
            cm0 = fmaxf(cm0, fmaxf(s[j][0], s[j][1]));
            cm1 = fmaxf(cm1, fmaxf(s[j][2], s[j][3]));
        }
        cm0 = fmaxf(cm0, __shfl_xor_sync(0xffffffffu, cm0, 1));
        cm0 = fmaxf(cm0, __shfl_xor_sync(0xffffffffu, cm0, 2));
        cm1 = fmaxf(cm1, __shfl_xor_sync(0xffffffffu, cm1, 1));
        cm1 = fmaxf(cm1, __shfl_xor_sync(0xffffffffu, cm1, 2));
        const float nm0 = fmaxf(m0, cm0), nm1 = fmaxf(m1, cm1);
        const float f0 = __expf(m0 - nm0), f1 = __expf(m1 - nm1);
        float rs0 = 0.f, rs1 = 0.f;
#pragma unroll
        for (int j = 0; j < 16; j++) {
            s[j][0] = __expf(s[j][0] - nm0);
            s[j][1] = __expf(s[j][1] - nm0);
            s[j][2] = __expf(s[j][2] - nm1);
            s[j][3] = __expf(s[j][3] - nm1);
            rs0 += s[j][0] + s[j][1];
            rs1 += s[j][2] + s[j][3];
        }
        rs0 += __shfl_xor_sync(0xffffffffu, rs0, 1);
        rs0 += __shfl_xor_sync(0xffffffffu, rs0, 2);
        rs1 += __shfl_xor_sync(0xffffffffu, rs1, 1);
        rs1 += __shfl_xor_sync(0xffffffffu, rs1, 2);
        l0 = l0 * f0 + rs0;
        l1 = l1 * f1 + rs1;
        m0 = nm0; m1 = nm1;
#pragma unroll
        for (int nf = 0; nf < 8; nf++) {
            o[nf][0] *= f0; o[nf][1] *= f0;
            o[nf][2] *= f1; o[nf][3] *= f1;
        }

        // ---- pack P into split-bf16 A fragments (C layout == A layout) ----
        uint32_t pH[8][4], pL[8][4];
#pragma unroll
        for (int ks = 0; ks < 8; ks++) {
            pack_split2(s[2*ks][0],   s[2*ks][1],   pH[ks][0], pL[ks][0]);
            pack_split2(s[2*ks][2],   s[2*ks][3],   pH[ks][1], pL[ks][1]);
            pack_split2(s[2*ks+1][0], s[2*ks+1][1], pH[ks][2], pL[ks][2]);
            pack_split2(s[2*ks+1][2], s[2*ks+1][3], pH[ks][3], pL[ks][3]);
        }

        // ---- O += P V (3-term) ----
#pragma unroll
        for (int ks = 0; ks < 8; ks++) {
            const uint32_t koff = ks * 32;
#pragma unroll
            for (int nd = 0; nd < 4; nd++) {
                uint32_t vH[4], vL[4];
                const uint32_t ba = sv + (uint32_t)(nd * 16) * FLDV * 2 + koff + lmV;
                ldm4(vH, ba);
                ldm4(vL, ba + FVT);
                mma16816(o[2*nd],   pH[ks], vH[0], vH[2]);
                mma16816(o[2*nd+1], pH[ks], vH[1], vH[3]);
                mma16816(o[2*nd],   pH[ks], vL[0], vL[2]);
                mma16816(o[2*nd+1], pH[ks], vL[1], vL[3]);
                mma16816(o[2*nd],   pL[ks], vH[0], vH[2]);
                mma16816(o[2*nd+1], pL[ks], vH[1], vH[3]);
            }
        }
        __syncthreads();          // protect this stage before next prefetch
    }
#undef FLOADKV

    // ---- epilogue: normalize + split-bf16 store ----
    const float il0 = 1.f / l0, il1 = 1.f / l1;
#pragma unroll
    for (int nf = 0; nf < 8; nf++) {
        const int col = hh * HD + nf * 8 + cbase;
        const size_t o0 = (size_t)(b * SS + r0) * DD + col;
        const size_t o1 = o0 + (size_t)8 * DD;
        __nv_bfloat16 h0, h1, h2, h3, q0, q1, q2, q3;
        split_bf16(o[nf][0] * il0, h0, q0);
        split_bf16(o[nf][1] * il0, h1, q1);
        split_bf16(o[nf][2] * il1, h2, q2);
        split_bf16(o[nf][3] * il1, h3, q3);
        *reinterpret_cast<__nv_bfloat162*>(Oh + o0) = __nv_bfloat162(h0, h1);
        *reinterpret_cast<__nv_bfloat162*>(Oh + o1) = __nv_bfloat162(h2, h3);
        *reinterpret_cast<__nv_bfloat162*>(Ol + o0) = __nv_bfloat162(q0, q1);
        *reinterpret_cast<__nv_bfloat162*>(Ol + o1) = __nv_bfloat162(q2, q3);
    }
}

// =================== weight transpose + bf16 split ===========================
__global__ void __launch_bounds__(256) wconv_kernel(const float* __restrict__ W,
        __nv_bfloat16* __restrict__ hi, __nv_bfloat16* __restrict__ lo, int K, int N) {
    __shared__ float t[32][33];
    const int bx = blockIdx.x * 32;
    const int by = blockIdx.y * 32;
    const int tx = threadIdx.x & 31, ty = threadIdx.x >> 5;
#pragma unroll
    for (int i = 0; i < 4; i++) {
        const int ky = ty + i * 8;
        t[ky][tx] = W[(size_t)(by + ky) * N + bx + tx];
    }
    __syncthreads();
#pragma unroll
    for (int i = 0; i < 4; i++) {
        const int ny = ty + i * 8;
        const float v = t[tx][ny];
        __nv_bfloat16 h, l;
        split_bf16(v, h, l);
        const size_t o = (size_t)(bx + ny) * K + by + tx;
        hi[o] = h;
        lo[o] = l;
    }
}

// ============================ rmsnorm -> bf16 split ==========================
__global__ void rmsnorm_split(const float* __restrict__ x, const float* __restrict__ w,
                              __nv_bfloat16* __restrict__ hi, __nv_bfloat16* __restrict__ lo) {
    __shared__ float red[8];
    const int row = blockIdx.x;
    const float* xr = x + (size_t)row * DD;
    float vals[4];
    float ss = 0.f;
#pragma unroll
    for (int i = 0; i < 4; i++) {
        vals[i] = xr[threadIdx.x + i * 256];
        ss += vals[i] * vals[i];
    }
#pragma unroll
    for (int off = 16; off; off >>= 1) ss += __shfl_xor_sync(0xffffffffu, ss, off);
    if ((threadIdx.x & 31) == 0) red[threadIdx.x >> 5] = ss;
    __syncthreads();
    if (threadIdx.x < 32) {
        float s2 = (threadIdx.x < 8) ? red[threadIdx.x] : 0.f;
#pragma unroll
        for (int off = 4; off; off >>= 1) s2 += __shfl_xor_sync(0xffffffffu, s2, off);
        if (threadIdx.x == 0) red[0] = s2;
    }
    __syncthreads();
    const float rms = rsqrtf(red[0] * (1.0f / DD) + 1e-6f);
#pragma unroll
    for (int i = 0; i < 4; i++) {
        const int c = threadIdx.x + i * 256;
        const float v = vals[i] * rms * w[c];
        __nv_bfloat16 h, l;
        split_bf16(v, h, l);
        const size_t o = (size_t)row * DD + c;
        hi[o] = h;
        lo[o] = l;
    }
}

// ======================= rope -> bf16 split (+scale) =========================
__global__ void rope_split(const float* __restrict__ X, const float* __restrict__ rf,
                           __nv_bfloat16* __restrict__ hi, __nv_bfloat16* __restrict__ lo,
                           float scale) {
    const int idx = blockIdx.x * blockDim.x + threadIdx.x;
    if (idx >= TT * NH * (HD / 2)) return;
    const int i = idx & 31;
    const int hh = (idx >> 5) & (NH - 1);
    const int t = idx >> 9;
    const int s = t & (SS - 1);
    const float2 cs = *reinterpret_cast<const float2*>(rf + ((size_t)s * 32 + i) * 2);
    const float2 xv = *reinterpret_cast<const float2*>(X + (size_t)t * DD + hh * HD + 2 * i);
    const float o0 = (xv.x * cs.x - xv.y * cs.y) * scale;
    const float o1 = (xv.x * cs.y + xv.y * cs.x) * scale;
    __nv_bfloat16 h0, h1, l0, l1;
    split_bf16(o0, h0, l0);
    split_bf16(o1, h1, l1);
    const size_t o = (size_t)t * DD + hh * HD + 2 * i;
    *reinterpret_cast<__nv_bfloat162*>(hi + o) = __nv_bfloat162(h0, h1);
    *reinterpret_cast<__nv_bfloat162*>(lo + o) = __nv_bfloat162(l0, l1);
}

// ====================== V transpose -> split bf16 ============================
__global__ void vtrans_split(const float* __restrict__ V,
                             __nv_bfloat16* __restrict__ vh, __nv_bfloat16* __restrict__ vl) {
    __shared__ float tile[32][33];
    const int bh = blockIdx.z, b = bh >> 4, hh = bh & 15;
    const int t0 = blockIdx.x * 32, d0 = blockIdx.y * 32;
    const int tx = threadIdx.x & 31, ty = threadIdx.x >> 5;
#pragma unroll
    for (int i = 0; i < 4; i++) {
        const int tt = ty + i * 8;
        tile[tt][tx] = V[(size_t)(b * SS + t0 + tt) * DD + hh * HD + d0 + tx];
    }
    __syncthreads();
#pragma unroll
    for (int i = 0; i < 4; i++) {
        const int dd = ty + i * 8;
        const float v = tile[tx][dd];
        __nv_bfloat16 h, l;
        split_bf16(v, h, l);
        const size_t o = (size_t)(bh * HD + d0 + dd) * SS + t0 + tx;
        vh[o] = h;
        vl[o] = l;
    }
}

// ========================= silu(gate)*up -> bf16 split =======================
__global__ void silu_mul_split(const float* __restrict__ g, const float* __restrict__ u,
                               __nv_bfloat16* __restrict__ hi, __nv_bfloat16* __restrict__ lo) {
    const size_t i = (size_t)blockIdx.x * blockDim.x + threadIdx.x;
    const float gv = g[i];
    const float r = gv / (1.f + __expf(-gv)) * u[i];
    __nv_bfloat16 h, l;
    split_bf16(r, h, l);
    hi[i] = h;
    lo[i] = l;
}

// ================================= launch ====================================
extern "C" void kernel_launch(void* const* d_in, const int* in_sizes, int n_in,
                              void* d_out, int out_size) {
    const float* x   = (const float*)d_in[0];
    const float* rf  = (const float*)d_in[1];
    const float* anw = (const float*)d_in[3];
    const float* fnw = (const float*)d_in[4];
    const float* wq  = (const float*)d_in[5];
    const float* wk  = (const float*)d_in[6];
    const float* wv  = (const float*)d_in[7];
    const float* wo  = (const float*)d_in[8];
    const float* wg  = (const float*)d_in[9];
    const float* wu  = (const float*)d_in[10];
    const float* wd  = (const float*)d_in[11];
    float* out = (float*)d_out;

    float *q, *k, *v, *gt, *up;
    __nv_bfloat16 *ahi, *alo, *qsh, *qsl, *ksh, *ksl, *vth, *vtl;
    __nv_bfloat16 *wqh, *wql, *wkh, *wkl, *wvh, *wvl, *woh, *wol;
    __nv_bfloat16 *wgh, *wgl, *wuh, *wul, *wdh, *wdl;
    cudaGetSymbolAddress((void**)&q,  g_q);
    cudaGetSymbolAddress((void**)&k,  g_k);
    cudaGetSymbolAddress((void**)&v,  g_v);
    cudaGetSymbolAddress((void**)&gt, g_gate);
    cudaGetSymbolAddress((void**)&up, g_up);
    cudaGetSymbolAddress((void**)&ahi, g_ahi);
    cudaGetSymbolAddress((void**)&alo, g_alo);
    cudaGetSymbolAddress((void**)&qsh, g_qsh); cudaGetSymbolAddress((void**)&qsl, g_qsl);
    cudaGetSymbolAddress((void**)&ksh, g_ksh); cudaGetSymbolAddress((void**)&ksl, g_ksl);
    cudaGetSymbolAddress((void**)&vth, g_vth); cudaGetSymbolAddress((void**)&vtl, g_vtl);
    cudaGetSymbolAddress((void**)&wqh, g_wqh); cudaGetSymbolAddress((void**)&wql, g_wql);
    cudaGetSymbolAddress((void**)&wkh, g_wkh); cudaGetSymbolAddress((void**)&wkl, g_wkl);
    cudaGetSymbolAddress((void**)&wvh, g_wvh); cudaGetSymbolAddress((void**)&wvl, g_wvl);
    cudaGetSymbolAddress((void**)&woh, g_woh); cudaGetSymbolAddress((void**)&wol, g_wol);
    cudaGetSymbolAddress((void**)&wgh, g_wgh); cudaGetSymbolAddress((void**)&wgl, g_wgl);
    cudaGetSymbolAddress((void**)&wuh, g_wuh); cudaGetSymbolAddress((void**)&wul, g_wul);
    cudaGetSymbolAddress((void**)&wdh, g_wdh); cudaGetSymbolAddress((void**)&wdl, g_wdl);

    cudaFuncSetAttribute(hgemm_split, cudaFuncAttributeMaxDynamicSharedMemorySize, HG_DSM);
    cudaFuncSetAttribute(flash_attn, cudaFuncAttributeMaxDynamicSharedMemorySize, FA_DSM);

    // weight conversion (transpose + split)
    wconv_kernel<<<dim3(1024/32, 1024/32), 256>>>(wq, wqh, wql, 1024, 1024);
    wconv_kernel<<<dim3(1024/32, 1024/32), 256>>>(wk, wkh, wkl, 1024, 1024);
    wconv_kernel<<<dim3(1024/32, 1024/32), 256>>>(wv, wvh, wvl, 1024, 1024);
    wconv_kernel<<<dim3(1024/32, 1024/32), 256>>>(wo, woh, wol, 1024, 1024);
    wconv_kernel<<<dim3(4096/32, 1024/32), 256>>>(wg, wgh, wgl, 1024, 4096);
    wconv_kernel<<<dim3(4096/32, 1024/32), 256>>>(wu, wuh, wul, 1024, 4096);
    wconv_kernel<<<dim3(1024/32, 4096/32), 256>>>(wd, wdh, wdl, 4096, 1024);

    // 1) attn rmsnorm -> split-bf16 activations
    rmsnorm_split<<<TT, 256>>>(x, anw, ahi, alo);
    // 2) QKV projections
    hgemm_split<<<dim3(TT/128, 1024/128), 256, HG_DSM>>>(ahi, alo, wqh, wql, nullptr, q, TT, 1024, 1024);
    hgemm_split<<<dim3(TT/128, 1024/128), 256, HG_DSM>>>(ahi, alo, wkh, wkl, nullptr, k, TT, 1024, 1024);
    hgemm_split<<<dim3(TT/128, 1024/128), 256, HG_DSM>>>(ahi, alo, wvh, wvl, nullptr, v, TT, 1024, 1024);
    // 3) rope + split (q scaled by 1/sqrt(HD)); V transpose + split
    const int nrope = TT * NH * (HD / 2);
    rope_split<<<nrope / 256, 256>>>(q, rf, qsh, qsl, 0.125f);
    rope_split<<<nrope / 256, 256>>>(k, rf, ksh, ksl, 1.0f);
    vtrans_split<<<dim3(SS/32, HD/32, BB*NH), 256>>>(v, vth, vtl);
    // 4) fused flash attention -> split bf16 attn output
    flash_attn<<<dim3(1, SS/128, BB*NH), 256, FA_DSM>>>(qsh, qsl, ksh, ksl, vth, vtl, ahi, alo);
    // 5) output projection + residual
    hgemm_split<<<dim3(TT/128, 1024/128), 256, HG_DSM>>>(ahi, alo, woh, wol, x, out, TT, 1024, 1024);
    // 6) ffn rmsnorm
    rmsnorm_split<<<TT, 256>>>(out, fnw, ahi, alo);
    // 7) gate / up
    hgemm_split<<<dim3(TT/128, 4096/128), 256, HG_DSM>>>(ahi, alo, wgh, wgl, nullptr, gt, TT, 4096, 1024);
    hgemm_split<<<dim3(TT/128, 4096/128), 256, HG_DSM>>>(ahi, alo, wuh, wul, nullptr, up, TT, 4096, 1024);
    // 8) silu * up -> split bf16
    silu_mul_split<<<(int)(((size_t)TT * INNER) / 256), 256>>>(gt, up, ahi, alo);
    // 9) down projection + residual
    hgemm_split<<<dim3(TT/128, 1024/128), 256, HG_DSM>>>(ahi, alo, wdh, wdl, out, out, TT, 1024, 4096);
}

// round 8
// speedup vs baseline: 2.2588x; 1.0068x over previous
#include <cuda_runtime.h>
#include <cuda_bf16.h>
#include <math.h>
#include <stdint.h>

#define BB 2
#define SS 2048
#define DD 1024
#define NH 16
#define HD 64
#define TT (BB*SS)        // 4096 tokens
#define INNER 4096

// ===================== scratch (device globals; no cudaMalloc) ===============
__device__ __align__(256) float g_q[(size_t)TT*DD];            // 16 MB
__device__ __align__(256) float g_k[(size_t)TT*DD];            // 16 MB
__device__ __align__(256) float g_v[(size_t)TT*DD];            // 16 MB
__device__ __align__(256) float g_gate[(size_t)TT*INNER];      // 64 MB
__device__ __align__(256) float g_up[(size_t)TT*INNER];        // 64 MB
// split-bf16 activation buffers (A operand of GEMMs), max K = 4096
__device__ __align__(256) __nv_bfloat16 g_ahi[(size_t)TT*INNER];
__device__ __align__(256) __nv_bfloat16 g_alo[(size_t)TT*INNER];
// split-bf16 roped Q/K and transposed V
__device__ __align__(256) __nv_bfloat16 g_qsh[(size_t)TT*DD], g_qsl[(size_t)TT*DD];
__device__ __align__(256) __nv_bfloat16 g_ksh[(size_t)TT*DD], g_ksl[(size_t)TT*DD];
__device__ __align__(256) __nv_bfloat16 g_vth[(size_t)TT*DD], g_vtl[(size_t)TT*DD];
// split-bf16 transposed weights [N,K]
__device__ __align__(256) __nv_bfloat16 g_wqh[1024*1024], g_wql[1024*1024];
__device__ __align__(256) __nv_bfloat16 g_wkh[1024*1024], g_wkl[1024*1024];
__device__ __align__(256) __nv_bfloat16 g_wvh[1024*1024], g_wvl[1024*1024];
__device__ __align__(256) __nv_bfloat16 g_woh[1024*1024], g_wol[1024*1024];
__device__ __align__(256) __nv_bfloat16 g_wgh[(size_t)4096*1024], g_wgl[(size_t)4096*1024];
__device__ __align__(256) __nv_bfloat16 g_wuh[(size_t)4096*1024], g_wul[(size_t)4096*1024];
__device__ __align__(256) __nv_bfloat16 g_wdh[(size_t)1024*4096], g_wdl[(size_t)1024*4096];

// ============================== PTX helpers ==================================
__device__ __forceinline__ uint32_t smem_u32(const void* p) {
    uint32_t a;
    asm("{ .reg .u64 t; cvta.to.shared.u64 t, %1; cvt.u32.u64 %0, t; }" : "=r"(a) : "l"(p));
    return a;
}
__device__ __forceinline__ void cp16(uint32_t dst, const void* src) {
    asm volatile("cp.async.cg.shared.global [%0], [%1], 16;\n" :: "r"(dst), "l"(src));
}
__device__ __forceinline__ void cp_commit() { asm volatile("cp.async.commit_group;\n" ::: "memory"); }
template <int N> __device__ __forceinline__ void cp_wait() {
    asm volatile("cp.async.wait_group %0;\n" :: "n"(N) : "memory");
}
__device__ __forceinline__ void ldm4(uint32_t* r, uint32_t addr) {
    asm volatile("ldmatrix.sync.aligned.m8n8.x4.shared.b16 {%0,%1,%2,%3}, [%4];"
        : "=r"(r[0]), "=r"(r[1]), "=r"(r[2]), "=r"(r[3]) : "r"(addr));
}
__device__ __forceinline__ void mma16816(float* c, const uint32_t* a, uint32_t b0, uint32_t b1) {
    asm volatile("mma.sync.aligned.m16n8k16.row.col.f32.bf16.bf16.f32 "
        "{%0,%1,%2,%3}, {%4,%5,%6,%7}, {%8,%9}, {%0,%1,%2,%3};"
        : "+f"(c[0]), "+f"(c[1]), "+f"(c[2]), "+f"(c[3])
        : "r"(a[0]), "r"(a[1]), "r"(a[2]), "r"(a[3]), "r"(b0), "r"(b1));
}
__device__ __forceinline__ void split_bf16(float v, __nv_bfloat16& h, __nv_bfloat16& l) {
    h = __float2bfloat16(v);
    l = __float2bfloat16(v - __bfloat162float(h));
}
__device__ __forceinline__ void pack_split2(float a, float b, uint32_t& h, uint32_t& l) {
    __nv_bfloat16 ha, la, hb, lb;
    split_bf16(a, ha, la);
    split_bf16(b, hb, lb);
    __nv_bfloat162 ph(ha, hb), pl(la, lb);
    h = *reinterpret_cast<uint32_t*>(&ph);
    l = *reinterpret_cast<uint32_t*>(&pl);
}

// ====================== HMMA split-bf16 dense GEMM ===========================
// CTA tile 256x128, warp tile 64x64 (8 warps, 4x2). K chunk 32.
#define KC 32
#define LDA 40
#define ATILE_B (256*LDA*2)          // 20480 B
#define BTILE_B (128*LDA*2)          // 10240 B
#define HSTAGE_B (2*ATILE_B + 2*BTILE_B) // 61440 B
#define HG_DSM (2*HSTAGE_B)          // 122880 B

__global__ void __launch_bounds__(256, 1) hgemm_split(
    const __nv_bfloat16* __restrict__ Ahi, const __nv_bfloat16* __restrict__ Alo,
    const __nv_bfloat16* __restrict__ Bhi, const __nv_bfloat16* __restrict__ Blo,
    const float* __restrict__ R, float* __restrict__ C, int M, int N, int K)
{
    extern __shared__ __align__(16) char smem[];
    const int tid = threadIdx.x;
    const int lane = tid & 31, wid = tid >> 5;
    const int wm = wid & 3, wn = wid >> 2;            // 4x2 warp grid, 64x64 tiles
    const int bm = blockIdx.x * 256, bn = blockIdx.y * 128;
    const uint32_t sbase = smem_u32(smem);

    float acc[4][8][4] = {};                          // 128 regs

    // loaders: A tiles 1024 chunks (4/thread), B tiles 512 chunks (2/thread)
    const int ar_[4] = { (tid) >> 2, (tid+256) >> 2, (tid+512) >> 2, (tid+768) >> 2 };
    const int ac_ = tid & 3;
    const int br_[2] = { (tid) >> 2, (tid+256) >> 2 };

#define LOAD_STAGE(st, k0)                                                     \
    do {                                                                       \
        const uint32_t sb_ = sbase + (st) * HSTAGE_B;                          \
        _Pragma("unroll")                                                      \
        for (int i_ = 0; i_ < 4; i_++) {                                       \
            const uint32_t dd_ = (uint32_t)(ar_[i_] * LDA * 2 + ac_ * 16);     \
            const size_t so_ = (size_t)(bm + ar_[i_]) * K + (k0) + ac_ * 8;    \
            cp16(sb_ + dd_,           Ahi + so_);                              \
            cp16(sb_ + ATILE_B + dd_, Alo + so_);                              \
        }                                                                      \
        _Pragma("unroll")                                                      \
        for (int i_ = 0; i_ < 2; i_++) {                                       \
            const uint32_t dd_ = (uint32_t)(br_[i_] * LDA * 2 + ac_ * 16);     \
            const size_t so_ = (size_t)(bn + br_[i_]) * K + (k0) + ac_ * 8;    \
            cp16(sb_ + 2*ATILE_B + dd_,           Bhi + so_);                  \
            cp16(sb_ + 2*ATILE_B + BTILE_B + dd_, Blo + so_);                  \
        }                                                                      \
        cp_commit();                                                           \
    } while (0)

    const int NCK = K / KC;
    LOAD_STAGE(0, 0);
    LOAD_STAGE(1, KC);

    const uint32_t lmoff = (uint32_t)((lane & 15) * LDA + (lane >> 4) * 8) * 2;
    const uint32_t aRowOff = (uint32_t)(wm * 64) * LDA * 2;
    const uint32_t bRowOff = (uint32_t)(wn * 64) * LDA * 2;

    for (int kc = 0; kc < NCK; kc++) {
        if (kc < NCK - 1) cp_wait<1>(); else cp_wait<0>();
        __syncthreads();
        const uint32_t sb = sbase + (kc & 1) * HSTAGE_B;
#pragma unroll
        for (int kk = 0; kk < 2; kk++) {
            const uint32_t koff = kk * 32;
            uint32_t bh[4][4], bl[4][4];
#pragma unroll
            for (int np = 0; np < 4; np++) {
                const uint32_t b = sb + 2*ATILE_B + bRowOff + (uint32_t)(np * 16) * LDA * 2 + koff + lmoff;
                ldm4(bh[np], b);
                ldm4(bl[np], b + BTILE_B);
            }
#pragma unroll
            for (int mf = 0; mf < 4; mf++) {
                uint32_t ah[4], al[4];
                const uint32_t a = sb + aRowOff + (uint32_t)(mf * 16) * LDA * 2 + koff + lmoff;
                ldm4(ah, a);
                ldm4(al, a + ATILE_B);
#pragma unroll
                for (int np = 0; np < 4; np++) {
                    mma16816(acc[mf][2*np],   ah, bh[np][0], bh[np][2]);
                    mma16816(acc[mf][2*np+1], ah, bh[np][1], bh[np][3]);
                    mma16816(acc[mf][2*np],   ah, bl[np][0], bl[np][2]);
                    mma16816(acc[mf][2*np+1], ah, bl[np][1], bl[np][3]);
                    mma16816(acc[mf][2*np],   al, bh[np][0], bh[np][2]);
                    mma16816(acc[mf][2*np+1], al, bh[np][1], bh[np][3]);
                }
            }
        }
        __syncthreads();
        if (kc + 2 < NCK) LOAD_STAGE(kc & 1, (kc + 2) * KC);
    }
#undef LOAD_STAGE

#pragma unroll
    for (int mf = 0; mf < 4; mf++)
#pragma unroll
        for (int nf = 0; nf < 8; nf++) {
            const int row0 = bm + wm * 64 + mf * 16 + (lane >> 2);
            const int col  = bn + wn * 64 + nf * 8 + (lane & 3) * 2;
            const size_t o0 = (size_t)row0 * N + col;
            const size_t o1 = o0 + (size_t)8 * N;
            float2 v0 = make_float2(acc[mf][nf][0], acc[mf][nf][1]);
            float2 v1 = make_float2(acc[mf][nf][2], acc[mf][nf][3]);
            if (R) {
                const float2 r0 = *reinterpret_cast<const float2*>(R + o0);
                const float2 r1 = *reinterpret_cast<const float2*>(R + o1);
                v0.x += r0.x; v0.y += r0.y; v1.x += r1.x; v1.y += r1.y;
            }
            *reinterpret_cast<float2*>(C + o0) = v0;
            *reinterpret_cast<float2*>(C + o1) = v1;
        }
}

// ========================= fused flash attention =============================
#define FLDA 72
#define FLDV 136
#define FQT (128*FLDA*2)
#define FVT (64*FLDV*2)
#define FSTAGE (2*FQT + 2*FVT)
#define FA_DSM (2*FQT + 2*FSTAGE)       // 180224 B

__global__ void __launch_bounds__(256, 1) flash_attn(
    const __nv_bfloat16* __restrict__ qh, const __nv_bfloat16* __restrict__ ql,
    const __nv_bfloat16* __restrict__ kh, const __nv_bfloat16* __restrict__ kl,
    const __nv_bfloat16* __restrict__ vh, const __nv_bfloat16* __restrict__ vl,
    __nv_bfloat16* __restrict__ Oh, __nv_bfloat16* __restrict__ Ol)
{
    const int bh = blockIdx.z, b = bh >> 4, hh = bh & 15;
    const int qb = (int)(gridDim.y - 1 - blockIdx.y);
    const int bm = qb * 128;
    const int nck = qb + 1;
    extern __shared__ __align__(16) char smem[];
    const uint32_t sbQ = smem_u32(smem);
    const int tid = threadIdx.x, lane = tid & 31, wid = tid >> 5;

    const __nv_bfloat16* Qh = qh + (size_t)(b * SS) * DD + hh * HD;
    const __nv_bfloat16* Ql = ql + (size_t)(b * SS) * DD + hh * HD;
    const __nv_bfloat16* Kh = kh + (size_t)(b * SS) * DD + hh * HD;
    const __nv_bfloat16* Kl = kl + (size_t)(b * SS) * DD + hh * HD;
    const __nv_bfloat16* Vh = vh + (size_t)(bh * HD) * SS;
    const __nv_bfloat16* Vl = vl + (size_t)(bh * HD) * SS;

#define FLOADKV(st, kc2)                                                        \
    do {                                                                        \
        const int t0_ = (kc2) * 128;                                            \
        const uint32_t sk_ = sbQ + 2*FQT + (st) * FSTAGE;                       \
        const uint32_t sv_ = sk_ + 2*FQT;                                       \
        _Pragma("unroll")                                                       \
        for (int i_ = 0; i_ < 4; i_++) {                                        \
            const int id_ = tid + (i_ << 8);                                    \
            const int r_ = id_ >> 3, c_ = id_ & 7;                              \
            const uint32_t dd_ = (uint32_t)(r_ * FLDA + c_ * 8) * 2;            \
            const size_t so_ = (size_t)(t0_ + r_) * DD + c_ * 8;                \
            cp16(sk_ + dd_,        Kh + so_);                                   \
            cp16(sk_ + FQT + dd_,  Kl + so_);                                   \
        }                                                                       \
        _Pragma("unroll")                                                       \
        for (int i_ = 0; i_ < 4; i_++) {                                        \
            const int id_ = tid + (i_ << 8);                                    \
            const int r_ = id_ >> 4, c_ = id_ & 15;                             \
            const uint32_t dd_ = (uint32_t)(r_ * FLDV + c_ * 8) * 2;            \
            const size_t so_ = (size_t)r_ * SS + t0_ + c_ * 8;                  \
            cp16(sv_ + dd_,        Vh + so_);                                   \
            cp16(sv_ + FVT + dd_,  Vl + so_);                                   \
        }                                                                       \
        cp_commit();                                                            \
    } while (0)

#pragma unroll
    for (int i = 0; i < 4; i++) {
        const int id = tid + (i << 8);
        const int r = id >> 3, c = id & 7;
        const uint32_t dd = (uint32_t)(r * FLDA + c * 8) * 2;
        const size_t so = (size_t)(bm + r) * DD + c * 8;
        cp16(sbQ + dd,        Qh + so);
        cp16(sbQ + FQT + dd,  Ql + so);
    }
    FLOADKV(0, 0);

    const uint32_t lmA = (uint32_t)((lane & 15) * FLDA + (lane >> 4) * 8) * 2;
    const uint32_t lmV = (uint32_t)((lane & 15) * FLDV + (lane >> 4) * 8) * 2;
    const uint32_t aRow = (uint32_t)(wid * 16) * FLDA * 2;
    const int r0 = bm + wid * 16 + (lane >> 2);
    const int cbase = (lane & 3) * 2;

    float o[8][4] = {};
    float m0 = -INFINITY, m1 = -INFINITY, l0 = 0.f, l1 = 0.f;

    for (int kc = 0; kc < nck; kc++) {
        if (kc + 1 < nck) { FLOADKV((kc + 1) & 1, kc + 1); cp_wait<1>(); }
        else cp_wait<0>();
        __syncthreads();
        const uint32_t sk = sbQ + 2*FQT + (kc & 1) * FSTAGE;
        const uint32_t sv = sk + 2*FQT;

        float s[16][4] = {};
#pragma unroll
        for (int kk = 0; kk < 4; kk++) {
            const uint32_t koff = kk * 32;
            uint32_t aH[4], aL[4];
            ldm4(aH, sbQ + aRow + koff + lmA);
            ldm4(aL, sbQ + FQT + aRow + koff + lmA);
#pragma unroll
            for (int np = 0; np < 8; np++) {
                uint32_t bH[4], bL[4];
                const uint32_t ba = sk + (uint32_t)(np * 16) * FLDA * 2 + koff + lmA;
                ldm4(bH, ba);
                ldm4(bL, ba + FQT);
                mma16816(s[2*np],   aH, bH[0], bH[2]);
                mma16816(s[2*np+1], aH, bH[1], bH[3]);
                mma16816(s[2*np],   aH, bL[0], bL[2]);
                mma16816(s[2*np+1], aH, bL[1], bL[3]);
                mma16816(s[2*np],   aL, bH[0], bH[2]);
                mma16816(s[2*np+1], aL, bH[1], bH[3]);
            }
        }

        if (kc == qb) {
            const int t0 = kc * 128;
#pragma unroll
            for (int j = 0; j < 16; j++) {
                const int col = t0 + j * 8 + cbase;
                if (col > r0)         s[j][0] = -INFINITY;
                if (col + 1 > r0)     s[j][1] = -INFINITY;
                if (col > r0 + 8)     s[j][2] = -INFINITY;
                if (col + 1 > r0 + 8) s[j][3] = -INFINITY;
            }
        }

        float cm0 = -INFINITY, cm1 = -INFINITY;
#pragma unroll
        for (int j = 0; j < 16; j++) {
            cm0 = fmaxf(cm0, fmaxf(s[j][0], s[j][1]));
            cm1 = fmaxf(cm1, fmaxf(s[j][2], s[j][3]));
        }
        cm0 = fmaxf(cm0, __shfl_xor_sync(0xffffffffu, cm0, 1));
        cm0 = fmaxf(cm0, __shfl_xor_sync(0xffffffffu, cm0, 2));
        cm1 = fmaxf(cm1, __shfl_xor_sync(0xffffffffu, cm1, 1));
        cm1 = fmaxf(cm1, __shfl_xor_sync(0xffffffffu, cm1, 2));
        const float nm0 = fmaxf(m0, cm0), nm1 = fmaxf(m1, cm1);
        const float f0 = __expf(m0 - nm0), f1 = __expf(m1 - nm1);
        float rs0 = 0.f, rs1 = 0.f;
#pragma unroll
        for (int j = 0; j < 16; j++) {
            s[j][0] = __expf(s[j][0] - nm0);
            s[j][1] = __expf(s[j][1] - nm0);
            s[j][2] = __expf(s[j][2] - nm1);
            s[j][3] = __expf(s[j][3] - nm1);
            rs0 += s[j][0] + s[j][1];
            rs1 += s[j][2] + s[j][3];
        }
        rs0 += __shfl_xor_sync(0xffffffffu, rs0, 1);
        rs0 += __shfl_xor_sync(0xffffffffu, rs0, 2);
        rs1 += __shfl_xor_sync(0xffffffffu, rs1, 1);
        rs1 += __shfl_xor_sync(0xffffffffu, rs1, 2);
        l0 = l0 * f0 + rs0;
        l1 = l1 * f1 + rs1;
        m0 = nm0; m1 = nm1;
#pragma unroll
        for (int nf = 0; nf < 8; nf++) {
            o[nf][0] *= f0; o[nf][1] *= f0;
            o[nf][2] *= f1; o[nf][3] *= f1;
        }

        uint32_t pH[8][4], pL[8][4];
#pragma unroll
        for (int ks = 0; ks < 8; ks++) {
            pack_split2(s[2*ks][0],   s[2*ks][1],   pH[ks][0], pL[ks][0]);
            pack_split2(s[2*ks][2],   s[2*ks][3],   pH[ks][1], pL[ks][1]);
            pack_split2(s[2*ks+1][0], s[2*ks+1][1], pH[ks][2], pL[ks][2]);
            pack_split2(s[2*ks+1][2], s[2*ks+1][3], pH[ks][3], pL[ks][3]);
        }

#pragma unroll
        for (int ks = 0; ks < 8; ks++) {
            const uint32_t koff = ks * 32;
#pragma unroll
            for (int nd = 0; nd < 4; nd++) {
                uint32_t vH[4], vL[4];
                const uint32_t ba = sv + (uint32_t)(nd * 16) * FLDV * 2 + koff + lmV;
                ldm4(vH, ba);
                ldm4(vL, ba + FVT);
                mma16816(o[2*nd],   pH[ks], vH[0], vH[2]);
                mma16816(o[2*nd+1], pH[ks], vH[1], vH[3]);
                mma16816(o[2*nd],   pH[ks], vL[0], vL[2]);
                mma16816(o[2*nd+1], pH[ks], vL[1], vL[3]);
                mma16816(o[2*nd],   pL[ks], vH[0], vH[2]);
                mma16816(o[2*nd+1], pL[ks], vH[1], vH[3]);
            }
        }
        __syncthreads();
    }
#undef FLOADKV

    const float il0 = 1.f / l0, il1 = 1.f / l1;
#pragma unroll
    for (int nf = 0; nf < 8; nf++) {
        const int col = hh * HD + nf * 8 + cbase;
        const size_t o0 = (size_t)(b * SS + r0) * DD + col;
        const size_t o1 = o0 + (size_t)8 * DD;
        __nv_bfloat16 h0, h1, h2, h3, q0, q1, q2, q3;
        split_bf16(o[nf][0] * il0, h0, q0);
        split_bf16(o[nf][1] * il0, h1, q1);
        split_bf16(o[nf][2] * il1, h2, q2);
        split_bf16(o[nf][3] * il1, h3, q3);
        *reinterpret_cast<__nv_bfloat162*>(Oh + o0) = __nv_bfloat162(h0, h1);
        *reinterpret_cast<__nv_bfloat162*>(Oh + o1) = __nv_bfloat162(h2, h3);
        *reinterpret_cast<__nv_bfloat162*>(Ol + o0) = __nv_bfloat162(q0, q1);
        *reinterpret_cast<__nv_bfloat162*>(Ol + o1) = __nv_bfloat162(q2, q3);
    }
}

// =================== weight transpose + bf16 split ===========================
__global__ void __launch_bounds__(256) wconv_kernel(const float* __restrict__ W,
        __nv_bfloat16* __restrict__ hi, __nv_bfloat16* __restrict__ lo, int K, int N) {
    __shared__ float t[32][33];
    const int bx = blockIdx.x * 32;
    const int by = blockIdx.y * 32;
    const int tx = threadIdx.x & 31, ty = threadIdx.x >> 5;
#pragma unroll
    for (int i = 0; i < 4; i++) {
        const int ky = ty + i * 8;
        t[ky][tx] = W[(size_t)(by + ky) * N + bx + tx];
    }
    __syncthreads();
#pragma unroll
    for (int i = 0; i < 4; i++) {
        const int ny = ty + i * 8;
        const float v = t[tx][ny];
        __nv_bfloat16 h, l;
        split_bf16(v, h, l);
        const size_t o = (size_t)(bx + ny) * K + by + tx;
        hi[o] = h;
        lo[o] = l;
    }
}

// ============================ rmsnorm -> bf16 split ==========================
__global__ void rmsnorm_split(const float* __restrict__ x, const float* __restrict__ w,
                              __nv_bfloat16* __restrict__ hi, __nv_bfloat16* __restrict__ lo) {
    __shared__ float red[8];
    const int row = blockIdx.x;
    const float* xr = x + (size_t)row * DD;
    float vals[4];
    float ss = 0.f;
#pragma unroll
    for (int i = 0; i < 4; i++) {
        vals[i] = xr[threadIdx.x + i * 256];
        ss += vals[i] * vals[i];
    }
#pragma unroll
    for (int off = 16; off; off >>= 1) ss += __shfl_xor_sync(0xffffffffu, ss, off);
    if ((threadIdx.x & 31) == 0) red[threadIdx.x >> 5] = ss;
    __syncthreads();
    if (threadIdx.x < 32) {
        float s2 = (threadIdx.x < 8) ? red[threadIdx.x] : 0.f;
#pragma unroll
        for (int off = 4; off; off >>= 1) s2 += __shfl_xor_sync(0xffffffffu, s2, off);
        if (threadIdx.x == 0) red[0] = s2;
    }
    __syncthreads();
    const float rms = rsqrtf(red[0] * (1.0f / DD) + 1e-6f);
#pragma unroll
    for (int i = 0; i < 4; i++) {
        const int c = threadIdx.x + i * 256;
        const float v = vals[i] * rms * w[c];
        __nv_bfloat16 h, l;
        split_bf16(v, h, l);
        const size_t o = (size_t)row * DD + c;
        hi[o] = h;
        lo[o] = l;
    }
}

// ======================= rope -> bf16 split (+scale) =========================
__global__ void rope_split(const float* __restrict__ X, const float* __restrict__ rf,
                           __nv_bfloat16* __restrict__ hi, __nv_bfloat16* __restrict__ lo,
                           float scale) {
    const int idx = blockIdx.x * blockDim.x + threadIdx.x;
    if (idx >= TT * NH * (HD / 2)) return;
    const int i = idx & 31;
    const int hh = (idx >> 5) & (NH - 1);
    const int t = idx >> 9;
    const int s = t & (SS - 1);
    const float2 cs = *reinterpret_cast<const float2*>(rf + ((size_t)s * 32 + i) * 2);
    const float2 xv = *reinterpret_cast<const float2*>(X + (size_t)t * DD + hh * HD + 2 * i);
    const float o0 = (xv.x * cs.x - xv.y * cs.y) * scale;
    const float o1 = (xv.x * cs.y + xv.y * cs.x) * scale;
    __nv_bfloat16 h0, h1, l0, l1;
    split_bf16(o0, h0, l0);
    split_bf16(o1, h1, l1);
    const size_t o = (size_t)t * DD + hh * HD + 2 * i;
    *reinterpret_cast<__nv_bfloat162*>(hi + o) = __nv_bfloat162(h0, h1);
    *reinterpret_cast<__nv_bfloat162*>(lo + o) = __nv_bfloat162(l0, l1);
}

// ====================== V transpose -> split bf16 ============================
__global__ void vtrans_split(const float* __restrict__ V,
                             __nv_bfloat16* __restrict__ vh, __nv_bfloat16* __restrict__ vl) {
    __shared__ float tile[32][33];
    const int bh = blockIdx.z, b = bh >> 4, hh = bh & 15;
    const int t0 = blockIdx.x * 32, d0 = blockIdx.y * 32;
    const int tx = threadIdx.x & 31, ty = threadIdx.x >> 5;
#pragma unroll
    for (int i = 0; i < 4; i++) {
        const int tt = ty + i * 8;
        tile[tt][tx] = V[(size_t)(b * SS + t0 + tt) * DD + hh * HD + d0 + tx];
    }
    __syncthreads();
#pragma unroll
    for (int i = 0; i < 4; i++) {
        const int dd = ty + i * 8;
        const float v = tile[tx][dd];
        __nv_bfloat16 h, l;
        split_bf16(v, h, l);
        const size_t o = (size_t)(bh * HD + d0 + dd) * SS + t0 + tx;
        vh[o] = h;
        vl[o] = l;
    }
}

// ========================= silu(gate)*up -> bf16 split =======================
__global__ void silu_mul_split(const float* __restrict__ g, const float* __restrict__ u,
                               __nv_bfloat16* __restrict__ hi, __nv_bfloat16* __restrict__ lo) {
    const size_t i = (size_t)blockIdx.x * blockDim.x + threadIdx.x;
    const float gv = g[i];
    const float r = gv / (1.f + __expf(-gv)) * u[i];
    __nv_bfloat16 h, l;
    split_bf16(r, h, l);
    hi[i] = h;
    lo[i] = l;
}

// ================================= launch ====================================
extern "C" void kernel_launch(void* const* d_in, const int* in_sizes, int n_in,
                              void* d_out, int out_size) {
    const float* x   = (const float*)d_in[0];
    const float* rf  = (const float*)d_in[1];
    const float* anw = (const float*)d_in[3];
    const float* fnw = (const float*)d_in[4];
    const float* wq  = (const float*)d_in[5];
    const float* wk  = (const float*)d_in[6];
    const float* wv  = (const float*)d_in[7];
    const float* wo  = (const float*)d_in[8];
    const float* wg  = (const float*)d_in[9];
    const float* wu  = (const float*)d_in[10];
    const float* wd  = (const float*)d_in[11];
    float* out = (float*)d_out;

    float *q, *k, *v, *gt, *up;
    __nv_bfloat16 *ahi, *alo, *qsh, *qsl, *ksh, *ksl, *vth, *vtl;
    __nv_bfloat16 *wqh, *wql, *wkh, *wkl, *wvh, *wvl, *woh, *wol;
    __nv_bfloat16 *wgh, *wgl, *wuh, *wul, *wdh, *wdl;
    cudaGetSymbolAddress((void**)&q,  g_q);
    cudaGetSymbolAddress((void**)&k,  g_k);
    cudaGetSymbolAddress((void**)&v,  g_v);
    cudaGetSymbolAddress((void**)&gt, g_gate);
    cudaGetSymbolAddress((void**)&up, g_up);
    cudaGetSymbolAddress((void**)&ahi, g_ahi);
    cudaGetSymbolAddress((void**)&alo, g_alo);
    cudaGetSymbolAddress((void**)&qsh, g_qsh); cudaGetSymbolAddress((void**)&qsl, g_qsl);
    cudaGetSymbolAddress((void**)&ksh, g_ksh); cudaGetSymbolAddress((void**)&ksl, g_ksl);
    cudaGetSymbolAddress((void**)&vth, g_vth); cudaGetSymbolAddress((void**)&vtl, g_vtl);
    cudaGetSymbolAddress((void**)&wqh, g_wqh); cudaGetSymbolAddress((void**)&wql, g_wql);
    cudaGetSymbolAddress((void**)&wkh, g_wkh); cudaGetSymbolAddress((void**)&wkl, g_wkl);
    cudaGetSymbolAddress((void**)&wvh, g_wvh); cudaGetSymbolAddress((void**)&wvl, g_wvl);
    cudaGetSymbolAddress((void**)&woh, g_woh); cudaGetSymbolAddress((void**)&wol, g_wol);
    cudaGetSymbolAddress((void**)&wgh, g_wgh); cudaGetSymbolAddress((void**)&wgl, g_wgl);
    cudaGetSymbolAddress((void**)&wuh, g_wuh); cudaGetSymbolAddress((void**)&wul, g_wul);
    cudaGetSymbolAddress((void**)&wdh, g_wdh); cudaGetSymbolAddress((void**)&wdl, g_wdl);

    cudaFuncSetAttribute(hgemm_split, cudaFuncAttributeMaxDynamicSharedMemorySize, HG_DSM);
    cudaFuncSetAttribute(flash_attn, cudaFuncAttributeMaxDynamicSharedMemorySize, FA_DSM);

    // weight conversion (transpose + split)
    wconv_kernel<<<dim3(1024/32, 1024/32), 256>>>(wq, wqh, wql, 1024, 1024);
    wconv_kernel<<<dim3(1024/32, 1024/32), 256>>>(wk, wkh, wkl, 1024, 1024);
    wconv_kernel<<<dim3(1024/32, 1024/32), 256>>>(wv, wvh, wvl, 1024, 1024);
    wconv_kernel<<<dim3(1024/32, 1024/32), 256>>>(wo, woh, wol, 1024, 1024);
    wconv_kernel<<<dim3(4096/32, 1024/32), 256>>>(wg, wgh, wgl, 1024, 4096);
    wconv_kernel<<<dim3(4096/32, 1024/32), 256>>>(wu, wuh, wul, 1024, 4096);
    wconv_kernel<<<dim3(1024/32, 4096/32), 256>>>(wd, wdh, wdl, 4096, 1024);

    // 1) attn rmsnorm -> split-bf16 activations
    rmsnorm_split<<<TT, 256>>>(x, anw, ahi, alo);
    // 2) QKV projections
    hgemm_split<<<dim3(TT/256, 1024/128), 256, HG_DSM>>>(ahi, alo, wqh, wql, nullptr, q, TT, 1024, 1024);
    hgemm_split<<<dim3(TT/256, 1024/128), 256, HG_DSM>>>(ahi, alo, wkh, wkl, nullptr, k, TT, 1024, 1024);
    hgemm_split<<<dim3(TT/256, 1024/128), 256, HG_DSM>>>(ahi, alo, wvh, wvl, nullptr, v, TT, 1024, 1024);
    // 3) rope + split (q scaled by 1/sqrt(HD)); V transpose + split
    const int nrope = TT * NH * (HD / 2);
    rope_split<<<nrope / 256, 256>>>(q, rf, qsh, qsl, 0.125f);
    rope_split<<<nrope / 256, 256>>>(k, rf, ksh, ksl, 1.0f);
    vtrans_split<<<dim3(SS/32, HD/32, BB*NH), 256>>>(v, vth, vtl);
    // 4) fused flash attention -> split bf16 attn output
    flash_attn<<<dim3(1, SS/128, BB*NH), 256, FA_DSM>>>(qsh, qsl, ksh, ksl, vth, vtl, ahi, alo);
    // 5) output projection + residual
    hgemm_split<<<dim3(TT/256, 1024/128), 256, HG_DSM>>>(ahi, alo, woh, wol, x, out, TT, 1024, 1024);
    // 6) ffn rmsnorm
    rmsnorm_split<<<TT, 256>>>(out, fnw, ahi, alo);
    // 7) gate / up
    hgemm_split<<<dim3(TT/256, 4096/128), 256, HG_DSM>>>(ahi, alo, wgh, wgl, nullptr, gt, TT, 4096, 1024);
    hgemm_split<<<dim3(TT/256, 4096/128), 256, HG_DSM>>>(ahi, alo, wuh, wul, nullptr, up, TT, 4096, 1024);
    // 8) silu * up -> split bf16
    silu_mul_split<<<(int)(((size_t)TT * INNER) / 256), 256>>>(gt, up, ahi, alo);
    // 9) down projection + residual
    hgemm_split<<<dim3(TT/256, 1024/128), 256, HG_DSM>>>(ahi, alo, wdh, wdl, out, out, TT, 1024, 4096);
}

// round 9
// speedup vs baseline: 3.5371x; 1.5660x over previous
#include <cuda_runtime.h>
#include <cuda_fp16.h>
#include <math.h>
#include <stdint.h>

#define BB 2
#define SS 2048
#define DD 1024
#define NH 16
#define HD 64
#define TT (BB*SS)        // 4096 tokens
#define INNER 4096

// ===================== scratch (device globals; no cudaMalloc) ===============
__device__ __align__(256) float g_gate[(size_t)TT*INNER];      // 64 MB fp32
// fp16 activations
__device__ __align__(256) __half g_af[(size_t)TT*INNER];       // A operand (rmsnorm out / attn out)
__device__ __align__(256) __half g_uf[(size_t)TT*INNER];       // silu(gate)*up
__device__ __align__(256) __half g_qsh[(size_t)TT*DD];
__device__ __align__(256) __half g_ksh[(size_t)TT*DD];
__device__ __align__(256) __half g_vth[(size_t)TT*DD];         // V^T [bh*64+d, t]
__device__ __align__(256) __half g_vtmp[(size_t)TT*DD];        // V [t, 1024]
// split-fp16 transposed weights [N,K]
__device__ __align__(256) __half g_wqh[1024*1024], g_wql[1024*1024];
__device__ __align__(256) __half g_wkh[1024*1024], g_wkl[1024*1024];
__device__ __align__(256) __half g_wvh[1024*1024], g_wvl[1024*1024];
__device__ __align__(256) __half g_woh[1024*1024], g_wol[1024*1024];
__device__ __align__(256) __half g_wgh[(size_t)4096*1024], g_wgl[(size_t)4096*1024];
__device__ __align__(256) __half g_wuh[(size_t)4096*1024], g_wul[(size_t)4096*1024];
__device__ __align__(256) __half g_wdh[(size_t)1024*4096], g_wdl[(size_t)1024*4096];

// ============================== PTX helpers ==================================
__device__ __forceinline__ uint32_t smem_u32(const void* p) {
    uint32_t a;
    asm("{ .reg .u64 t; cvta.to.shared.u64 t, %1; cvt.u32.u64 %0, t; }" : "=r"(a) : "l"(p));
    return a;
}
__device__ __forceinline__ void cp16(uint32_t dst, const void* src) {
    asm volatile("cp.async.cg.shared.global [%0], [%1], 16;\n" :: "r"(dst), "l"(src));
}
__device__ __forceinline__ void cp_commit() { asm volatile("cp.async.commit_group;\n" ::: "memory"); }
template <int N> __device__ __forceinline__ void cp_wait() {
    asm volatile("cp.async.wait_group %0;\n" :: "n"(N) : "memory");
}
__device__ __forceinline__ void ldm4(uint32_t* r, uint32_t addr) {
    asm volatile("ldmatrix.sync.aligned.m8n8.x4.shared.b16 {%0,%1,%2,%3}, [%4];"
        : "=r"(r[0]), "=r"(r[1]), "=r"(r[2]), "=r"(r[3]) : "r"(addr));
}
__device__ __forceinline__ void mma16816(float* c, const uint32_t* a, uint32_t b0, uint32_t b1) {
    asm volatile("mma.sync.aligned.m16n8k16.row.col.f32.f16.f16.f32 "
        "{%0,%1,%2,%3}, {%4,%5,%6,%7}, {%8,%9}, {%0,%1,%2,%3};"
        : "+f"(c[0]), "+f"(c[1]), "+f"(c[2]), "+f"(c[3])
        : "r"(a[0]), "r"(a[1]), "r"(a[2]), "r"(a[3]), "r"(b0), "r"(b1));
}
__device__ __forceinline__ uint32_t pack_h2(float a, float b) {
    __half2 p = __floats2half2_rn(a, b);
    return *reinterpret_cast<uint32_t*>(&p);
}
__device__ __forceinline__ void split_h(float v, __half& h, __half& l) {
    h = __float2half(v);
    l = __float2half(v - __half2float(h));
}

// ================ 2-term fp16 GEMM: C = A(fp16) @ (Bhi+Blo)^T =================
// CTA 128x128, warp 32x64 (8 warps 4x2), KC=32. MODE selects epilogue:
// 0: fp32 out (+ optional residual aux)     1: rope(aux=rf)*scale -> fp16
// 2: plain fp16                              3: silu(aux=gate)*acc -> fp16
#define KC 32
#define LDA 40
#define GT_B (128*LDA*2)                 // 10240 B per tile
#define GSTG (3*GT_B)                    // A, Bhi, Blo = 30720 B
#define HG_DSM (2*GSTG)                  // 61440 B

template <int MODE>
__global__ void __launch_bounds__(256, 1) hgemm2(
    const __half* __restrict__ A, const __half* __restrict__ Bhi,
    const __half* __restrict__ Blo, const float* __restrict__ aux,
    float* __restrict__ OutF, __half* __restrict__ OutH,
    int M, int N, int K, float scale)
{
    extern __shared__ __align__(16) char smem[];
    const int tid = threadIdx.x;
    const int lane = tid & 31, wid = tid >> 5;
    const int wm = wid >> 1, wn = wid & 1;
    const int bm = blockIdx.x * 128, bn = blockIdx.y * 128;
    const uint32_t sbase = smem_u32(smem);

    float acc[2][8][4] = {};

    const int r0_ = tid >> 2,            c0_ = tid & 3;
    const int r1_ = (tid + 256) >> 2;
    const uint32_t d0 = (uint32_t)(r0_ * LDA * 2 + c0_ * 16);
    const uint32_t d1 = (uint32_t)(r1_ * LDA * 2 + c0_ * 16);
    const size_t a0 = (size_t)(bm + r0_) * K + c0_ * 8;
    const size_t a1 = (size_t)(bm + r1_) * K + c0_ * 8;
    const size_t b0 = (size_t)(bn + r0_) * K + c0_ * 8;
    const size_t b1 = (size_t)(bn + r1_) * K + c0_ * 8;

#define LOAD_STAGE(st, k0)                                              \
    do {                                                                \
        const uint32_t sb_ = sbase + (st) * GSTG;                       \
        cp16(sb_ + d0,            A   + a0 + (k0));                     \
        cp16(sb_ + d1,            A   + a1 + (k0));                     \
        cp16(sb_ + GT_B + d0,     Bhi + b0 + (k0));                     \
        cp16(sb_ + GT_B + d1,     Bhi + b1 + (k0));                     \
        cp16(sb_ + 2*GT_B + d0,   Blo + b0 + (k0));                     \
        cp16(sb_ + 2*GT_B + d1,   Blo + b1 + (k0));                     \
        cp_commit();                                                    \
    } while (0)

    const int NCK = K / KC;
    LOAD_STAGE(0, 0);
    LOAD_STAGE(1, KC);

    const uint32_t lmoff = (uint32_t)((lane & 15) * LDA + (lane >> 4) * 8) * 2;
    const uint32_t aRowOff = (uint32_t)(wm * 32) * LDA * 2;
    const uint32_t bRowOff = (uint32_t)(wn * 64) * LDA * 2;

    for (int kc = 0; kc < NCK; kc++) {
        if (kc < NCK - 1) cp_wait<1>(); else cp_wait<0>();
        __syncthreads();
        const uint32_t sb = sbase + (kc & 1) * GSTG;
#pragma unroll
        for (int kk = 0; kk < 2; kk++) {
            const uint32_t koff = kk * 32;
            uint32_t ah[2][4], bh[4][4], bl[4][4];
#pragma unroll
            for (int mf = 0; mf < 2; mf++)
                ldm4(ah[mf], sb + aRowOff + (uint32_t)(mf * 16) * LDA * 2 + koff + lmoff);
#pragma unroll
            for (int np = 0; np < 4; np++) {
                const uint32_t b = sb + GT_B + bRowOff + (uint32_t)(np * 16) * LDA * 2 + koff + lmoff;
                ldm4(bh[np], b);
                ldm4(bl[np], b + GT_B);
            }
#pragma unroll
            for (int mf = 0; mf < 2; mf++)
#pragma unroll
                for (int np = 0; np < 4; np++) {
                    mma16816(acc[mf][2*np],   ah[mf], bh[np][0], bh[np][2]);
                    mma16816(acc[mf][2*np+1], ah[mf], bh[np][1], bh[np][3]);
                    mma16816(acc[mf][2*np],   ah[mf], bl[np][0], bl[np][2]);
                    mma16816(acc[mf][2*np+1], ah[mf], bl[np][1], bl[np][3]);
                }
        }
        __syncthreads();
        if (kc + 2 < NCK) LOAD_STAGE(kc & 1, (kc + 2) * KC);
    }
#undef LOAD_STAGE

#pragma unroll
    for (int mf = 0; mf < 2; mf++)
#pragma unroll
        for (int nf = 0; nf < 8; nf++) {
            const int row0 = bm + wm * 32 + mf * 16 + (lane >> 2);
            const int col  = bn + wn * 64 + nf * 8 + (lane & 3) * 2;
            const size_t o0 = (size_t)row0 * N + col;
            const size_t o1 = o0 + (size_t)8 * N;
            float2 v0 = make_float2(acc[mf][nf][0], acc[mf][nf][1]);
            float2 v1 = make_float2(acc[mf][nf][2], acc[mf][nf][3]);
            if (MODE == 0) {
                if (aux) {
                    const float2 r0v = *reinterpret_cast<const float2*>(aux + o0);
                    const float2 r1v = *reinterpret_cast<const float2*>(aux + o1);
                    v0.x += r0v.x; v0.y += r0v.y; v1.x += r1v.x; v1.y += r1v.y;
                }
                *reinterpret_cast<float2*>(OutF + o0) = v0;
                *reinterpret_cast<float2*>(OutF + o1) = v1;
            } else if (MODE == 1) {
                const int i = (col & 63) >> 1;
                const float2 cs0 = *reinterpret_cast<const float2*>(
                    aux + ((size_t)(row0 & (SS - 1)) * 32 + i) * 2);
                const float2 cs1 = *reinterpret_cast<const float2*>(
                    aux + ((size_t)((row0 + 8) & (SS - 1)) * 32 + i) * 2);
                const float p0 = (v0.x * cs0.x - v0.y * cs0.y) * scale;
                const float p1 = (v0.x * cs0.y + v0.y * cs0.x) * scale;
                const float p2 = (v1.x * cs1.x - v1.y * cs1.y) * scale;
                const float p3 = (v1.x * cs1.y + v1.y * cs1.x) * scale;
                *reinterpret_cast<uint32_t*>(OutH + o0) = pack_h2(p0, p1);
                *reinterpret_cast<uint32_t*>(OutH + o1) = pack_h2(p2, p3);
            } else if (MODE == 2) {
                *reinterpret_cast<uint32_t*>(OutH + o0) = pack_h2(v0.x, v0.y);
                *reinterpret_cast<uint32_t*>(OutH + o1) = pack_h2(v1.x, v1.y);
            } else {   // MODE 3: silu(gate) * acc
                const float2 gv0 = *reinterpret_cast<const float2*>(aux + o0);
                const float2 gv1 = *reinterpret_cast<const float2*>(aux + o1);
                const float r00 = gv0.x / (1.f + __expf(-gv0.x)) * v0.x;
                const float r01 = gv0.y / (1.f + __expf(-gv0.y)) * v0.y;
                const float r10 = gv1.x / (1.f + __expf(-gv1.x)) * v1.x;
                const float r11 = gv1.y / (1.f + __expf(-gv1.y)) * v1.y;
                *reinterpret_cast<uint32_t*>(OutH + o0) = pack_h2(r00, r01);
                *reinterpret_cast<uint32_t*>(OutH + o1) = pack_h2(r10, r11);
            }
        }
}

// ================== fused flash attention (fp16, 1-term) =====================
#define FLDA 72
#define FLDV 136
#define FQT (128*FLDA*2)                // 18432 B
#define FVT (64*FLDV*2)                 // 17408 B
#define FSTAGE (FQT + FVT)              // 35840 B
#define FA_DSM (FQT + 2*FSTAGE)         // 90112 B

__global__ void __launch_bounds__(256, 1) flash_attn(
    const __half* __restrict__ qf, const __half* __restrict__ kf,
    const __half* __restrict__ vf, __half* __restrict__ O)
{
    const int bh = blockIdx.z, b = bh >> 4, hh = bh & 15;
    const int qb = (int)(gridDim.y - 1 - blockIdx.y);     // big blocks first
    const int bm = qb * 128;
    const int nck = qb + 1;
    extern __shared__ __align__(16) char smem[];
    const uint32_t sbQ = smem_u32(smem);
    const int tid = threadIdx.x, lane = tid & 31, wid = tid >> 5;

    const __half* Q = qf + (size_t)(b * SS) * DD + hh * HD;
    const __half* Kp = kf + (size_t)(b * SS) * DD + hh * HD;
    const __half* Vp = vf + (size_t)(bh * HD) * SS;

#define FLOADKV(st, kc2)                                                        \
    do {                                                                        \
        const int t0_ = (kc2) * 128;                                            \
        const uint32_t sk_ = sbQ + FQT + (st) * FSTAGE;                         \
        const uint32_t sv_ = sk_ + FQT;                                         \
        _Pragma("unroll")                                                       \
        for (int i_ = 0; i_ < 4; i_++) {                                        \
            const int id_ = tid + (i_ << 8);                                    \
            const int r_ = id_ >> 3, c_ = id_ & 7;                              \
            cp16(sk_ + (uint32_t)(r_ * FLDA + c_ * 8) * 2,                      \
                 Kp + (size_t)(t0_ + r_) * DD + c_ * 8);                        \
        }                                                                       \
        _Pragma("unroll")                                                       \
        for (int i_ = 0; i_ < 4; i_++) {                                        \
            const int id_ = tid + (i_ << 8);                                    \
            const int r_ = id_ >> 4, c_ = id_ & 15;                             \
            cp16(sv_ + (uint32_t)(r_ * FLDV + c_ * 8) * 2,                      \
                 Vp + (size_t)r_ * SS + t0_ + c_ * 8);                          \
        }                                                                       \
        cp_commit();                                                            \
    } while (0)

#pragma unroll
    for (int i = 0; i < 4; i++) {
        const int id = tid + (i << 8);
        const int r = id >> 3, c = id & 7;
        cp16(sbQ + (uint32_t)(r * FLDA + c * 8) * 2, Q + (size_t)(bm + r) * DD + c * 8);
    }
    FLOADKV(0, 0);

    const uint32_t lmA = (uint32_t)((lane & 15) * FLDA + (lane >> 4) * 8) * 2;
    const uint32_t lmV = (uint32_t)((lane & 15) * FLDV + (lane >> 4) * 8) * 2;
    const uint32_t aRow = (uint32_t)(wid * 16) * FLDA * 2;
    const int r0 = bm + wid * 16 + (lane >> 2);
    const int cbase = (lane & 3) * 2;

    float o[8][4] = {};
    float m0 = -INFINITY, m1 = -INFINITY, l0 = 0.f, l1 = 0.f;

    for (int kc = 0; kc < nck; kc++) {
        if (kc + 1 < nck) { FLOADKV((kc + 1) & 1, kc + 1); cp_wait<1>(); }
        else cp_wait<0>();
        __syncthreads();
        const uint32_t sk = sbQ + FQT + (kc & 1) * FSTAGE;
        const uint32_t sv = sk + FQT;

        // ---- S = Q K^T (1 term) ----
        float s[16][4] = {};
#pragma unroll
        for (int kk = 0; kk < 4; kk++) {
            const uint32_t koff = kk * 32;
            uint32_t aH[4];
            ldm4(aH, sbQ + aRow + koff + lmA);
#pragma unroll
            for (int np = 0; np < 8; np++) {
                uint32_t bH[4];
                ldm4(bH, sk + (uint32_t)(np * 16) * FLDA * 2 + koff + lmA);
                mma16816(s[2*np],   aH, bH[0], bH[2]);
                mma16816(s[2*np+1], aH, bH[1], bH[3]);
            }
        }

        if (kc == qb) {
            const int t0 = kc * 128;
#pragma unroll
            for (int j = 0; j < 16; j++) {
                const int col = t0 + j * 8 + cbase;
                if (col > r0)         s[j][0] = -INFINITY;
                if (col + 1 > r0)     s[j][1] = -INFINITY;
                if (col > r0 + 8)     s[j][2] = -INFINITY;
                if (col + 1 > r0 + 8) s[j][3] = -INFINITY;
            }
        }

        // ---- online softmax ----
        float cm0 = -INFINITY, cm1 = -INFINITY;
#pragma unroll
        for (int j = 0; j < 16; j++) {
            cm0 = fmaxf(cm0, fmaxf(s[j][0], s[j][1]));
            cm1 = fmaxf(cm1, fmaxf(s[j][2], s[j][3]));
        }
        cm0 = fmaxf(cm0, __shfl_xor_sync(0xffffffffu, cm0, 1));
        cm0 = fmaxf(cm0, __shfl_xor_sync(0xffffffffu, cm0, 2));
        cm1 = fmaxf(cm1, __shfl_xor_sync(0xffffffffu, cm1, 1));
        cm1 = fmaxf(cm1, __shfl_xor_sync(0xffffffffu, cm1, 2));
        const float nm0 = fmaxf(m0, cm0), nm1 = fmaxf(m1, cm1);
        const float f0 = __expf(m0 - nm0), f1 = __expf(m1 - nm1);
        float rs0 = 0.f, rs1 = 0.f;
#pragma unroll
        for (int j = 0; j < 16; j++) {
            s[j][0] = __expf(s[j][0] - nm0);
            s[j][1] = __expf(s[j][1] - nm0);
            s[j][2] = __expf(s[j][2] - nm1);
            s[j][3] = __expf(s[j][3] - nm1);
            rs0 += s[j][0] + s[j][1];
            rs1 += s[j][2] + s[j][3];
        }
        rs0 += __shfl_xor_sync(0xffffffffu, rs0, 1);
        rs0 += __shfl_xor_sync(0xffffffffu, rs0, 2);
        rs1 += __shfl_xor_sync(0xffffffffu, rs1, 1);
        rs1 += __shfl_xor_sync(0xffffffffu, rs1, 2);
        l0 = l0 * f0 + rs0;
        l1 = l1 * f1 + rs1;
        m0 = nm0; m1 = nm1;
#pragma unroll
        for (int nf = 0; nf < 8; nf++) {
            o[nf][0] *= f0; o[nf][1] *= f0;
            o[nf][2] *= f1; o[nf][3] *= f1;
        }

        // ---- pack P to fp16 A-fragments ----
        uint32_t pH[8][4];
#pragma unroll
        for (int ks = 0; ks < 8; ks++) {
            pH[ks][0] = pack_h2(s[2*ks][0],   s[2*ks][1]);
            pH[ks][1] = pack_h2(s[2*ks][2],   s[2*ks][3]);
            pH[ks][2] = pack_h2(s[2*ks+1][0], s[2*ks+1][1]);
            pH[ks][3] = pack_h2(s[2*ks+1][2], s[2*ks+1][3]);
        }

        // ---- O += P V (1 term) ----
#pragma unroll
        for (int ks = 0; ks < 8; ks++) {
            const uint32_t koff = ks * 32;
#pragma unroll
            for (int nd = 0; nd < 4; nd++) {
                uint32_t vH[4];
                ldm4(vH, sv + (uint32_t)(nd * 16) * FLDV * 2 + koff + lmV);
                mma16816(o[2*nd],   pH[ks], vH[0], vH[2]);
                mma16816(o[2*nd+1], pH[ks], vH[1], vH[3]);
            }
        }
        __syncthreads();
    }
#undef FLOADKV

    const float il0 = 1.f / l0, il1 = 1.f / l1;
#pragma unroll
    for (int nf = 0; nf < 8; nf++) {
        const int col = hh * HD + nf * 8 + cbase;
        const size_t o0 = (size_t)(b * SS + r0) * DD + col;
        const size_t o1 = o0 + (size_t)8 * DD;
        *reinterpret_cast<uint32_t*>(O + o0) = pack_h2(o[nf][0] * il0, o[nf][1] * il0);
        *reinterpret_cast<uint32_t*>(O + o1) = pack_h2(o[nf][2] * il1, o[nf][3] * il1);
    }
}

// =================== weight transpose + fp16 split ===========================
__global__ void __launch_bounds__(256) wconv_kernel(const float* __restrict__ W,
        __half* __restrict__ hi, __half* __restrict__ lo, int K, int N) {
    __shared__ float t[32][33];
    const int bx = blockIdx.x * 32;
    const int by = blockIdx.y * 32;
    const int tx = threadIdx.x & 31, ty = threadIdx.x >> 5;
#pragma unroll
    for (int i = 0; i < 4; i++) {
        const int ky = ty + i * 8;
        t[ky][tx] = W[(size_t)(by + ky) * N + bx + tx];
    }
    __syncthreads();
#pragma unroll
    for (int i = 0; i < 4; i++) {
        const int ny = ty + i * 8;
        const float v = t[tx][ny];
        __half h, l;
        split_h(v, h, l);
        const size_t o = (size_t)(bx + ny) * K + by + tx;
        hi[o] = h;
        lo[o] = l;
    }
}

// ============================ rmsnorm -> fp16 ================================
__global__ void rmsnorm_fp16(const float* __restrict__ x, const float* __restrict__ w,
                             __half* __restrict__ o) {
    __shared__ float red[8];
    const int row = blockIdx.x;
    const float* xr = x + (size_t)row * DD;
    float vals[4];
    float ss = 0.f;
#pragma unroll
    for (int i = 0; i < 4; i++) {
        vals[i] = xr[threadIdx.x + i * 256];
        ss += vals[i] * vals[i];
    }
#pragma unroll
    for (int off = 16; off; off >>= 1) ss += __shfl_xor_sync(0xffffffffu, ss, off);
    if ((threadIdx.x & 31) == 0) red[threadIdx.x >> 5] = ss;
    __syncthreads();
    if (threadIdx.x < 32) {
        float s2 = (threadIdx.x < 8) ? red[threadIdx.x] : 0.f;
#pragma unroll
        for (int off = 4; off; off >>= 1) s2 += __shfl_xor_sync(0xffffffffu, s2, off);
        if (threadIdx.x == 0) red[0] = s2;
    }
    __syncthreads();
    const float rms = rsqrtf(red[0] * (1.0f / DD) + 1e-6f);
#pragma unroll
    for (int i = 0; i < 4; i++) {
        const int c = threadIdx.x + i * 256;
        o[(size_t)row * DD + c] = __float2half(vals[i] * rms * w[c]);
    }
}

// ====================== V transpose (fp16 -> fp16) ===========================
__global__ void vtrans_fp16(const __half* __restrict__ V, __half* __restrict__ vt) {
    __shared__ __half tile[32][33];
    const int bh = blockIdx.z, b = bh >> 4, hh = bh & 15;
    const int t0 = blockIdx.x * 32, d0 = blockIdx.y * 32;
    const int tx = threadIdx.x & 31, ty = threadIdx.x >> 5;
#pragma unroll
    for (int i = 0; i < 4; i++) {
        const int tt = ty + i * 8;
        tile[tt][tx] = V[(size_t)(b * SS + t0 + tt) * DD + hh * HD + d0 + tx];
    }
    __syncthreads();
#pragma unroll
    for (int i = 0; i < 4; i++) {
        const int dd = ty + i * 8;
        vt[(size_t)(bh * HD + d0 + dd) * SS + t0 + tx] = tile[tx][dd];
    }
}

// ================================= launch ====================================
extern "C" void kernel_launch(void* const* d_in, const int* in_sizes, int n_in,
                              void* d_out, int out_size) {
    const float* x   = (const float*)d_in[0];
    const float* rf  = (const float*)d_in[1];
    const float* anw = (const float*)d_in[3];
    const float* fnw = (const float*)d_in[4];
    const float* wq  = (const float*)d_in[5];
    const float* wk  = (const float*)d_in[6];
    const float* wv  = (const float*)d_in[7];
    const float* wo  = (const float*)d_in[8];
    const float* wg  = (const float*)d_in[9];
    const float* wu  = (const float*)d_in[10];
    const float* wd  = (const float*)d_in[11];
    float* out = (float*)d_out;

    float *gt;
    __half *af, *uf, *qsh, *ksh, *vth, *vtmp;
    __half *wqh, *wql, *wkh, *wkl, *wvh, *wvl, *woh, *wol;
    __half *wgh, *wgl, *wuh, *wul, *wdh, *wdl;
    cudaGetSymbolAddress((void**)&gt,  g_gate);
    cudaGetSymbolAddress((void**)&af,  g_af);
    cudaGetSymbolAddress((void**)&uf,  g_uf);
    cudaGetSymbolAddress((void**)&qsh, g_qsh);
    cudaGetSymbolAddress((void**)&ksh, g_ksh);
    cudaGetSymbolAddress((void**)&vth, g_vth);
    cudaGetSymbolAddress((void**)&vtmp, g_vtmp);
    cudaGetSymbolAddress((void**)&wqh, g_wqh); cudaGetSymbolAddress((void**)&wql, g_wql);
    cudaGetSymbolAddress((void**)&wkh, g_wkh); cudaGetSymbolAddress((void**)&wkl, g_wkl);
    cudaGetSymbolAddress((void**)&wvh, g_wvh); cudaGetSymbolAddress((void**)&wvl, g_wvl);
    cudaGetSymbolAddress((void**)&woh, g_woh); cudaGetSymbolAddress((void**)&wol, g_wol);
    cudaGetSymbolAddress((void**)&wgh, g_wgh); cudaGetSymbolAddress((void**)&wgl, g_wgl);
    cudaGetSymbolAddress((void**)&wuh, g_wuh); cudaGetSymbolAddress((void**)&wul, g_wul);
    cudaGetSymbolAddress((void**)&wdh, g_wdh); cudaGetSymbolAddress((void**)&wdl, g_wdl);

    cudaFuncSetAttribute(hgemm2<0>, cudaFuncAttributeMaxDynamicSharedMemorySize, HG_DSM);
    cudaFuncSetAttribute(hgemm2<1>, cudaFuncAttributeMaxDynamicSharedMemorySize, HG_DSM);
    cudaFuncSetAttribute(hgemm2<2>, cudaFuncAttributeMaxDynamicSharedMemorySize, HG_DSM);
    cudaFuncSetAttribute(hgemm2<3>, cudaFuncAttributeMaxDynamicSharedMemorySize, HG_DSM);
    cudaFuncSetAttribute(flash_attn, cudaFuncAttributeMaxDynamicSharedMemorySize, FA_DSM);

    // weight conversion (transpose + fp16 split)
    wconv_kernel<<<dim3(1024/32, 1024/32), 256>>>(wq, wqh, wql, 1024, 1024);
    wconv_kernel<<<dim3(1024/32, 1024/32), 256>>>(wk, wkh, wkl, 1024, 1024);
    wconv_kernel<<<dim3(1024/32, 1024/32), 256>>>(wv, wvh, wvl, 1024, 1024);
    wconv_kernel<<<dim3(1024/32, 1024/32), 256>>>(wo, woh, wol, 1024, 1024);
    wconv_kernel<<<dim3(4096/32, 1024/32), 256>>>(wg, wgh, wgl, 1024, 4096);
    wconv_kernel<<<dim3(4096/32, 1024/32), 256>>>(wu, wuh, wul, 1024, 4096);
    wconv_kernel<<<dim3(1024/32, 4096/32), 256>>>(wd, wdh, wdl, 4096, 1024);

    // 1) attn rmsnorm -> fp16
    rmsnorm_fp16<<<TT, 256>>>(x, anw, af);
    // 2) QKV projections; rope fused into Q/K epilogues, V -> fp16
    hgemm2<1><<<dim3(TT/128, 1024/128), 256, HG_DSM>>>(af, wqh, wql, rf, nullptr, qsh, TT, 1024, 1024, 0.125f);
    hgemm2<1><<<dim3(TT/128, 1024/128), 256, HG_DSM>>>(af, wkh, wkl, rf, nullptr, ksh, TT, 1024, 1024, 1.0f);
    hgemm2<2><<<dim3(TT/128, 1024/128), 256, HG_DSM>>>(af, wvh, wvl, nullptr, nullptr, vtmp, TT, 1024, 1024, 0.f);
    // 3) V transpose
    vtrans_fp16<<<dim3(SS/32, HD/32, BB*NH), 256>>>(vtmp, vth);
    // 4) fused flash attention -> fp16 attn out (af reuse)
    flash_attn<<<dim3(1, SS/128, BB*NH), 256, FA_DSM>>>(qsh, ksh, vth, af);
    // 5) output projection + residual
    hgemm2<0><<<dim3(TT/128, 1024/128), 256, HG_DSM>>>(af, woh, wol, x, out, nullptr, TT, 1024, 1024, 0.f);
    // 6) ffn rmsnorm
    rmsnorm_fp16<<<TT, 256>>>(out, fnw, af);
    // 7) gate; then up with fused silu(gate)*up -> fp16
    hgemm2<0><<<dim3(TT/128, 4096/128), 256, HG_DSM>>>(af, wgh, wgl, nullptr, gt, nullptr, TT, 4096, 1024, 0.f);
    hgemm2<3><<<dim3(TT/128, 4096/128), 256, HG_DSM>>>(af, wuh, wul, gt, nullptr, uf, TT, 4096, 1024, 0.f);
    // 8) down projection + residual
    hgemm2<0><<<dim3(TT/128, 1024/128), 256, HG_DSM>>>(uf, wdh, wdl, out, out, nullptr, TT, 1024, 4096, 0.f);
}

// round 10
// speedup vs baseline: 5.1632x; 1.4597x over previous
#include <cuda_runtime.h>
#include <cuda_fp16.h>
#include <math.h>
#include <stdint.h>

#define BB 2
#define SS 2048
#define DD 1024
#define NH 16
#define HD 64
#define TT (BB*SS)        // 4096 tokens
#define INNER 4096

// ===================== scratch (device globals; no cudaMalloc) ===============
__device__ __align__(256) float g_gate[(size_t)TT*INNER];      // 64 MB fp32
__device__ __align__(256) __half g_af[(size_t)TT*INNER];       // A operand
__device__ __align__(256) __half g_uf[(size_t)TT*INNER];       // silu(gate)*up
__device__ __align__(256) __half g_qsh[(size_t)TT*DD];
__device__ __align__(256) __half g_ksh[(size_t)TT*DD];
__device__ __align__(256) __half g_vth[(size_t)TT*DD];         // V^T [bh*64+d, t]
__device__ __align__(256) __half g_vtmp[(size_t)TT*DD];        // V [t, 1024]
// fp16 transposed weights [N,K]
__device__ __align__(256) __half g_wq[1024*1024];
__device__ __align__(256) __half g_wk[1024*1024];
__device__ __align__(256) __half g_wv[1024*1024];
__device__ __align__(256) __half g_wo[1024*1024];
__device__ __align__(256) __half g_wg[(size_t)4096*1024];
__device__ __align__(256) __half g_wu[(size_t)4096*1024];
__device__ __align__(256) __half g_wd[(size_t)1024*4096];

// ============================== PTX helpers ==================================
__device__ __forceinline__ uint32_t smem_u32(const void* p) {
    uint32_t a;
    asm("{ .reg .u64 t; cvta.to.shared.u64 t, %1; cvt.u32.u64 %0, t; }" : "=r"(a) : "l"(p));
    return a;
}
__device__ __forceinline__ void cp16(uint32_t dst, const void* src) {
    asm volatile("cp.async.cg.shared.global [%0], [%1], 16;\n" :: "r"(dst), "l"(src));
}
__device__ __forceinline__ void cp_commit() { asm volatile("cp.async.commit_group;\n" ::: "memory"); }
template <int N> __device__ __forceinline__ void cp_wait() {
    asm volatile("cp.async.wait_group %0;\n" :: "n"(N) : "memory");
}
__device__ __forceinline__ void ldm4(uint32_t* r, uint32_t addr) {
    asm volatile("ldmatrix.sync.aligned.m8n8.x4.shared.b16 {%0,%1,%2,%3}, [%4];"
        : "=r"(r[0]), "=r"(r[1]), "=r"(r[2]), "=r"(r[3]) : "r"(addr));
}
__device__ __forceinline__ void mma16816(float* c, const uint32_t* a, uint32_t b0, uint32_t b1) {
    asm volatile("mma.sync.aligned.m16n8k16.row.col.f32.f16.f16.f32 "
        "{%0,%1,%2,%3}, {%4,%5,%6,%7}, {%8,%9}, {%0,%1,%2,%3};"
        : "+f"(c[0]), "+f"(c[1]), "+f"(c[2]), "+f"(c[3])
        : "r"(a[0]), "r"(a[1]), "r"(a[2]), "r"(a[3]), "r"(b0), "r"(b1));
}
__device__ __forceinline__ uint32_t pack_h2(float a, float b) {
    __half2 p = __floats2half2_rn(a, b);
    return *reinterpret_cast<uint32_t*>(&p);
}

// ================= 1-term fp16 GEMM: C = A(fp16) @ B(fp16)^T ==================
// CTA 256x128, warp 64x64 (8 warps, 4x2 in m x n), KC=32. MODE epilogues:
// 0: fp32 out (+ optional residual aux)   1: rope(aux=rf)*scale -> fp16
// 2: plain fp16                            3: silu(aux=gate)*acc -> fp16
#define KC 32
#define LDA 40
#define AT_B (256*LDA*2)                 // 20480 B
#define BT_B (128*LDA*2)                 // 10240 B
#define GSTG (AT_B + BT_B)               // 30720 B
#define HG_DSM (2*GSTG)                  // 61440 B

template <int MODE>
__global__ void __launch_bounds__(256, 1) hgemm1(
    const __half* __restrict__ A, const __half* __restrict__ B,
    const float* __restrict__ aux,
    float* __restrict__ OutF, __half* __restrict__ OutH,
    int M, int N, int K, float scale)
{
    extern __shared__ __align__(16) char smem[];
    const int tid = threadIdx.x;
    const int lane = tid & 31, wid = tid >> 5;
    const int wm = wid & 3, wn = wid >> 2;
    const int bm = blockIdx.x * 256, bn = blockIdx.y * 128;
    const uint32_t sbase = smem_u32(smem);

    float acc[4][8][4] = {};

    const int ar_[4] = { tid >> 2, (tid+256) >> 2, (tid+512) >> 2, (tid+768) >> 2 };
    const int ac_ = tid & 3;
    const int br_[2] = { tid >> 2, (tid+256) >> 2 };

#define LOAD_STAGE(st, k0)                                                     \
    do {                                                                       \
        const uint32_t sb_ = sbase + (st) * GSTG;                              \
        _Pragma("unroll")                                                      \
        for (int i_ = 0; i_ < 4; i_++)                                         \
            cp16(sb_ + (uint32_t)(ar_[i_] * LDA * 2 + ac_ * 16),               \
                 A + (size_t)(bm + ar_[i_]) * K + (k0) + ac_ * 8);             \
        _Pragma("unroll")                                                      \
        for (int i_ = 0; i_ < 2; i_++)                                         \
            cp16(sb_ + AT_B + (uint32_t)(br_[i_] * LDA * 2 + ac_ * 16),        \
                 B + (size_t)(bn + br_[i_]) * K + (k0) + ac_ * 8);             \
        cp_commit();                                                           \
    } while (0)

    const int NCK = K / KC;
    LOAD_STAGE(0, 0);
    LOAD_STAGE(1, KC);

    const uint32_t lmoff = (uint32_t)((lane & 15) * LDA + (lane >> 4) * 8) * 2;
    const uint32_t aRowOff = (uint32_t)(wm * 64) * LDA * 2;
    const uint32_t bRowOff = (uint32_t)(wn * 64) * LDA * 2;

    for (int kc = 0; kc < NCK; kc++) {
        if (kc < NCK - 1) cp_wait<1>(); else cp_wait<0>();
        __syncthreads();
        const uint32_t sb = sbase + (kc & 1) * GSTG;
#pragma unroll
        for (int kk = 0; kk < 2; kk++) {
            const uint32_t koff = kk * 32;
            uint32_t bh[4][4];
#pragma unroll
            for (int np = 0; np < 4; np++)
                ldm4(bh[np], sb + AT_B + bRowOff + (uint32_t)(np * 16) * LDA * 2 + koff + lmoff);
#pragma unroll
            for (int mf = 0; mf < 4; mf++) {
                uint32_t ah[4];
                ldm4(ah, sb + aRowOff + (uint32_t)(mf * 16) * LDA * 2 + koff + lmoff);
#pragma unroll
                for (int np = 0; np < 4; np++) {
                    mma16816(acc[mf][2*np],   ah, bh[np][0], bh[np][2]);
                    mma16816(acc[mf][2*np+1], ah, bh[np][1], bh[np][3]);
                }
            }
        }
        __syncthreads();
        if (kc + 2 < NCK) LOAD_STAGE(kc & 1, (kc + 2) * KC);
    }
#undef LOAD_STAGE

#pragma unroll
    for (int mf = 0; mf < 4; mf++)
#pragma unroll
        for (int nf = 0; nf < 8; nf++) {
            const int row0 = bm + wm * 64 + mf * 16 + (lane >> 2);
            const int col  = bn + wn * 64 + nf * 8 + (lane & 3) * 2;
            const size_t o0 = (size_t)row0 * N + col;
            const size_t o1 = o0 + (size_t)8 * N;
            float2 v0 = make_float2(acc[mf][nf][0], acc[mf][nf][1]);
            float2 v1 = make_float2(acc[mf][nf][2], acc[mf][nf][3]);
            if (MODE == 0) {
                if (aux) {
                    const float2 r0v = *reinterpret_cast<const float2*>(aux + o0);
                    const float2 r1v = *reinterpret_cast<const float2*>(aux + o1);
                    v0.x += r0v.x; v0.y += r0v.y; v1.x += r1v.x; v1.y += r1v.y;
                }
                *reinterpret_cast<float2*>(OutF + o0) = v0;
                *reinterpret_cast<float2*>(OutF + o1) = v1;
            } else if (MODE == 1) {
                const int i = (col & 63) >> 1;
                const float2 cs0 = *reinterpret_cast<const float2*>(
                    aux + ((size_t)(row0 & (SS - 1)) * 32 + i) * 2);
                const float2 cs1 = *reinterpret_cast<const float2*>(
                    aux + ((size_t)((row0 + 8) & (SS - 1)) * 32 + i) * 2);
                const float p0 = (v0.x * cs0.x - v0.y * cs0.y) * scale;
                const float p1 = (v0.x * cs0.y + v0.y * cs0.x) * scale;
                const float p2 = (v1.x * cs1.x - v1.y * cs1.y) * scale;
                const float p3 = (v1.x * cs1.y + v1.y * cs1.x) * scale;
                *reinterpret_cast<uint32_t*>(OutH + o0) = pack_h2(p0, p1);
                *reinterpret_cast<uint32_t*>(OutH + o1) = pack_h2(p2, p3);
            } else if (MODE == 2) {
                *reinterpret_cast<uint32_t*>(OutH + o0) = pack_h2(v0.x, v0.y);
                *reinterpret_cast<uint32_t*>(OutH + o1) = pack_h2(v1.x, v1.y);
            } else {
                const float2 gv0 = *reinterpret_cast<const float2*>(aux + o0);
                const float2 gv1 = *reinterpret_cast<const float2*>(aux + o1);
                const float r00 = gv0.x / (1.f + __expf(-gv0.x)) * v0.x;
                const float r01 = gv0.y / (1.f + __expf(-gv0.y)) * v0.y;
                const float r10 = gv1.x / (1.f + __expf(-gv1.x)) * v1.x;
                const float r11 = gv1.y / (1.f + __expf(-gv1.y)) * v1.y;
                *reinterpret_cast<uint32_t*>(OutH + o0) = pack_h2(r00, r01);
                *reinterpret_cast<uint32_t*>(OutH + o1) = pack_h2(r10, r11);
            }
        }
}

// ================== fused flash attention (fp16, 1-term) =====================
#define FLDA 72
#define FLDV 136
#define FQT (128*FLDA*2)                // 18432 B
#define FVT (64*FLDV*2)                 // 17408 B
#define FSTAGE (FQT + FVT)              // 35840 B
#define FA_DSM (FQT + 2*FSTAGE)         // 90112 B

__global__ void __launch_bounds__(256, 1) flash_attn(
    const __half* __restrict__ qf, const __half* __restrict__ kf,
    const __half* __restrict__ vf, __half* __restrict__ O)
{
    const int bh = blockIdx.z, b = bh >> 4, hh = bh & 15;
    const int qb = (int)(gridDim.y - 1 - blockIdx.y);
    const int bm = qb * 128;
    const int nck = qb + 1;
    extern __shared__ __align__(16) char smem[];
    const uint32_t sbQ = smem_u32(smem);
    const int tid = threadIdx.x, lane = tid & 31, wid = tid >> 5;

    const __half* Q = qf + (size_t)(b * SS) * DD + hh * HD;
    const __half* Kp = kf + (size_t)(b * SS) * DD + hh * HD;
    const __half* Vp = vf + (size_t)(bh * HD) * SS;

#define FLOADKV(st, kc2)                                                        \
    do {                                                                        \
        const int t0_ = (kc2) * 128;                                            \
        const uint32_t sk_ = sbQ + FQT + (st) * FSTAGE;                         \
        const uint32_t sv_ = sk_ + FQT;                                         \
        _Pragma("unroll")                                                       \
        for (int i_ = 0; i_ < 4; i_++) {                                        \
            const int id_ = tid + (i_ << 8);                                    \
            const int r_ = id_ >> 3, c_ = id_ & 7;                              \
            cp16(sk_ + (uint32_t)(r_ * FLDA + c_ * 8) * 2,                      \
                 Kp + (size_t)(t0_ + r_) * DD + c_ * 8);                        \
        }                                                                       \
        _Pragma("unroll")                                                       \
        for (int i_ = 0; i_ < 4; i_++) {                                        \
            const int id_ = tid + (i_ << 8);                                    \
            const int r_ = id_ >> 4, c_ = id_ & 15;                             \
            cp16(sv_ + (uint32_t)(r_ * FLDV + c_ * 8) * 2,                      \
                 Vp + (size_t)r_ * SS + t0_ + c_ * 8);                          \
        }                                                                       \
        cp_commit();                                                            \
    } while (0)

#pragma unroll
    for (int i = 0; i < 4; i++) {
        const int id = tid + (i << 8);
        const int r = id >> 3, c = id & 7;
        cp16(sbQ + (uint32_t)(r * FLDA + c * 8) * 2, Q + (size_t)(bm + r) * DD + c * 8);
    }
    FLOADKV(0, 0);

    const uint32_t lmA = (uint32_t)((lane & 15) * FLDA + (lane >> 4) * 8) * 2;
    const uint32_t lmV = (uint32_t)((lane & 15) * FLDV + (lane >> 4) * 8) * 2;
    const uint32_t aRow = (uint32_t)(wid * 16) * FLDA * 2;
    const int r0 = bm + wid * 16 + (lane >> 2);
    const int cbase = (lane & 3) * 2;

    float o[8][4] = {};
    float m0 = -INFINITY, m1 = -INFINITY, l0 = 0.f, l1 = 0.f;

    for (int kc = 0; kc < nck; kc++) {
        if (kc + 1 < nck) { FLOADKV((kc + 1) & 1, kc + 1); cp_wait<1>(); }
        else cp_wait<0>();
        __syncthreads();
        const uint32_t sk = sbQ + FQT + (kc & 1) * FSTAGE;
        const uint32_t sv = sk + FQT;

        float s[16][4] = {};
#pragma unroll
        for (int kk = 0; kk < 4; kk++) {
            const uint32_t koff = kk * 32;
            uint32_t aH[4];
            ldm4(aH, sbQ + aRow + koff + lmA);
#pragma unroll
            for (int np = 0; np < 8; np++) {
                uint32_t bH[4];
                ldm4(bH, sk + (uint32_t)(np * 16) * FLDA * 2 + koff + lmA);
                mma16816(s[2*np],   aH, bH[0], bH[2]);
                mma16816(s[2*np+1], aH, bH[1], bH[3]);
            }
        }

        if (kc == qb) {
            const int t0 = kc * 128;
#pragma unroll
            for (int j = 0; j < 16; j++) {
                const int col = t0 + j * 8 + cbase;
                if (col > r0)         s[j][0] = -INFINITY;
                if (col + 1 > r0)     s[j][1] = -INFINITY;
                if (col > r0 + 8)     s[j][2] = -INFINITY;
                if (col + 1 > r0 + 8) s[j][3] = -INFINITY;
            }
        }

        float cm0 = -INFINITY, cm1 = -INFINITY;
#pragma unroll
        for (int j = 0; j < 16; j++) {
            cm0 = fmaxf(cm0, fmaxf(s[j][0], s[j][1]));
            cm1 = fmaxf(cm1, fmaxf(s[j][2], s[j][3]));
        }
        cm0 = fmaxf(cm0, __shfl_xor_sync(0xffffffffu, cm0, 1));
        cm0 = fmaxf(cm0, __shfl_xor_sync(0xffffffffu, cm0, 2));
        cm1 = fmaxf(cm1, __shfl_xor_sync(0xffffffffu, cm1, 1));
        cm1 = fmaxf(cm1, __shfl_xor_sync(0xffffffffu, cm1, 2));
        const float nm0 = fmaxf(m0, cm0), nm1 = fmaxf(m1, cm1);
        const float f0 = __expf(m0 - nm0), f1 = __expf(m1 - nm1);
        float rs0 = 0.f, rs1 = 0.f;
#pragma unroll
        for (int j = 0; j < 16; j++) {
            s[j][0] = __expf(s[j][0] - nm0);
            s[j][1] = __expf(s[j][1] - nm0);
            s[j][2] = __expf(s[j][2] - nm1);
            s[j][3] = __expf(s[j][3] - nm1);
            rs0 += s[j][0] + s[j][1];
            rs1 += s[j][2] + s[j][3];
        }
        rs0 += __shfl_xor_sync(0xffffffffu, rs0, 1);
        rs0 += __shfl_xor_sync(0xffffffffu, rs0, 2);
        rs1 += __shfl_xor_sync(0xffffffffu, rs1, 1);
        rs1 += __shfl_xor_sync(0xffffffffu, rs1, 2);
        l0 = l0 * f0 + rs0;
        l1 = l1 * f1 + rs1;
        m0 = nm0; m1 = nm1;
#pragma unroll
        for (int nf = 0; nf < 8; nf++) {
            o[nf][0] *= f0; o[nf][1] *= f0;
            o[nf][2] *= f1; o[nf][3] *= f1;
        }

        uint32_t pH[8][4];
#pragma unroll
        for (int ks = 0; ks < 8; ks++) {
            pH[ks][0] = pack_h2(s[2*ks][0],   s[2*ks][1]);
            pH[ks][1] = pack_h2(s[2*ks][2],   s[2*ks][3]);
            pH[ks][2] = pack_h2(s[2*ks+1][0], s[2*ks+1][1]);
            pH[ks][3] = pack_h2(s[2*ks+1][2], s[2*ks+1][3]);
        }

#pragma unroll
        for (int ks = 0; ks < 8; ks++) {
            const uint32_t koff = ks * 32;
#pragma unroll
            for (int nd = 0; nd < 4; nd++) {
                uint32_t vH[4];
                ldm4(vH, sv + (uint32_t)(nd * 16) * FLDV * 2 + koff + lmV);
                mma16816(o[2*nd],   pH[ks], vH[0], vH[2]);
                mma16816(o[2*nd+1], pH[ks], vH[1], vH[3]);
            }
        }
        __syncthreads();
    }
#undef FLOADKV

    const float il0 = 1.f / l0, il1 = 1.f / l1;
#pragma unroll
    for (int nf = 0; nf < 8; nf++) {
        const int col = hh * HD + nf * 8 + cbase;
        const size_t o0 = (size_t)(b * SS + r0) * DD + col;
        const size_t o1 = o0 + (size_t)8 * DD;
        *reinterpret_cast<uint32_t*>(O + o0) = pack_h2(o[nf][0] * il0, o[nf][1] * il0);
        *reinterpret_cast<uint32_t*>(O + o1) = pack_h2(o[nf][2] * il1, o[nf][3] * il1);
    }
}

// =================== weight transpose -> fp16 ================================
__global__ void __launch_bounds__(256) wconv_kernel(const float* __restrict__ W,
        __half* __restrict__ hi, int K, int N) {
    __shared__ float t[32][33];
    const int bx = blockIdx.x * 32;
    const int by = blockIdx.y * 32;
    const int tx = threadIdx.x & 31, ty = threadIdx.x >> 5;
#pragma unroll
    for (int i = 0; i < 4; i++) {
        const int ky = ty + i * 8;
        t[ky][tx] = W[(size_t)(by + ky) * N + bx + tx];
    }
    __syncthreads();
#pragma unroll
    for (int i = 0; i < 4; i++) {
        const int ny = ty + i * 8;
        hi[(size_t)(bx + ny) * K + by + tx] = __float2half(t[tx][ny]);
    }
}

// ============================ rmsnorm -> fp16 ================================
__global__ void rmsnorm_fp16(const float* __restrict__ x, const float* __restrict__ w,
                             __half* __restrict__ o) {
    __shared__ float red[8];
    const int row = blockIdx.x;
    const float* xr = x + (size_t)row * DD;
    float vals[4];
    float ss = 0.f;
#pragma unroll
    for (int i = 0; i < 4; i++) {
        vals[i] = xr[threadIdx.x + i * 256];
        ss += vals[i] * vals[i];
    }
#pragma unroll
    for (int off = 16; off; off >>= 1) ss += __shfl_xor_sync(0xffffffffu, ss, off);
    if ((threadIdx.x & 31) == 0) red[threadIdx.x >> 5] = ss;
    __syncthreads();
    if (threadIdx.x < 32) {
        float s2 = (threadIdx.x < 8) ? red[threadIdx.x] : 0.f;
#pragma unroll
        for (int off = 4; off; off >>= 1) s2 += __shfl_xor_sync(0xffffffffu, s2, off);
        if (threadIdx.x == 0) red[0] = s2;
    }
    __syncthreads();
    const float rms = rsqrtf(red[0] * (1.0f / DD) + 1e-6f);
#pragma unroll
    for (int i = 0; i < 4; i++) {
        const int c = threadIdx.x + i * 256;
        o[(size_t)row * DD + c] = __float2half(vals[i] * rms * w[c]);
    }
}

// ====================== V transpose (fp16 -> fp16) ===========================
__global__ void vtrans_fp16(const __half* __restrict__ V, __half* __restrict__ vt) {
    __shared__ __half tile[32][33];
    const int bh = blockIdx.z, b = bh >> 4, hh = bh & 15;
    const int t0 = blockIdx.x * 32, d0 = blockIdx.y * 32;
    const int tx = threadIdx.x & 31, ty = threadIdx.x >> 5;
#pragma unroll
    for (int i = 0; i < 4; i++) {
        const int tt = ty + i * 8;
        tile[tt][tx] = V[(size_t)(b * SS + t0 + tt) * DD + hh * HD + d0 + tx];
    }
    __syncthreads();
#pragma unroll
    for (int i = 0; i < 4; i++) {
        const int dd = ty + i * 8;
        vt[(size_t)(bh * HD + d0 + dd) * SS + t0 + tx] = tile[tx][dd];
    }
}

// ================================= launch ====================================
extern "C" void kernel_launch(void* const* d_in, const int* in_sizes, int n_in,
                              void* d_out, int out_size) {
    const float* x   = (const float*)d_in[0];
    const float* rf  = (const float*)d_in[1];
    const float* anw = (const float*)d_in[3];
    const float* fnw = (const float*)d_in[4];
    const float* wq  = (const float*)d_in[5];
    const float* wk  = (const float*)d_in[6];
    const float* wv  = (const float*)d_in[7];
    const float* wo  = (const float*)d_in[8];
    const float* wg  = (const float*)d_in[9];
    const float* wu  = (const float*)d_in[10];
    const float* wd  = (const float*)d_in[11];
    float* out = (float*)d_out;

    float *gt;
    __half *af, *uf, *qsh, *ksh, *vth, *vtmp;
    __half *wqf, *wkf, *wvf, *wof, *wgf, *wuf, *wdf;
    cudaGetSymbolAddress((void**)&gt,  g_gate);
    cudaGetSymbolAddress((void**)&af,  g_af);
    cudaGetSymbolAddress((void**)&uf,  g_uf);
    cudaGetSymbolAddress((void**)&qsh, g_qsh);
    cudaGetSymbolAddress((void**)&ksh, g_ksh);
    cudaGetSymbolAddress((void**)&vth, g_vth);
    cudaGetSymbolAddress((void**)&vtmp, g_vtmp);
    cudaGetSymbolAddress((void**)&wqf, g_wq);
    cudaGetSymbolAddress((void**)&wkf, g_wk);
    cudaGetSymbolAddress((void**)&wvf, g_wv);
    cudaGetSymbolAddress((void**)&wof, g_wo);
    cudaGetSymbolAddress((void**)&wgf, g_wg);
    cudaGetSymbolAddress((void**)&wuf, g_wu);
    cudaGetSymbolAddress((void**)&wdf, g_wd);

    cudaFuncSetAttribute(hgemm1<0>, cudaFuncAttributeMaxDynamicSharedMemorySize, HG_DSM);
    cudaFuncSetAttribute(hgemm1<1>, cudaFuncAttributeMaxDynamicSharedMemorySize, HG_DSM);
    cudaFuncSetAttribute(hgemm1<2>, cudaFuncAttributeMaxDynamicSharedMemorySize, HG_DSM);
    cudaFuncSetAttribute(hgemm1<3>, cudaFuncAttributeMaxDynamicSharedMemorySize, HG_DSM);
    cudaFuncSetAttribute(flash_attn, cudaFuncAttributeMaxDynamicSharedMemorySize, FA_DSM);

    // weight conversion (transpose -> fp16)
    wconv_kernel<<<dim3(1024/32, 1024/32), 256>>>(wq, wqf, 1024, 1024);
    wconv_kernel<<<dim3(1024/32, 1024/32), 256>>>(wk, wkf, 1024, 1024);
    wconv_kernel<<<dim3(1024/32, 1024/32), 256>>>(wv, wvf, 1024, 1024);
    wconv_kernel<<<dim3(1024/32, 1024/32), 256>>>(wo, wof, 1024, 1024);
    wconv_kernel<<<dim3(4096/32, 1024/32), 256>>>(wg, wgf, 1024, 4096);
    wconv_kernel<<<dim3(4096/32, 1024/32), 256>>>(wu, wuf, 1024, 4096);
    wconv_kernel<<<dim3(1024/32, 4096/32), 256>>>(wd, wdf, 4096, 1024);

    // 1) attn rmsnorm -> fp16
    rmsnorm_fp16<<<TT, 256>>>(x, anw, af);
    // 2) QKV projections; rope fused into Q/K epilogues, V -> fp16
    hgemm1<1><<<dim3(TT/256, 1024/128), 256, HG_DSM>>>(af, wqf, rf, nullptr, qsh, TT, 1024, 1024, 0.125f);
    hgemm1<1><<<dim3(TT/256, 1024/128), 256, HG_DSM>>>(af, wkf, rf, nullptr, ksh, TT, 1024, 1024, 1.0f);
    hgemm1<2><<<dim3(TT/256, 1024/128), 256, HG_DSM>>>(af, wvf, nullptr, nullptr, vtmp, TT, 1024, 1024, 0.f);
    // 3) V transpose
    vtrans_fp16<<<dim3(SS/32, HD/32, BB*NH), 256>>>(vtmp, vth);
    // 4) fused flash attention -> fp16 attn out
    flash_attn<<<dim3(1, SS/128, BB*NH), 256, FA_DSM>>>(qsh, ksh, vth, af);
    // 5) output projection + residual
    hgemm1<0><<<dim3(TT/256, 1024/128), 256, HG_DSM>>>(af, wof, x, out, nullptr, TT, 1024, 1024, 0.f);
    // 6) ffn rmsnorm
    rmsnorm_fp16<<<TT, 256>>>(out, fnw, af);
    // 7) gate; then up with fused silu(gate)*up -> fp16
    hgemm1<0><<<dim3(TT/256, 4096/128), 256, HG_DSM>>>(af, wgf, nullptr, gt, nullptr, TT, 4096, 1024, 0.f);
    hgemm1<3><<<dim3(TT/256, 4096/128), 256, HG_DSM>>>(af, wuf, gt, nullptr, uf, TT, 4096, 1024, 0.f);
    // 8) down projection + residual
    hgemm1<0><<<dim3(TT/256, 1024/128), 256, HG_DSM>>>(uf, wdf, out, out, nullptr, TT, 1024, 4096, 0.f);
}

// round 11
// speedup vs baseline: 5.2711x; 1.0209x over previous
#include <cuda_runtime.h>
#include <cuda_fp16.h>
#include <math.h>
#include <stdint.h>

#define BB 2
#define SS 2048
#define DD 1024
#define NH 16
#define HD 64
#define TT (BB*SS)        // 4096 tokens
#define INNER 4096

// ===================== scratch (device globals; no cudaMalloc) ===============
__device__ __align__(256) __half g_af[(size_t)TT*INNER];       // A operand
__device__ __align__(256) __half g_gf[(size_t)TT*INNER];       // gate (fp16)
__device__ __align__(256) __half g_uf[(size_t)TT*INNER];       // silu(gate)*up
__device__ __align__(256) __half g_qsh[(size_t)TT*DD];
__device__ __align__(256) __half g_ksh[(size_t)TT*DD];
__device__ __align__(256) __half g_vth[(size_t)TT*DD];         // V^T [bh*64+d, t]
__device__ __align__(256) __half g_vtmp[(size_t)TT*DD];        // V [t, 1024]
// fp16 transposed weights [N,K]
__device__ __align__(256) __half g_wqkv[(size_t)3072*1024];    // q rows 0-1023, k 1024-2047, v 2048-3071
__device__ __align__(256) __half g_wo[1024*1024];
__device__ __align__(256) __half g_wg[(size_t)4096*1024];
__device__ __align__(256) __half g_wu[(size_t)4096*1024];
__device__ __align__(256) __half g_wd[(size_t)1024*4096];

// ============================== PTX helpers ==================================
__device__ __forceinline__ uint32_t smem_u32(const void* p) {
    uint32_t a;
    asm("{ .reg .u64 t; cvta.to.shared.u64 t, %1; cvt.u32.u64 %0, t; }" : "=r"(a) : "l"(p));
    return a;
}
__device__ __forceinline__ void cp16(uint32_t dst, const void* src) {
    asm volatile("cp.async.cg.shared.global [%0], [%1], 16;\n" :: "r"(dst), "l"(src));
}
__device__ __forceinline__ void cp_commit() { asm volatile("cp.async.commit_group;\n" ::: "memory"); }
template <int N> __device__ __forceinline__ void cp_wait() {
    asm volatile("cp.async.wait_group %0;\n" :: "n"(N) : "memory");
}
__device__ __forceinline__ void ldm4(uint32_t* r, uint32_t addr) {
    asm volatile("ldmatrix.sync.aligned.m8n8.x4.shared.b16 {%0,%1,%2,%3}, [%4];"
        : "=r"(r[0]), "=r"(r[1]), "=r"(r[2]), "=r"(r[3]) : "r"(addr));
}
__device__ __forceinline__ void mma16816(float* c, const uint32_t* a, uint32_t b0, uint32_t b1) {
    asm volatile("mma.sync.aligned.m16n8k16.row.col.f32.f16.f16.f32 "
        "{%0,%1,%2,%3}, {%4,%5,%6,%7}, {%8,%9}, {%0,%1,%2,%3};"
        : "+f"(c[0]), "+f"(c[1]), "+f"(c[2]), "+f"(c[3])
        : "r"(a[0]), "r"(a[1]), "r"(a[2]), "r"(a[3]), "r"(b0), "r"(b1));
}
__device__ __forceinline__ uint32_t pack_h2(float a, float b) {
    __half2 p = __floats2half2_rn(a, b);
    return *reinterpret_cast<uint32_t*>(&p);
}

// ================= 1-term fp16 GEMM: C = A(fp16) @ B(fp16)^T ==================
// CTA 256x128, warp 64x64 (8 warps, 4x2 m x n), KC=32. MODE epilogues:
// 0: fp32 out (+ optional residual aux)     2: plain fp16
// 3: silu(auxh=gate fp16)*acc -> fp16       5: merged QKV (rope q/k, plain v)
#define KC 32
#define LDA 40
#define AT_B (256*LDA*2)                 // 20480 B
#define BT_B (128*LDA*2)                 // 10240 B
#define GSTG (AT_B + BT_B)               // 30720 B
#define HG_DSM (2*GSTG)                  // 61440 B

template <int MODE>
__global__ void __launch_bounds__(256, 1) hgemm1(
    const __half* __restrict__ A, const __half* __restrict__ B,
    const float* __restrict__ aux, const __half* __restrict__ auxh,
    float* __restrict__ OutF, __half* __restrict__ OutH,
    __half* __restrict__ OutH2, __half* __restrict__ OutH3,
    int M, int N, int K)
{
    extern __shared__ __align__(16) char smem[];
    const int tid = threadIdx.x;
    const int lane = tid & 31, wid = tid >> 5;
    const int wm = wid & 3, wn = wid >> 2;
    const int bm = blockIdx.x * 256, bn = blockIdx.y * 128;
    const uint32_t sbase = smem_u32(smem);

    float acc[4][8][4] = {};

    const int ar_[4] = { tid >> 2, (tid+256) >> 2, (tid+512) >> 2, (tid+768) >> 2 };
    const int ac_ = tid & 3;
    const int br_[2] = { tid >> 2, (tid+256) >> 2 };

#define LOAD_STAGE(st, k0)                                                     \
    do {                                                                       \
        const uint32_t sb_ = sbase + (st) * GSTG;                              \
        _Pragma("unroll")                                                      \
        for (int i_ = 0; i_ < 4; i_++)                                         \
            cp16(sb_ + (uint32_t)(ar_[i_] * LDA * 2 + ac_ * 16),               \
                 A + (size_t)(bm + ar_[i_]) * K + (k0) + ac_ * 8);             \
        _Pragma("unroll")                                                      \
        for (int i_ = 0; i_ < 2; i_++)                                         \
            cp16(sb_ + AT_B + (uint32_t)(br_[i_] * LDA * 2 + ac_ * 16),        \
                 B + (size_t)(bn + br_[i_]) * K + (k0) + ac_ * 8);             \
        cp_commit();                                                           \
    } while (0)

    const int NCK = K / KC;
    LOAD_STAGE(0, 0);
    LOAD_STAGE(1, KC);

    const uint32_t lmoff = (uint32_t)((lane & 15) * LDA + (lane >> 4) * 8) * 2;
    const uint32_t aRowOff = (uint32_t)(wm * 64) * LDA * 2;
    const uint32_t bRowOff = (uint32_t)(wn * 64) * LDA * 2;

    for (int kc = 0; kc < NCK; kc++) {
        if (kc < NCK - 1) cp_wait<1>(); else cp_wait<0>();
        __syncthreads();
        const uint32_t sb = sbase + (kc & 1) * GSTG;
#pragma unroll
        for (int kk = 0; kk < 2; kk++) {
            const uint32_t koff = kk * 32;
            uint32_t bh[4][4];
#pragma unroll
            for (int np = 0; np < 4; np++)
                ldm4(bh[np], sb + AT_B + bRowOff + (uint32_t)(np * 16) * LDA * 2 + koff + lmoff);
#pragma unroll
            for (int mf = 0; mf < 4; mf++) {
                uint32_t ah[4];
                ldm4(ah, sb + aRowOff + (uint32_t)(mf * 16) * LDA * 2 + koff + lmoff);
#pragma unroll
                for (int np = 0; np < 4; np++) {
                    mma16816(acc[mf][2*np],   ah, bh[np][0], bh[np][2]);
                    mma16816(acc[mf][2*np+1], ah, bh[np][1], bh[np][3]);
                }
            }
        }
        __syncthreads();
        if (kc + 2 < NCK) LOAD_STAGE(kc & 1, (kc + 2) * KC);
    }
#undef LOAD_STAGE

#pragma unroll
    for (int mf = 0; mf < 4; mf++)
#pragma unroll
        for (int nf = 0; nf < 8; nf++) {
            const int row0 = bm + wm * 64 + mf * 16 + (lane >> 2);
            const int col  = bn + wn * 64 + nf * 8 + (lane & 3) * 2;
            const size_t o0 = (size_t)row0 * N + col;
            const size_t o1 = o0 + (size_t)8 * N;
            float2 v0 = make_float2(acc[mf][nf][0], acc[mf][nf][1]);
            float2 v1 = make_float2(acc[mf][nf][2], acc[mf][nf][3]);
            if (MODE == 0) {
                if (aux) {
                    const float2 r0v = *reinterpret_cast<const float2*>(aux + o0);
                    const float2 r1v = *reinterpret_cast<const float2*>(aux + o1);
                    v0.x += r0v.x; v0.y += r0v.y; v1.x += r1v.x; v1.y += r1v.y;
                }
                *reinterpret_cast<float2*>(OutF + o0) = v0;
                *reinterpret_cast<float2*>(OutF + o1) = v1;
            } else if (MODE == 2) {
                *reinterpret_cast<uint32_t*>(OutH + o0) = pack_h2(v0.x, v0.y);
                *reinterpret_cast<uint32_t*>(OutH + o1) = pack_h2(v1.x, v1.y);
            } else if (MODE == 3) {
                const __half2 g0 = *reinterpret_cast<const __half2*>(auxh + o0);
                const __half2 g1 = *reinterpret_cast<const __half2*>(auxh + o1);
                const float g00 = __half2float(__low2half(g0)),  g01 = __half2float(__high2half(g0));
                const float g10 = __half2float(__low2half(g1)),  g11 = __half2float(__high2half(g1));
                const float r00 = g00 / (1.f + __expf(-g00)) * v0.x;
                const float r01 = g01 / (1.f + __expf(-g01)) * v0.y;
                const float r10 = g10 / (1.f + __expf(-g10)) * v1.x;
                const float r11 = g11 / (1.f + __expf(-g11)) * v1.y;
                *reinterpret_cast<uint32_t*>(OutH + o0) = pack_h2(r00, r01);
                *reinterpret_cast<uint32_t*>(OutH + o1) = pack_h2(r10, r11);
            } else {       // MODE 5: merged QKV; rng constant per CTA (bn % 1024 tiles)
                const int rng = bn >> 10;
                const int c = col & 1023;
                const size_t q0 = (size_t)row0 * 1024 + c;
                const size_t q1 = q0 + (size_t)8 * 1024;
                if (rng == 2) {
                    *reinterpret_cast<uint32_t*>(OutH3 + q0) = pack_h2(v0.x, v0.y);
                    *reinterpret_cast<uint32_t*>(OutH3 + q1) = pack_h2(v1.x, v1.y);
                } else {
                    __half* Op = (rng == 0) ? OutH : OutH2;
                    const float sc = (rng == 0) ? 0.125f : 1.0f;
                    const int i = (c & 63) >> 1;
                    const float2 cs0 = *reinterpret_cast<const float2*>(
                        aux + ((size_t)(row0 & (SS - 1)) * 32 + i) * 2);
                    const float2 cs1 = *reinterpret_cast<const float2*>(
                        aux + ((size_t)((row0 + 8) & (SS - 1)) * 32 + i) * 2);
                    const float p0 = (v0.x * cs0.x - v0.y * cs0.y) * sc;
                    const float p1 = (v0.x * cs0.y + v0.y * cs0.x) * sc;
                    const float p2 = (v1.x * cs1.x - v1.y * cs1.y) * sc;
                    const float p3 = (v1.x * cs1.y + v1.y * cs1.x) * sc;
                    *reinterpret_cast<uint32_t*>(Op + q0) = pack_h2(p0, p1);
                    *reinterpret_cast<uint32_t*>(Op + q1) = pack_h2(p2, p3);
                }
            }
        }
}

// ================== fused flash attention (fp16, 1-term) =====================
#define FLDA 72
#define FLDV 136
#define FQT (128*FLDA*2)                // 18432 B
#define FVT (64*FLDV*2)                 // 17408 B
#define FSTAGE (FQT + FVT)              // 35840 B
#define FA_DSM (FQT + 2*FSTAGE)         // 90112 B

__global__ void __launch_bounds__(256, 1) flash_attn(
    const __half* __restrict__ qf, const __half* __restrict__ kf,
    const __half* __restrict__ vf, __half* __restrict__ O)
{
    const int bh = blockIdx.z, b = bh >> 4, hh = bh & 15;
    const int qb = (int)(gridDim.y - 1 - blockIdx.y);
    const int bm = qb * 128;
    const int nck = qb + 1;
    extern __shared__ __align__(16) char smem[];
    const uint32_t sbQ = smem_u32(smem);
    const int tid = threadIdx.x, lane = tid & 31, wid = tid >> 5;

    const __half* Q = qf + (size_t)(b * SS) * DD + hh * HD;
    const __half* Kp = kf + (size_t)(b * SS) * DD + hh * HD;
    const __half* Vp = vf + (size_t)(bh * HD) * SS;

#define FLOADKV(st, kc2)                                                        \
    do {                                                                        \
        const int t0_ = (kc2) * 128;                                            \
        const uint32_t sk_ = sbQ + FQT + (st) * FSTAGE;                         \
        const uint32_t sv_ = sk_ + FQT;                                         \
        _Pragma("unroll")                                                       \
        for (int i_ = 0; i_ < 4; i_++) {                                        \
            const int id_ = tid + (i_ << 8);                                    \
            const int r_ = id_ >> 3, c_ = id_ & 7;                              \
            cp16(sk_ + (uint32_t)(r_ * FLDA + c_ * 8) * 2,                      \
                 Kp + (size_t)(t0_ + r_) * DD + c_ * 8);                        \
        }                                                                       \
        _Pragma("unroll")                                                       \
        for (int i_ = 0; i_ < 4; i_++) {                                        \
            const int id_ = tid + (i_ << 8);                                    \
            const int r_ = id_ >> 4, c_ = id_ & 15;                             \
            cp16(sv_ + (uint32_t)(r_ * FLDV + c_ * 8) * 2,                      \
                 Vp + (size_t)r_ * SS + t0_ + c_ * 8);                          \
        }                                                                       \
        cp_commit();                                                            \
    } while (0)

#pragma unroll
    for (int i = 0; i < 4; i++) {
        const int id = tid + (i << 8);
        const int r = id >> 3, c = id & 7;
        cp16(sbQ + (uint32_t)(r * FLDA + c * 8) * 2, Q + (size_t)(bm + r) * DD + c * 8);
    }
    FLOADKV(0, 0);

    const uint32_t lmA = (uint32_t)((lane & 15) * FLDA + (lane >> 4) * 8) * 2;
    const uint32_t lmV = (uint32_t)((lane & 15) * FLDV + (lane >> 4) * 8) * 2;
    const uint32_t aRow = (uint32_t)(wid * 16) * FLDA * 2;
    const int r0 = bm + wid * 16 + (lane >> 2);
    const int cbase = (lane & 3) * 2;

    float o[8][4] = {};
    float m0 = -INFINITY, m1 = -INFINITY, l0 = 0.f, l1 = 0.f;

    for (int kc = 0; kc < nck; kc++) {
        if (kc + 1 < nck) { FLOADKV((kc + 1) & 1, kc + 1); cp_wait<1>(); }
        else cp_wait<0>();
        __syncthreads();
        const uint32_t sk = sbQ + FQT + (kc & 1) * FSTAGE;
        const uint32_t sv = sk + FQT;

        float s[16][4] = {};
#pragma unroll
        for (int kk = 0; kk < 4; kk++) {
            const uint32_t koff = kk * 32;
            uint32_t aH[4];
            ldm4(aH, sbQ + aRow + koff + lmA);
#pragma unroll
            for (int np = 0; np < 8; np++) {
                uint32_t bH[4];
                ldm4(bH, sk + (uint32_t)(np * 16) * FLDA * 2 + koff + lmA);
                mma16816(s[2*np],   aH, bH[0], bH[2]);
                mma16816(s[2*np+1], aH, bH[1], bH[3]);
            }
        }

        if (kc == qb) {
            const int t0 = kc * 128;
#pragma unroll
            for (int j = 0; j < 16; j++) {
                const int col = t0 + j * 8 + cbase;
                if (col > r0)         s[j][0] = -INFINITY;
                if (col + 1 > r0)     s[j][1] = -INFINITY;
                if (col > r0 + 8)     s[j][2] = -INFINITY;
                if (col + 1 > r0 + 8) s[j][3] = -INFINITY;
            }
        }

        float cm0 = -INFINITY, cm1 = -INFINITY;
#pragma unroll
        for (int j = 0; j < 16; j++) {
            cm0 = fmaxf(cm0, fmaxf(s[j][0], s[j][1]));
            cm1 = fmaxf(cm1, fmaxf(s[j][2], s[j][3]));
        }
        cm0 = fmaxf(cm0, __shfl_xor_sync(0xffffffffu, cm0, 1));
        cm0 = fmaxf(cm0, __shfl_xor_sync(0xffffffffu, cm0, 2));
        cm1 = fmaxf(cm1, __shfl_xor_sync(0xffffffffu, cm1, 1));
        cm1 = fmaxf(cm1, __shfl_xor_sync(0xffffffffu, cm1, 2));
        const float nm0 = fmaxf(m0, cm0), nm1 = fmaxf(m1, cm1);
        const float f0 = __expf(m0 - nm0), f1 = __expf(m1 - nm1);
        float rs0 = 0.f, rs1 = 0.f;
#pragma unroll
        for (int j = 0; j < 16; j++) {
            s[j][0] = __expf(s[j][0] - nm0);
            s[j][1] = __expf(s[j][1] - nm0);
            s[j][2] = __expf(s[j][2] - nm1);
            s[j][3] = __expf(s[j][3] - nm1);
            rs0 += s[j][0] + s[j][1];
            rs1 += s[j][2] + s[j][3];
        }
        rs0 += __shfl_xor_sync(0xffffffffu, rs0, 1);
        rs0 += __shfl_xor_sync(0xffffffffu, rs0, 2);
        rs1 += __shfl_xor_sync(0xffffffffu, rs1, 1);
        rs1 += __shfl_xor_sync(0xffffffffu, rs1, 2);
        l0 = l0 * f0 + rs0;
        l1 = l1 * f1 + rs1;
        m0 = nm0; m1 = nm1;
#pragma unroll
        for (int nf = 0; nf < 8; nf++) {
            o[nf][0] *= f0; o[nf][1] *= f0;
            o[nf][2] *= f1; o[nf][3] *= f1;
        }

        uint32_t pH[8][4];
#pragma unroll
        for (int ks = 0; ks < 8; ks++) {
            pH[ks][0] = pack_h2(s[2*ks][0],   s[2*ks][1]);
            pH[ks][1] = pack_h2(s[2*ks][2],   s[2*ks][3]);
            pH[ks][2] = pack_h2(s[2*ks+1][0], s[2*ks+1][1]);
            pH[ks][3] = pack_h2(s[2*ks+1][2], s[2*ks+1][3]);
        }

#pragma unroll
        for (int ks = 0; ks < 8; ks++) {
            const uint32_t koff = ks * 32;
#pragma unroll
            for (int nd = 0; nd < 4; nd++) {
                uint32_t vH[4];
                ldm4(vH, sv + (uint32_t)(nd * 16) * FLDV * 2 + koff + lmV);
                mma16816(o[2*nd],   pH[ks], vH[0], vH[2]);
                mma16816(o[2*nd+1], pH[ks], vH[1], vH[3]);
            }
        }
        __syncthreads();
    }
#undef FLOADKV

    const float il0 = 1.f / l0, il1 = 1.f / l1;
#pragma unroll
    for (int nf = 0; nf < 8; nf++) {
        const int col = hh * HD + nf * 8 + cbase;
        const size_t o0 = (size_t)(b * SS + r0) * DD + col;
        const size_t o1 = o0 + (size_t)8 * DD;
        *reinterpret_cast<uint32_t*>(O + o0) = pack_h2(o[nf][0] * il0, o[nf][1] * il0);
        *reinterpret_cast<uint32_t*>(O + o1) = pack_h2(o[nf][2] * il1, o[nf][3] * il1);
    }
}

// ============== fast weight transpose: W[K,N] f32 -> Wt[N,K] f16 ==============
__global__ void __launch_bounds__(256) wconv_fast(const float* __restrict__ W,
        __half* __restrict__ Wt, int K, int N) {
    __shared__ float tile[64][65];
    const int bx = blockIdx.x * 64;   // N
    const int by = blockIdx.y * 64;   // K
    const int t = threadIdx.x;
#pragma unroll
    for (int i = 0; i < 4; i++) {
        const int lin = t + i * 256;            // float4 index, 1024 total
        const int k = lin >> 4;
        const int c4 = (lin & 15) * 4;
        const float4 v = *reinterpret_cast<const float4*>(W + (size_t)(by + k) * N + bx + c4);
        tile[k][c4 + 0] = v.x; tile[k][c4 + 1] = v.y;
        tile[k][c4 + 2] = v.z; tile[k][c4 + 3] = v.w;
    }
    __syncthreads();
    const int w = t >> 5, l = t & 31;
#pragma unroll
    for (int i = 0; i < 8; i++) {
        const int n = w * 8 + i;
        const __half2 h = __floats2half2_rn(tile[2 * l][n], tile[2 * l + 1][n]);
        *reinterpret_cast<__half2*>(Wt + (size_t)(bx + n) * K + by + 2 * l) = h;
    }
}

// ============================ rmsnorm -> fp16 ================================
__global__ void rmsnorm_fp16(const float* __restrict__ x, const float* __restrict__ w,
                             __half* __restrict__ o) {
    __shared__ float red[8];
    const int row = blockIdx.x;
    const float* xr = x + (size_t)row * DD;
    float vals[4];
    float ss = 0.f;
#pragma unroll
    for (int i = 0; i < 4; i++) {
        vals[i] = xr[threadIdx.x + i * 256];
        ss += vals[i] * vals[i];
    }
#pragma unroll
    for (int off = 16; off; off >>= 1) ss += __shfl_xor_sync(0xffffffffu, ss, off);
    if ((threadIdx.x & 31) == 0) red[threadIdx.x >> 5] = ss;
    __syncthreads();
    if (threadIdx.x < 32) {
        float s2 = (threadIdx.x < 8) ? red[threadIdx.x] : 0.f;
#pragma unroll
        for (int off = 4; off; off >>= 1) s2 += __shfl_xor_sync(0xffffffffu, s2, off);
        if (threadIdx.x == 0) red[0] = s2;
    }
    __syncthreads();
    const float rms = rsqrtf(red[0] * (1.0f / DD) + 1e-6f);
#pragma unroll
    for (int i = 0; i < 4; i++) {
        const int c = threadIdx.x + i * 256;
        o[(size_t)row * DD + c] = __float2half(vals[i] * rms * w[c]);
    }
}

// ====================== V transpose (fp16 -> fp16) ===========================
__global__ void vtrans_fp16(const __half* __restrict__ V, __half* __restrict__ vt) {
    __shared__ __half tile[32][33];
    const int bh = blockIdx.z, b = bh >> 4, hh = bh & 15;
    const int t0 = blockIdx.x * 32, d0 = blockIdx.y * 32;
    const int tx = threadIdx.x & 31, ty = threadIdx.x >> 5;
#pragma unroll
    for (int i = 0; i < 4; i++) {
        const int tt = ty + i * 8;
        tile[tt][tx] = V[(size_t)(b * SS + t0 + tt) * DD + hh * HD + d0 + tx];
    }
    __syncthreads();
#pragma unroll
    for (int i = 0; i < 4; i++) {
        const int dd = ty + i * 8;
        vt[(size_t)(bh * HD + d0 + dd) * SS + t0 + tx] = tile[tx][dd];
    }
}

// ================================= launch ====================================
extern "C" void kernel_launch(void* const* d_in, const int* in_sizes, int n_in,
                              void* d_out, int out_size) {
    const float* x   = (const float*)d_in[0];
    const float* rf  = (const float*)d_in[1];
    const float* anw = (const float*)d_in[3];
    const float* fnw = (const float*)d_in[4];
    const float* wq  = (const float*)d_in[5];
    const float* wk  = (const float*)d_in[6];
    const float* wv  = (const float*)d_in[7];
    const float* wo  = (const float*)d_in[8];
    const float* wg  = (const float*)d_in[9];
    const float* wu  = (const float*)d_in[10];
    const float* wd  = (const float*)d_in[11];
    float* out = (float*)d_out;

    __half *af, *gf, *uf, *qsh, *ksh, *vth, *vtmp;
    __half *wqkv, *wof, *wgf, *wuf, *wdf;
    cudaGetSymbolAddress((void**)&af,  g_af);
    cudaGetSymbolAddress((void**)&gf,  g_gf);
    cudaGetSymbolAddress((void**)&uf,  g_uf);
    cudaGetSymbolAddress((void**)&qsh, g_qsh);
    cudaGetSymbolAddress((void**)&ksh, g_ksh);
    cudaGetSymbolAddress((void**)&vth, g_vth);
    cudaGetSymbolAddress((void**)&vtmp, g_vtmp);
    cudaGetSymbolAddress((void**)&wqkv, g_wqkv);
    cudaGetSymbolAddress((void**)&wof, g_wo);
    cudaGetSymbolAddress((void**)&wgf, g_wg);
    cudaGetSymbolAddress((void**)&wuf, g_wu);
    cudaGetSymbolAddress((void**)&wdf, g_wd);

    cudaFuncSetAttribute(hgemm1<0>, cudaFuncAttributeMaxDynamicSharedMemorySize, HG_DSM);
    cudaFuncSetAttribute(hgemm1<2>, cudaFuncAttributeMaxDynamicSharedMemorySize, HG_DSM);
    cudaFuncSetAttribute(hgemm1<3>, cudaFuncAttributeMaxDynamicSharedMemorySize, HG_DSM);
    cudaFuncSetAttribute(hgemm1<5>, cudaFuncAttributeMaxDynamicSharedMemorySize, HG_DSM);
    cudaFuncSetAttribute(flash_attn, cudaFuncAttributeMaxDynamicSharedMemorySize, FA_DSM);

    // weight conversion (fast transpose -> fp16); q/k/v into one [3072,1024]
    wconv_fast<<<dim3(1024/64, 1024/64), 256>>>(wq, wqkv,                   1024, 1024);
    wconv_fast<<<dim3(1024/64, 1024/64), 256>>>(wk, wqkv + 1024*1024,       1024, 1024);
    wconv_fast<<<dim3(1024/64, 1024/64), 256>>>(wv, wqkv + 2*1024*1024,     1024, 1024);
    wconv_fast<<<dim3(1024/64, 1024/64), 256>>>(wo, wof, 1024, 1024);
    wconv_fast<<<dim3(4096/64, 1024/64), 256>>>(wg, wgf, 1024, 4096);
    wconv_fast<<<dim3(4096/64, 1024/64), 256>>>(wu, wuf, 1024, 4096);
    wconv_fast<<<dim3(1024/64, 4096/64), 256>>>(wd, wdf, 4096, 1024);

    // 1) attn rmsnorm -> fp16
    rmsnorm_fp16<<<TT, 256>>>(x, anw, af);
    // 2) merged QKV projection; rope fused (q scaled), v plain
    hgemm1<5><<<dim3(TT/256, 3072/128), 256, HG_DSM>>>(
        af, wqkv, rf, nullptr, nullptr, qsh, ksh, vtmp, TT, 3072, 1024);
    // 3) V transpose
    vtrans_fp16<<<dim3(SS/32, HD/32, BB*NH), 256>>>(vtmp, vth);
    // 4) fused flash attention -> fp16 attn out
    flash_attn<<<dim3(1, SS/128, BB*NH), 256, FA_DSM>>>(qsh, ksh, vth, af);
    // 5) output projection + residual
    hgemm1<0><<<dim3(TT/256, 1024/128), 256, HG_DSM>>>(
        af, wof, x, nullptr, out, nullptr, nullptr, nullptr, TT, 1024, 1024);
    // 6) ffn rmsnorm
    rmsnorm_fp16<<<TT, 256>>>(out, fnw, af);
    // 7) gate (fp16) ; up with fused silu(gate)*up -> fp16
    hgemm1<2><<<dim3(TT/256, 4096/128), 256, HG_DSM>>>(
        af, wgf, nullptr, nullptr, nullptr, gf, nullptr, nullptr, TT, 4096, 1024);
    hgemm1<3><<<dim3(TT/256, 4096/128), 256, HG_DSM>>>(
        af, wuf, nullptr, gf, nullptr, uf, nullptr, nullptr, TT, 4096, 1024);
    // 8) down projection + residual
    hgemm1<0><<<dim3(TT/256, 1024/128), 256, HG_DSM>>>(
        uf, wdf, out, nullptr, out, nullptr, nullptr, nullptr, TT, 1024, 4096);
}

// round 12
// speedup vs baseline: 5.7488x; 1.0906x over previous
#include <cuda_runtime.h>
#include <cuda_fp16.h>
#include <math.h>
#include <stdint.h>

#define BB 2
#define SS 2048
#define DD 1024
#define NH 16
#define HD 64
#define TT (BB*SS)        // 4096 tokens
#define INNER 4096

// ===================== scratch (device globals; no cudaMalloc) ===============
__device__ __align__(256) __half g_af[(size_t)TT*INNER];       // A operand
__device__ __align__(256) __half g_uf[(size_t)TT*INNER];       // silu(gate)*up
__device__ __align__(256) __half g_qsh[(size_t)TT*DD];
__device__ __align__(256) __half g_ksh[(size_t)TT*DD];
__device__ __align__(256) __half g_vth[(size_t)TT*DD];         // V^T [bh*64+d, t]
__device__ __align__(256) __half g_vtmp[(size_t)TT*DD];        // V [t, 1024]
// fp16 transposed weights [N,K]
__device__ __align__(256) __half g_wqkv[(size_t)3072*1024];    // q 0-1023, k 1024-2047, v 2048-3071
__device__ __align__(256) __half g_wo[1024*1024];
__device__ __align__(256) __half g_wgu[(size_t)8192*1024];     // interleaved: row 2n=gate_n, 2n+1=up_n
__device__ __align__(256) __half g_wd[(size_t)1024*4096];

// ============================== PTX helpers ==================================
__device__ __forceinline__ uint32_t smem_u32(const void* p) {
    uint32_t a;
    asm("{ .reg .u64 t; cvta.to.shared.u64 t, %1; cvt.u32.u64 %0, t; }" : "=r"(a) : "l"(p));
    return a;
}
__device__ __forceinline__ void cp16(uint32_t dst, const void* src) {
    asm volatile("cp.async.cg.shared.global [%0], [%1], 16;\n" :: "r"(dst), "l"(src));
}
__device__ __forceinline__ void cp_commit() { asm volatile("cp.async.commit_group;\n" ::: "memory"); }
template <int N> __device__ __forceinline__ void cp_wait() {
    asm volatile("cp.async.wait_group %0;\n" :: "n"(N) : "memory");
}
__device__ __forceinline__ void ldm4(uint32_t* r, uint32_t addr) {
    asm volatile("ldmatrix.sync.aligned.m8n8.x4.shared.b16 {%0,%1,%2,%3}, [%4];"
        : "=r"(r[0]), "=r"(r[1]), "=r"(r[2]), "=r"(r[3]) : "r"(addr));
}
__device__ __forceinline__ void mma16816(float* c, const uint32_t* a, uint32_t b0, uint32_t b1) {
    asm volatile("mma.sync.aligned.m16n8k16.row.col.f32.f16.f16.f32 "
        "{%0,%1,%2,%3}, {%4,%5,%6,%7}, {%8,%9}, {%0,%1,%2,%3};"
        : "+f"(c[0]), "+f"(c[1]), "+f"(c[2]), "+f"(c[3])
        : "r"(a[0]), "r"(a[1]), "r"(a[2]), "r"(a[3]), "r"(b0), "r"(b1));
}
__device__ __forceinline__ uint32_t pack_h2(float a, float b) {
    __half2 p = __floats2half2_rn(a, b);
    return *reinterpret_cast<uint32_t*>(&p);
}

// ================= 1-term fp16 GEMM: C = A(fp16) @ B(fp16)^T ==================
// CTA 256x128, warp 64x64 (8 warps, 4x2 m x n), KC=32. MODE epilogues:
// 0: fp32 out (+ optional residual aux)   4: interleaved silu(g)*u -> fp16 [N/2]
// 5: merged QKV (rope q/k, plain v)
#define KC 32
#define LDA 40
#define AT_B (256*LDA*2)                 // 20480 B
#define BT_B (128*LDA*2)                 // 10240 B
#define GSTG (AT_B + BT_B)               // 30720 B
#define HG_DSM (2*GSTG)                  // 61440 B

template <int MODE>
__global__ void __launch_bounds__(256, 1) hgemm1(
    const __half* __restrict__ A, const __half* __restrict__ B,
    const float* __restrict__ aux,
    float* __restrict__ OutF, __half* __restrict__ OutH,
    __half* __restrict__ OutH2, __half* __restrict__ OutH3,
    int M, int N, int K)
{
    extern __shared__ __align__(16) char smem[];
    const int tid = threadIdx.x;
    const int lane = tid & 31, wid = tid >> 5;
    const int wm = wid & 3, wn = wid >> 2;
    const int bm = blockIdx.x * 256, bn = blockIdx.y * 128;
    const uint32_t sbase = smem_u32(smem);

    float acc[4][8][4] = {};

    const int ar_[4] = { tid >> 2, (tid+256) >> 2, (tid+512) >> 2, (tid+768) >> 2 };
    const int ac_ = tid & 3;
    const int br_[2] = { tid >> 2, (tid+256) >> 2 };

#define LOAD_STAGE(st, k0)                                                     \
    do {                                                                       \
        const uint32_t sb_ = sbase + (st) * GSTG;                              \
        _Pragma("unroll")                                                      \
        for (int i_ = 0; i_ < 4; i_++)                                         \
            cp16(sb_ + (uint32_t)(ar_[i_] * LDA * 2 + ac_ * 16),               \
                 A + (size_t)(bm + ar_[i_]) * K + (k0) + ac_ * 8);             \
        _Pragma("unroll")                                                      \
        for (int i_ = 0; i_ < 2; i_++)                                         \
            cp16(sb_ + AT_B + (uint32_t)(br_[i_] * LDA * 2 + ac_ * 16),        \
                 B + (size_t)(bn + br_[i_]) * K + (k0) + ac_ * 8);             \
        cp_commit();                                                           \
    } while (0)

    const int NCK = K / KC;
    LOAD_STAGE(0, 0);
    LOAD_STAGE(1, KC);

    const uint32_t lmoff = (uint32_t)((lane & 15) * LDA + (lane >> 4) * 8) * 2;
    const uint32_t aRowOff = (uint32_t)(wm * 64) * LDA * 2;
    const uint32_t bRowOff = (uint32_t)(wn * 64) * LDA * 2;

    for (int kc = 0; kc < NCK; kc++) {
        if (kc < NCK - 1) cp_wait<1>(); else cp_wait<0>();
        __syncthreads();
        const uint32_t sb = sbase + (kc & 1) * GSTG;
#pragma unroll
        for (int kk = 0; kk < 2; kk++) {
            const uint32_t koff = kk * 32;
            uint32_t bh[4][4];
#pragma unroll
            for (int np = 0; np < 4; np++)
                ldm4(bh[np], sb + AT_B + bRowOff + (uint32_t)(np * 16) * LDA * 2 + koff + lmoff);
#pragma unroll
            for (int mf = 0; mf < 4; mf++) {
                uint32_t ah[4];
                ldm4(ah, sb + aRowOff + (uint32_t)(mf * 16) * LDA * 2 + koff + lmoff);
#pragma unroll
                for (int np = 0; np < 4; np++) {
                    mma16816(acc[mf][2*np],   ah, bh[np][0], bh[np][2]);
                    mma16816(acc[mf][2*np+1], ah, bh[np][1], bh[np][3]);
                }
            }
        }
        __syncthreads();
        if (kc + 2 < NCK) LOAD_STAGE(kc & 1, (kc + 2) * KC);
    }
#undef LOAD_STAGE

#pragma unroll
    for (int mf = 0; mf < 4; mf++)
#pragma unroll
        for (int nf = 0; nf < 8; nf++) {
            const int row0 = bm + wm * 64 + mf * 16 + (lane >> 2);
            const int col  = bn + wn * 64 + nf * 8 + (lane & 3) * 2;
            const size_t o0 = (size_t)row0 * N + col;
            const size_t o1 = o0 + (size_t)8 * N;
            float2 v0 = make_float2(acc[mf][nf][0], acc[mf][nf][1]);
            float2 v1 = make_float2(acc[mf][nf][2], acc[mf][nf][3]);
            if (MODE == 0) {
                if (aux) {
                    const float2 r0v = *reinterpret_cast<const float2*>(aux + o0);
                    const float2 r1v = *reinterpret_cast<const float2*>(aux + o1);
                    v0.x += r0v.x; v0.y += r0v.y; v1.x += r1v.x; v1.y += r1v.y;
                }
                *reinterpret_cast<float2*>(OutF + o0) = v0;
                *reinterpret_cast<float2*>(OutF + o1) = v1;
            } else if (MODE == 4) {
                // col even: v.x = gate_n, v.y = up_n with n = col/2
                const float r0f = v0.x / (1.f + __expf(-v0.x)) * v0.y;
                const float r1f = v1.x / (1.f + __expf(-v1.x)) * v1.y;
                const int n = col >> 1;
                const int NH_ = N >> 1;
                OutH[(size_t)row0 * NH_ + n]       = __float2half(r0f);
                OutH[(size_t)(row0 + 8) * NH_ + n] = __float2half(r1f);
            } else {       // MODE 5: merged QKV; rng constant per CTA
                const int rng = bn >> 10;
                const int c = col & 1023;
                const size_t q0 = (size_t)row0 * 1024 + c;
                const size_t q1 = q0 + (size_t)8 * 1024;
                if (rng == 2) {
                    *reinterpret_cast<uint32_t*>(OutH3 + q0) = pack_h2(v0.x, v0.y);
                    *reinterpret_cast<uint32_t*>(OutH3 + q1) = pack_h2(v1.x, v1.y);
                } else {
                    __half* Op = (rng == 0) ? OutH : OutH2;
                    const float sc = (rng == 0) ? 0.125f : 1.0f;
                    const int i = (c & 63) >> 1;
                    const float2 cs0 = *reinterpret_cast<const float2*>(
                        aux + ((size_t)(row0 & (SS - 1)) * 32 + i) * 2);
                    const float2 cs1 = *reinterpret_cast<const float2*>(
                        aux + ((size_t)((row0 + 8) & (SS - 1)) * 32 + i) * 2);
                    const float p0 = (v0.x * cs0.x - v0.y * cs0.y) * sc;
                    const float p1 = (v0.x * cs0.y + v0.y * cs0.x) * sc;
                    const float p2 = (v1.x * cs1.x - v1.y * cs1.y) * sc;
                    const float p3 = (v1.x * cs1.y + v1.y * cs1.x) * sc;
                    *reinterpret_cast<uint32_t*>(Op + q0) = pack_h2(p0, p1);
                    *reinterpret_cast<uint32_t*>(Op + q1) = pack_h2(p2, p3);
                }
            }
        }
}

// ================== fused flash attention (fp16, 1-term) =====================
#define FLDA 72
#define FLDV 136
#define FQT (128*FLDA*2)                // 18432 B
#define FVT (64*FLDV*2)                 // 17408 B
#define FSTAGE (FQT + FVT)              // 35840 B
#define FA_DSM (FQT + 2*FSTAGE)         // 90112 B

__global__ void __launch_bounds__(256, 1) flash_attn(
    const __half* __restrict__ qf, const __half* __restrict__ kf,
    const __half* __restrict__ vf, __half* __restrict__ O)
{
    const int bh = blockIdx.z, b = bh >> 4, hh = bh & 15;
    const int qb = (int)(gridDim.y - 1 - blockIdx.y);
    const int bm = qb * 128;
    const int nck = qb + 1;
    extern __shared__ __align__(16) char smem[];
    const uint32_t sbQ = smem_u32(smem);
    const int tid = threadIdx.x, lane = tid & 31, wid = tid >> 5;

    const __half* Q = qf + (size_t)(b * SS) * DD + hh * HD;
    const __half* Kp = kf + (size_t)(b * SS) * DD + hh * HD;
    const __half* Vp = vf + (size_t)(bh * HD) * SS;

#define FLOADKV(st, kc2)                                                        \
    do {                                                                        \
        const int t0_ = (kc2) * 128;                                            \
        const uint32_t sk_ = sbQ + FQT + (st) * FSTAGE;                         \
        const uint32_t sv_ = sk_ + FQT;                                         \
        _Pragma("unroll")                                                       \
        for (int i_ = 0; i_ < 4; i_++) {                                        \
            const int id_ = tid + (i_ << 8);                                    \
            const int r_ = id_ >> 3, c_ = id_ & 7;                              \
            cp16(sk_ + (uint32_t)(r_ * FLDA + c_ * 8) * 2,                      \
                 Kp + (size_t)(t0_ + r_) * DD + c_ * 8);                        \
        }                                                                       \
        _Pragma("unroll")                                                       \
        for (int i_ = 0; i_ < 4; i_++) {                                        \
            const int id_ = tid + (i_ << 8);                                    \
            const int r_ = id_ >> 4, c_ = id_ & 15;                             \
            cp16(sv_ + (uint32_t)(r_ * FLDV + c_ * 8) * 2,                      \
                 Vp + (size_t)r_ * SS + t0_ + c_ * 8);                          \
        }                                                                       \
        cp_commit();                                                            \
    } while (0)

#pragma unroll
    for (int i = 0; i < 4; i++) {
        const int id = tid + (i << 8);
        const int r = id >> 3, c = id & 7;
        cp16(sbQ + (uint32_t)(r * FLDA + c * 8) * 2, Q + (size_t)(bm + r) * DD + c * 8);
    }
    FLOADKV(0, 0);

    const uint32_t lmA = (uint32_t)((lane & 15) * FLDA + (lane >> 4) * 8) * 2;
    const uint32_t lmV = (uint32_t)((lane & 15) * FLDV + (lane >> 4) * 8) * 2;
    const uint32_t aRow = (uint32_t)(wid * 16) * FLDA * 2;
    const int r0 = bm + wid * 16 + (lane >> 2);
    const int cbase = (lane & 3) * 2;

    float o[8][4] = {};
    float m0 = -INFINITY, m1 = -INFINITY, l0 = 0.f, l1 = 0.f;

    for (int kc = 0; kc < nck; kc++) {
        if (kc + 1 < nck) { FLOADKV((kc + 1) & 1, kc + 1); cp_wait<1>(); }
        else cp_wait<0>();
        __syncthreads();
        const uint32_t sk = sbQ + FQT + (kc & 1) * FSTAGE;
        const uint32_t sv = sk + FQT;

        float s[16][4] = {};
#pragma unroll
        for (int kk = 0; kk < 4; kk++) {
            const uint32_t koff = kk * 32;
            uint32_t aH[4];
            ldm4(aH, sbQ + aRow + koff + lmA);
#pragma unroll
            for (int np = 0; np < 8; np++) {
                uint32_t bH[4];
                ldm4(bH, sk + (uint32_t)(np * 16) * FLDA * 2 + koff + lmA);
                mma16816(s[2*np],   aH, bH[0], bH[2]);
                mma16816(s[2*np+1], aH, bH[1], bH[3]);
            }
        }

        if (kc == qb) {
            const int t0 = kc * 128;
#pragma unroll
            for (int j = 0; j < 16; j++) {
                const int col = t0 + j * 8 + cbase;
                if (col > r0)         s[j][0] = -INFINITY;
                if (col + 1 > r0)     s[j][1] = -INFINITY;
                if (col > r0 + 8)     s[j][2] = -INFINITY;
                if (col + 1 > r0 + 8) s[j][3] = -INFINITY;
            }
        }

        float cm0 = -INFINITY, cm1 = -INFINITY;
#pragma unroll
        for (int j = 0; j < 16; j++) {
            cm0 = fmaxf(cm0, fmaxf(s[j][0], s[j][1]));
            cm1 = fmaxf(cm1, fmaxf(s[j][2], s[j][3]));
        }
        cm0 = fmaxf(cm0, __shfl_xor_sync(0xffffffffu, cm0, 1));
        cm0 = fmaxf(cm0, __shfl_xor_sync(0xffffffffu, cm0, 2));
        cm1 = fmaxf(cm1, __shfl_xor_sync(0xffffffffu, cm1, 1));
        cm1 = fmaxf(cm1, __shfl_xor_sync(0xffffffffu, cm1, 2));
        const float nm0 = fmaxf(m0, cm0), nm1 = fmaxf(m1, cm1);
        const float f0 = __expf(m0 - nm0), f1 = __expf(m1 - nm1);
        float rs0 = 0.f, rs1 = 0.f;
#pragma unroll
        for (int j = 0; j < 16; j++) {
            s[j][0] = __expf(s[j][0] - nm0);
            s[j][1] = __expf(s[j][1] - nm0);
            s[j][2] = __expf(s[j][2] - nm1);
            s[j][3] = __expf(s[j][3] - nm1);
            rs0 += s[j][0] + s[j][1];
            rs1 += s[j][2] + s[j][3];
        }
        rs0 += __shfl_xor_sync(0xffffffffu, rs0, 1);
        rs0 += __shfl_xor_sync(0xffffffffu, rs0, 2);
        rs1 += __shfl_xor_sync(0xffffffffu, rs1, 1);
        rs1 += __shfl_xor_sync(0xffffffffu, rs1, 2);
        l0 = l0 * f0 + rs0;
        l1 = l1 * f1 + rs1;
        m0 = nm0; m1 = nm1;
#pragma unroll
        for (int nf = 0; nf < 8; nf++) {
            o[nf][0] *= f0; o[nf][1] *= f0;
            o[nf][2] *= f1; o[nf][3] *= f1;
        }

        uint32_t pH[8][4];
#pragma unroll
        for (int ks = 0; ks < 8; ks++) {
            pH[ks][0] = pack_h2(s[2*ks][0],   s[2*ks][1]);
            pH[ks][1] = pack_h2(s[2*ks][2],   s[2*ks][3]);
            pH[ks][2] = pack_h2(s[2*ks+1][0], s[2*ks+1][1]);
            pH[ks][3] = pack_h2(s[2*ks+1][2], s[2*ks+1][3]);
        }

#pragma unroll
        for (int ks = 0; ks < 8; ks++) {
            const uint32_t koff = ks * 32;
#pragma unroll
            for (int nd = 0; nd < 4; nd++) {
                uint32_t vH[4];
                ldm4(vH, sv + (uint32_t)(nd * 16) * FLDV * 2 + koff + lmV);
                mma16816(o[2*nd],   pH[ks], vH[0], vH[2]);
                mma16816(o[2*nd+1], pH[ks], vH[1], vH[3]);
            }
        }
        __syncthreads();
    }
#undef FLOADKV

    const float il0 = 1.f / l0, il1 = 1.f / l1;
#pragma unroll
    for (int nf = 0; nf < 8; nf++) {
        const int col = hh * HD + nf * 8 + cbase;
        const size_t o0 = (size_t)(b * SS + r0) * DD + col;
        const size_t o1 = o0 + (size_t)8 * DD;
        *reinterpret_cast<uint32_t*>(O + o0) = pack_h2(o[nf][0] * il0, o[nf][1] * il0);
        *reinterpret_cast<uint32_t*>(O + o1) = pack_h2(o[nf][2] * il1, o[nf][3] * il1);
    }
}

// ====== weight transpose helpers: W[K,N] f32 -> Wt[rowMul*n + rowAdd, K] f16 ==
__device__ __forceinline__ void wconv_body(const float* __restrict__ W,
        __half* __restrict__ Wt, int K, int N, int rowMul, int rowAdd) {
    __shared__ float tile[64][65];
    const int bx = blockIdx.x * 64;   // N
    const int by = blockIdx.y * 64;   // K
    const int t = threadIdx.x;
#pragma unroll
    for (int i = 0; i < 4; i++) {
        const int lin = t + i * 256;
        const int k = lin >> 4;
        const int c4 = (lin & 15) * 4;
        const float4 v = *reinterpret_cast<const float4*>(W + (size_t)(by + k) * N + bx + c4);
        tile[k][c4 + 0] = v.x; tile[k][c4 + 1] = v.y;
        tile[k][c4 + 2] = v.z; tile[k][c4 + 3] = v.w;
    }
    __syncthreads();
    const int w = t >> 5, l = t & 31;
#pragma unroll
    for (int i = 0; i < 8; i++) {
        const int n = w * 8 + i;
        const __half2 h = __floats2half2_rn(tile[2 * l][n], tile[2 * l + 1][n]);
        *reinterpret_cast<__half2*>(Wt + (size_t)((bx + n) * rowMul + rowAdd) * K + by + 2 * l) = h;
    }
}

// 4 square 1024x1024 weights in one launch (z selects)
__global__ void __launch_bounds__(256) wconv_sq(
        const float* __restrict__ W0, const float* __restrict__ W1,
        const float* __restrict__ W2, const float* __restrict__ W3,
        __half* __restrict__ dqkv, __half* __restrict__ dwo) {
    const int z = blockIdx.z;
    const float* W = (z == 0) ? W0 : (z == 1) ? W1 : (z == 2) ? W2 : W3;
    __half* D = (z < 3) ? (dqkv + (size_t)z * 1024 * 1024) : dwo;
    wconv_body(W, D, 1024, 1024, 1, 0);
}
// gate+up interleaved into [8192,1024]: out row = 2n + z
__global__ void __launch_bounds__(256) wconv_gu(
        const float* __restrict__ Wg, const float* __restrict__ Wu,
        __half* __restrict__ D) {
    const int z = blockIdx.z;
    wconv_body(z == 0 ? Wg : Wu, D, 1024, 4096, 2, z);
}
__global__ void __launch_bounds__(256) wconv_one(const float* __restrict__ W,
        __half* __restrict__ D, int K, int N) {
    wconv_body(W, D, K, N, 1, 0);
}

// ============================ rmsnorm -> fp16 ================================
__global__ void rmsnorm_fp16(const float* __restrict__ x, const float* __restrict__ w,
                             __half* __restrict__ o) {
    __shared__ float red[8];
    const int row = blockIdx.x;
    const float* xr = x + (size_t)row * DD;
    float vals[4];
    float ss = 0.f;
#pragma unroll
    for (int i = 0; i < 4; i++) {
        vals[i] = xr[threadIdx.x + i * 256];
        ss += vals[i] * vals[i];
    }
#pragma unroll
    for (int off = 16; off; off >>= 1) ss += __shfl_xor_sync(0xffffffffu, ss, off);
    if ((threadIdx.x & 31) == 0) red[threadIdx.x >> 5] = ss;
    __syncthreads();
    if (threadIdx.x < 32) {
        float s2 = (threadIdx.x < 8) ? red[threadIdx.x] : 0.f;
#pragma unroll
        for (int off = 4; off; off >>= 1) s2 += __shfl_xor_sync(0xffffffffu, s2, off);
        if (threadIdx.x == 0) red[0] = s2;
    }
    __syncthreads();
    const float rms = rsqrtf(red[0] * (1.0f / DD) + 1e-6f);
#pragma unroll
    for (int i = 0; i < 4; i++) {
        const int c = threadIdx.x + i * 256;
        o[(size_t)row * DD + c] = __float2half(vals[i] * rms * w[c]);
    }
}

// ====================== V transpose (fp16 -> fp16) ===========================
__global__ void vtrans_fp16(const __half* __restrict__ V, __half* __restrict__ vt) {
    __shared__ __half tile[32][33];
    const int bh = blockIdx.z, b = bh >> 4, hh = bh & 15;
    const int t0 = blockIdx.x * 32, d0 = blockIdx.y * 32;
    const int tx = threadIdx.x & 31, ty = threadIdx.x >> 5;
#pragma unroll
    for (int i = 0; i < 4; i++) {
        const int tt = ty + i * 8;
        tile[tt][tx] = V[(size_t)(b * SS + t0 + tt) * DD + hh * HD + d0 + tx];
    }
    __syncthreads();
#pragma unroll
    for (int i = 0; i < 4; i++) {
        const int dd = ty + i * 8;
        vt[(size_t)(bh * HD + d0 + dd) * SS + t0 + tx] = tile[tx][dd];
    }
}

// ================================= launch ====================================
extern "C" void kernel_launch(void* const* d_in, const int* in_sizes, int n_in,
                              void* d_out, int out_size) {
    const float* x   = (const float*)d_in[0];
    const float* rf  = (const float*)d_in[1];
    const float* anw = (const float*)d_in[3];
    const float* fnw = (const float*)d_in[4];
    const float* wq  = (const float*)d_in[5];
    const float* wk  = (const float*)d_in[6];
    const float* wv  = (const float*)d_in[7];
    const float* wo  = (const float*)d_in[8];
    const float* wg  = (const float*)d_in[9];
    const float* wu  = (const float*)d_in[10];
    const float* wd  = (const float*)d_in[11];
    float* out = (float*)d_out;

    __half *af, *uf, *qsh, *ksh, *vth, *vtmp;
    __half *wqkv, *wof, *wguf, *wdf;
    cudaGetSymbolAddress((void**)&af,  g_af);
    cudaGetSymbolAddress((void**)&uf,  g_uf);
    cudaGetSymbolAddress((void**)&qsh, g_qsh);
    cudaGetSymbolAddress((void**)&ksh, g_ksh);
    cudaGetSymbolAddress((void**)&vth, g_vth);
    cudaGetSymbolAddress((void**)&vtmp, g_vtmp);
    cudaGetSymbolAddress((void**)&wqkv, g_wqkv);
    cudaGetSymbolAddress((void**)&wof, g_wo);
    cudaGetSymbolAddress((void**)&wguf, g_wgu);
    cudaGetSymbolAddress((void**)&wdf, g_wd);

    cudaFuncSetAttribute(hgemm1<0>, cudaFuncAttributeMaxDynamicSharedMemorySize, HG_DSM);
    cudaFuncSetAttribute(hgemm1<4>, cudaFuncAttributeMaxDynamicSharedMemorySize, HG_DSM);
    cudaFuncSetAttribute(hgemm1<5>, cudaFuncAttributeMaxDynamicSharedMemorySize, HG_DSM);
    cudaFuncSetAttribute(flash_attn, cudaFuncAttributeMaxDynamicSharedMemorySize, FA_DSM);

    // weight conversion: 3 launches total
    wconv_sq<<<dim3(1024/64, 1024/64, 4), 256>>>(wq, wk, wv, wo, wqkv, wof);
    wconv_gu<<<dim3(4096/64, 1024/64, 2), 256>>>(wg, wu, wguf);
    wconv_one<<<dim3(1024/64, 4096/64), 256>>>(wd, wdf, 4096, 1024);

    // 1) attn rmsnorm -> fp16
    rmsnorm_fp16<<<TT, 256>>>(x, anw, af);
    // 2) merged QKV projection; rope fused (q scaled), v plain
    hgemm1<5><<<dim3(TT/256, 3072/128), 256, HG_DSM>>>(
        af, wqkv, rf, nullptr, qsh, ksh, vtmp, TT, 3072, 1024);
    // 3) V transpose
    vtrans_fp16<<<dim3(SS/32, HD/32, BB*NH), 256>>>(vtmp, vth);
    // 4) fused flash attention -> fp16 attn out
    flash_attn<<<dim3(1, SS/128, BB*NH), 256, FA_DSM>>>(qsh, ksh, vth, af);
    // 5) output projection + residual
    hgemm1<0><<<dim3(TT/256, 1024/128), 256, HG_DSM>>>(
        af, wof, x, out, nullptr, nullptr, nullptr, TT, 1024, 1024);
    // 6) ffn rmsnorm
    rmsnorm_fp16<<<TT, 256>>>(out, fnw, af);
    // 7) fused gate+up (interleaved weights) -> silu(g)*u fp16
    hgemm1<4><<<dim3(TT/256, 8192/128), 256, HG_DSM>>>(
        af, wguf, nullptr, nullptr, uf, nullptr, nullptr, TT, 8192, 1024);
    // 8) down projection + residual
    hgemm1<0><<<dim3(TT/256, 1024/128), 256, HG_DSM>>>(
        uf, wdf, out, out, nullptr, nullptr, nullptr, TT, 1024, 4096);
}

// round 16
// speedup vs baseline: 5.8515x; 1.0179x over previous
#include <cuda_runtime.h>
#include <cuda_fp16.h>
#include <math.h>
#include <stdint.h>

#define BB 2
#define SS 2048
#define DD 1024
#define NH 16
#define HD 64
#define TT (BB*SS)        // 4096 tokens
#define INNER 4096

// ===================== scratch (device globals; no cudaMalloc) ===============
__device__ __align__(256) __half g_af[(size_t)TT*INNER];       // A operand
__device__ __align__(256) __half g_uf[(size_t)TT*INNER];       // silu(gate)*up
__device__ __align__(256) __half g_qsh[(size_t)TT*DD];
__device__ __align__(256) __half g_ksh[(size_t)TT*DD];
__device__ __align__(256) __half g_vth[(size_t)TT*DD];         // V^T [bh*64+d, t]
// fp16 transposed weights [N,K]
__device__ __align__(256) __half g_wqkv[(size_t)3072*1024];    // q 0-1023, k 1024-2047, v 2048-3071
__device__ __align__(256) __half g_wo[1024*1024];
__device__ __align__(256) __half g_wgu[(size_t)8192*1024];     // interleaved: row 2n=gate_n, 2n+1=up_n
__device__ __align__(256) __half g_wd[(size_t)1024*4096];

// ============================== PTX helpers ==================================
__device__ __forceinline__ uint32_t smem_u32(const void* p) {
    uint32_t a;
    asm("{ .reg .u64 t; cvta.to.shared.u64 t, %1; cvt.u32.u64 %0, t; }" : "=r"(a) : "l"(p));
    return a;
}
__device__ __forceinline__ void cp16(uint32_t dst, const void* src) {
    asm volatile("cp.async.cg.shared.global [%0], [%1], 16;\n" :: "r"(dst), "l"(src));
}
__device__ __forceinline__ void cp_commit() { asm volatile("cp.async.commit_group;\n" ::: "memory"); }
template <int N> __device__ __forceinline__ void cp_wait() {
    asm volatile("cp.async.wait_group %0;\n" :: "n"(N) : "memory");
}
__device__ __forceinline__ void ldm4(uint32_t* r, uint32_t addr) {
    asm volatile("ldmatrix.sync.aligned.m8n8.x4.shared.b16 {%0,%1,%2,%3}, [%4];"
        : "=r"(r[0]), "=r"(r[1]), "=r"(r[2]), "=r"(r[3]) : "r"(addr));
}
__device__ __forceinline__ void mma16816(float* c, const uint32_t* a, uint32_t b0, uint32_t b1) {
    asm volatile("mma.sync.aligned.m16n8k16.row.col.f32.f16.f16.f32 "
        "{%0,%1,%2,%3}, {%4,%5,%6,%7}, {%8,%9}, {%0,%1,%2,%3};"
        : "+f"(c[0]), "+f"(c[1]), "+f"(c[2]), "+f"(c[3])
        : "r"(a[0]), "r"(a[1]), "r"(a[2]), "r"(a[3]), "r"(b0), "r"(b1));
}
__device__ __forceinline__ uint32_t pack_h2(float a, float b) {
    __half2 p = __floats2half2_rn(a, b);
    return *reinterpret_cast<uint32_t*>(&p);
}

// ================= 1-term fp16 GEMM: C = A(fp16) @ B(fp16)^T ==================
// CTA 256x128, warp 64x64 (8 warps, 4x2 m x n), KC=32, 3-stage cp.async.
// MODE: 0 fp32 out (+res aux) | 4 interleaved silu(g)*u -> fp16 [N/2]
//       5 merged QKV (rope q/k; V written TRANSPOSED via smem staging)
#define KC 32
#define LDA 40
#define AT_B (256*LDA*2)                 // 20480 B
#define BT_B (128*LDA*2)                 // 10240 B
#define GSTG (AT_B + BT_B)               // 30720 B
#define HG_DSM (3*GSTG)                  // 92160 B

template <int MODE>
__global__ void __launch_bounds__(256, 1) hgemm1(
    const __half* __restrict__ A, const __half* __restrict__ B,
    const float* __restrict__ aux,
    float* __restrict__ OutF, __half* __restrict__ OutH,
    __half* __restrict__ OutH2, __half* __restrict__ OutH3,
    int M, int N, int K)
{
    extern __shared__ __align__(16) char smem[];
    const int tid = threadIdx.x;
    const int lane = tid & 31, wid = tid >> 5;
    const int wm = wid & 3, wn = wid >> 2;
    const int bm = blockIdx.x * 256, bn = blockIdx.y * 128;
    const uint32_t sbase = smem_u32(smem);

    float acc[4][8][4] = {};

    const int ar_[4] = { tid >> 2, (tid+256) >> 2, (tid+512) >> 2, (tid+768) >> 2 };
    const int ac_ = tid & 3;
    const int br_[2] = { tid >> 2, (tid+256) >> 2 };

#define LOAD_STAGE(st, k0)                                                     \
    do {                                                                       \
        const uint32_t sb_ = sbase + (st) * GSTG;                              \
        _Pragma("unroll")                                                      \
        for (int i_ = 0; i_ < 4; i_++)                                         \
            cp16(sb_ + (uint32_t)(ar_[i_] * LDA * 2 + ac_ * 16),               \
                 A + (size_t)(bm + ar_[i_]) * K + (k0) + ac_ * 8);             \
        _Pragma("unroll")                                                      \
        for (int i_ = 0; i_ < 2; i_++)                                         \
            cp16(sb_ + AT_B + (uint32_t)(br_[i_] * LDA * 2 + ac_ * 16),        \
                 B + (size_t)(bn + br_[i_]) * K + (k0) + ac_ * 8);             \
        cp_commit();                                                           \
    } while (0)

    const int NCK = K / KC;
    LOAD_STAGE(0, 0);
    LOAD_STAGE(1, KC);

    const uint32_t lmoff = (uint32_t)((lane & 15) * LDA + (lane >> 4) * 8) * 2;
    const uint32_t aRowOff = (uint32_t)(wm * 64) * LDA * 2;
    const uint32_t bRowOff = (uint32_t)(wn * 64) * LDA * 2;

    int stg = 0;                       // kc % 3
    for (int kc = 0; kc < NCK; kc++) {
        if (kc < NCK - 1) cp_wait<1>(); else cp_wait<0>();
        __syncthreads();
        if (kc + 2 < NCK) {
            int ns = stg + 2; if (ns >= 3) ns -= 3;
            LOAD_STAGE(ns, (kc + 2) * KC);
        }
        const uint32_t sb = sbase + stg * GSTG;
#pragma unroll
        for (int kk = 0; kk < 2; kk++) {
            const uint32_t koff = kk * 32;
            uint32_t bh[4][4];
#pragma unroll
            for (int np = 0; np < 4; np++)
                ldm4(bh[np], sb + AT_B + bRowOff + (uint32_t)(np * 16) * LDA * 2 + koff + lmoff);
#pragma unroll
            for (int mf = 0; mf < 4; mf++) {
                uint32_t ah[4];
                ldm4(ah, sb + aRowOff + (uint32_t)(mf * 16) * LDA * 2 + koff + lmoff);
#pragma unroll
                for (int np = 0; np < 4; np++) {
                    mma16816(acc[mf][2*np],   ah, bh[np][0], bh[np][2]);
                    mma16816(acc[mf][2*np+1], ah, bh[np][1], bh[np][3]);
                }
            }
        }
        if (++stg == 3) stg = 0;
    }
#undef LOAD_STAGE

    // ----------------- epilogues -----------------
    if (MODE == 5 && (bn >> 10) == 2) {
        // V range: transpose via smem staging, write vth[(bh*64+d)*SS + t]
        __syncthreads();                                   // smem buffers now free
        __half* tb = reinterpret_cast<__half*>(smem) + (size_t)wid * 64 * 66;
#pragma unroll
        for (int mf = 0; mf < 4; mf++)
#pragma unroll
            for (int nf = 0; nf < 8; nf++) {
                const int rl = mf * 16 + (lane >> 2);
                const int cl = nf * 8 + (lane & 3) * 2;
                *reinterpret_cast<__half2*>(&tb[rl * 66 + cl]) =
                    __floats2half2_rn(acc[mf][nf][0], acc[mf][nf][1]);
                *reinterpret_cast<__half2*>(&tb[(rl + 8) * 66 + cl]) =
                    __floats2half2_rn(acc[mf][nf][2], acc[mf][nf][3]);
            }
        __syncwarp();
        const int c0 = (bn & 1023) + wn * 64;              // head-dim col base (multiple of 64)
        const int hh = c0 >> 6;
        const int gt = bm + wm * 64;                       // global token of warp's first row
        const int b  = gt >> 11;                           // / SS
        const int s0 = gt & (SS - 1);
        const int bh = b * NH + hh;
#pragma unroll
        for (int dd = 0; dd < 2; dd++) {
            const int d = lane * 2 + dd;                   // 0..63
            __half* dst = OutH3 + (size_t)(bh * HD + d) * SS + s0;
#pragma unroll
            for (int t8 = 0; t8 < 64; t8 += 8) {
                __half tmp[8];
#pragma unroll
                for (int j = 0; j < 8; j++) tmp[j] = tb[(t8 + j) * 66 + d];
                *reinterpret_cast<uint4*>(dst + t8) = *reinterpret_cast<uint4*>(tmp);
            }
        }
        return;
    }

#pragma unroll
    for (int mf = 0; mf < 4; mf++)
#pragma unroll
        for (int nf = 0; nf < 8; nf++) {
            const int row0 = bm + wm * 64 + mf * 16 + (lane >> 2);
            const int col  = bn + wn * 64 + nf * 8 + (lane & 3) * 2;
            const size_t o0 = (size_t)row0 * N + col;
            const size_t o1 = o0 + (size_t)8 * N;
            float2 v0 = make_float2(acc[mf][nf][0], acc[mf][nf][1]);
            float2 v1 = make_float2(acc[mf][nf][2], acc[mf][nf][3]);
            if (MODE == 0) {
                if (aux) {
                    const float2 r0v = *reinterpret_cast<const float2*>(aux + o0);
                    const float2 r1v = *reinterpret_cast<const float2*>(aux + o1);
                    v0.x += r0v.x; v0.y += r0v.y; v1.x += r1v.x; v1.y += r1v.y;
                }
                *reinterpret_cast<float2*>(OutF + o0) = v0;
                *reinterpret_cast<float2*>(OutF + o1) = v1;
            } else if (MODE == 4) {
                const float r0f = v0.x / (1.f + __expf(-v0.x)) * v0.y;
                const float r1f = v1.x / (1.f + __expf(-v1.x)) * v1.y;
                const int n = col >> 1;
                const int NH_ = N >> 1;
                OutH[(size_t)row0 * NH_ + n]       = __float2half(r0f);
                OutH[(size_t)(row0 + 8) * NH_ + n] = __float2half(r1f);
            } else {       // MODE 5, rng 0/1: rope
                const int rng = bn >> 10;
                const int c = col & 1023;
                const size_t q0 = (size_t)row0 * 1024 + c;
                const size_t q1 = q0 + (size_t)8 * 1024;
                __half* Op = (rng == 0) ? OutH : OutH2;
                const float sc = (rng == 0) ? 0.125f : 1.0f;
                const int i = (c & 63) >> 1;
                const float2 cs0 = *reinterpret_cast<const float2*>(
                    aux + ((size_t)(row0 & (SS - 1)) * 32 + i) * 2);
                const float2 cs1 = *reinterpret_cast<const float2*>(
                    aux + ((size_t)((row0 + 8) & (SS - 1)) * 32 + i) * 2);
                const float p0 = (v0.x * cs0.x - v0.y * cs0.y) * sc;
                const float p1 = (v0.x * cs0.y + v0.y * cs0.x) * sc;
                const float p2 = (v1.x * cs1.x - v1.y * cs1.y) * sc;
                const float p3 = (v1.x * cs1.y + v1.y * cs1.x) * sc;
                *reinterpret_cast<uint32_t*>(Op + q0) = pack_h2(p0, p1);
                *reinterpret_cast<uint32_t*>(Op + q1) = pack_h2(p2, p3);
            }
        }
}

// ============ fused flash attention (fp16, 1-term, 3-stage KV) ===============
#define FLDA 72
#define FLDV 136
#define FQT (128*FLDA*2)                // 18432 B
#define FVT (64*FLDV*2)                 // 17408 B
#define FSTAGE (FQT + FVT)              // 35840 B
#define FA_DSM (FQT + 3*FSTAGE)         // 125952 B

__global__ void __launch_bounds__(256, 1) flash_attn(
    const __half* __restrict__ qf, const __half* __restrict__ kf,
    const __half* __restrict__ vf, __half* __restrict__ O)
{
    const int bh = blockIdx.z, b = bh >> 4, hh = bh & 15;
    const int qb = (int)(gridDim.y - 1 - blockIdx.y);
    const int bm = qb * 128;
    const int nck = qb + 1;
    extern __shared__ __align__(16) char smem[];
    const uint32_t sbQ = smem_u32(smem);
    const int tid = threadIdx.x, lane = tid & 31, wid = tid >> 5;

    const __half* Q = qf + (size_t)(b * SS) * DD + hh * HD;
    const __half* Kp = kf + (size_t)(b * SS) * DD + hh * HD;
    const __half* Vp = vf + (size_t)(bh * HD) * SS;

#define FLOADKV(st, kc2)                                                        \
    do {                                                                        \
        const int t0_ = (kc2) * 128;                                            \
        const uint32_t sk_ = sbQ + FQT + (st) * FSTAGE;                         \
        const uint32_t sv_ = sk_ + FQT;                                         \
        _Pragma("unroll")                                                       \
        for (int i_ = 0; i_ < 4; i_++) {                                        \
            const int id_ = tid + (i_ << 8);                                    \
            const int r_ = id_ >> 3, c_ = id_ & 7;                              \
            cp16(sk_ + (uint32_t)(r_ * FLDA + c_ * 8) * 2,                      \
                 Kp + (size_t)(t0_ + r_) * DD + c_ * 8);                        \
        }                                                                       \
        _Pragma("unroll")                                                       \
        for (int i_ = 0; i_ < 4; i_++) {                                        \
            const int id_ = tid + (i_ << 8);                                    \
            const int r_ = id_ >> 4, c_ = id_ & 15;                             \
            cp16(sv_ + (uint32_t)(r_ * FLDV + c_ * 8) * 2,                      \
                 Vp + (size_t)r_ * SS + t0_ + c_ * 8);                          \
        }                                                                       \
        cp_commit();                                                            \
    } while (0)

#pragma unroll
    for (int i = 0; i < 4; i++) {
        const int id = tid + (i << 8);
        const int r = id >> 3, c = id & 7;
        cp16(sbQ + (uint32_t)(r * FLDA + c * 8) * 2, Q + (size_t)(bm + r) * DD + c * 8);
    }
    FLOADKV(0, 0);                     // group 1 = Q + chunk0
    if (nck > 1) FLOADKV(1, 1);        // group 2

    const uint32_t lmA = (uint32_t)((lane & 15) * FLDA + (lane >> 4) * 8) * 2;
    const uint32_t lmV = (uint32_t)((lane & 15) * FLDV + (lane >> 4) * 8) * 2;
    const uint32_t aRow = (uint32_t)(wid * 16) * FLDA * 2;
    const int r0 = bm + wid * 16 + (lane >> 2);
    const int cbase = (lane & 3) * 2;

    float o[8][4] = {};
    float m0 = -INFINITY, m1 = -INFINITY, l0 = 0.f, l1 = 0.f;

    int stg = 0;
    for (int kc = 0; kc < nck; kc++) {
        if (kc < nck - 1) cp_wait<1>(); else cp_wait<0>();
        __syncthreads();
        if (kc + 2 < nck) {
            int ns = stg + 2; if (ns >= 3) ns -= 3;
            FLOADKV(ns, kc + 2);
        }
        const uint32_t sk = sbQ + FQT + stg * FSTAGE;
        const uint32_t sv = sk + FQT;

        float s[16][4] = {};
#pragma unroll
        for (int kk = 0; kk < 4; kk++) {
            const uint32_t koff = kk * 32;
            uint32_t aH[4];
            ldm4(aH, sbQ + aRow + koff + lmA);
#pragma unroll
            for (int np = 0; np < 8; np++) {
                uint32_t bH[4];
                ldm4(bH, sk + (uint32_t)(np * 16) * FLDA * 2 + koff + lmA);
                mma16816(s[2*np],   aH, bH[0], bH[2]);
                mma16816(s[2*np+1], aH, bH[1], bH[3]);
            }
        }

        if (kc == qb) {
            const int t0 = kc * 128;
#pragma unroll
            for (int j = 0; j < 16; j++) {
                const int col = t0 + j * 8 + cbase;
                if (col > r0)         s[j][0] = -INFINITY;
                if (col + 1 > r0)     s[j][1] = -INFINITY;
                if (col > r0 + 8)     s[j][2] = -INFINITY;
                if (col + 1 > r0 + 8) s[j][3] = -INFINITY;
            }
        }

        float cm0 = -INFINITY, cm1 = -INFINITY;
#pragma unroll
        for (int j = 0; j < 16; j++) {
            cm0 = fmaxf(cm0, fmaxf(s[j][0], s[j][1]));
            cm1 = fmaxf(cm1, fmaxf(s[j][2], s[j][3]));
        }
        cm0 = fmaxf(cm0, __shfl_xor_sync(0xffffffffu, cm0, 1));
        cm0 = fmaxf(cm0, __shfl_xor_sync(0xffffffffu, cm0, 2));
        cm1 = fmaxf(cm1, __shfl_xor_sync(0xffffffffu, cm1, 1));
        cm1 = fmaxf(cm1, __shfl_xor_sync(0xffffffffu, cm1, 2));
        const float nm0 = fmaxf(m0, cm0), nm1 = fmaxf(m1, cm1);
        const float f0 = __expf(m0 - nm0), f1 = __expf(m1 - nm1);
        float rs0 = 0.f, rs1 = 0.f;
#pragma unroll
        for (int j = 0; j < 16; j++) {
            s[j][0] = __expf(s[j][0] - nm0);
            s[j][1] = __expf(s[j][1] - nm0);
            s[j][2] = __expf(s[j][2] - nm1);
            s[j][3] = __expf(s[j][3] - nm1);
            rs0 += s[j][0] + s[j][1];
            rs1 += s[j][2] + s[j][3];
        }
        rs0 += __shfl_xor_sync(0xffffffffu, rs0, 1);
        rs0 += __shfl_xor_sync(0xffffffffu, rs0, 2);
        rs1 += __shfl_xor_sync(0xffffffffu, rs1, 1);
        rs1 += __shfl_xor_sync(0xffffffffu, rs1, 2);
        l0 = l0 * f0 + rs0;
        l1 = l1 * f1 + rs1;
        m0 = nm0; m1 = nm1;
#pragma unroll
        for (int nf = 0; nf < 8; nf++) {
            o[nf][0] *= f0; o[nf][1] *= f0;
            o[nf][2] *= f1; o[nf][3] *= f1;
        }

        uint32_t pH[8][4];
#pragma unroll
        for (int ks = 0; ks < 8; ks++) {
            pH[ks][0] = pack_h2(s[2*ks][0],   s[2*ks][1]);
            pH[ks][1] = pack_h2(s[2*ks][2],   s[2*ks][3]);
            pH[ks][2] = pack_h2(s[2*ks+1][0], s[2*ks+1][1]);
            pH[ks][3] = pack_h2(s[2*ks+1][2], s[2*ks+1][3]);
        }

#pragma unroll
        for (int ks = 0; ks < 8; ks++) {
            const uint32_t koff = ks * 32;
#pragma unroll
            for (int nd = 0; nd < 4; nd++) {
                uint32_t vH[4];
                ldm4(vH, sv + (uint32_t)(nd * 16) * FLDV * 2 + koff + lmV);
                mma16816(o[2*nd],   pH[ks], vH[0], vH[2]);
                mma16816(o[2*nd+1], pH[ks], vH[1], vH[3]);
            }
        }
        if (++stg == 3) stg = 0;
    }
#undef FLOADKV

    const float il0 = 1.f / l0, il1 = 1.f / l1;
#pragma unroll
    for (int nf = 0; nf < 8; nf++) {
        const int col = hh * HD + nf * 8 + cbase;
        const size_t o0 = (size_t)(b * SS + r0) * DD + col;
        const size_t o1 = o0 + (size_t)8 * DD;
        *reinterpret_cast<uint32_t*>(O + o0) = pack_h2(o[nf][0] * il0, o[nf][1] * il0);
        *reinterpret_cast<uint32_t*>(O + o1) = pack_h2(o[nf][2] * il1, o[nf][3] * il1);
    }
}

// ====== weight transpose helpers: W[K,N] f32 -> Wt[rowMul*n + rowAdd, K] f16 ==
__device__ __forceinline__ void wconv_body(const float* __restrict__ W,
        __half* __restrict__ Wt, int K, int N, int rowMul, int rowAdd) {
    __shared__ float tile[64][65];
    const int bx = blockIdx.x * 64;   // N
    const int by = blockIdx.y * 64;   // K
    const int t = threadIdx.x;
#pragma unroll
    for (int i = 0; i < 4; i++) {
        const int lin = t + i * 256;
        const int k = lin >> 4;
        const int c4 = (lin & 15) * 4;
        const float4 v = *reinterpret_cast<const float4*>(W + (size_t)(by + k) * N + bx + c4);
        tile[k][c4 + 0] = v.x; tile[k][c4 + 1] = v.y;
        tile[k][c4 + 2] = v.z; tile[k][c4 + 3] = v.w;
    }
    __syncthreads();
    const int w = t >> 5, l = t & 31;
#pragma unroll
    for (int i = 0; i < 8; i++) {
        const int n = w * 8 + i;
        const __half2 h = __floats2half2_rn(tile[2 * l][n], tile[2 * l + 1][n]);
        *reinterpret_cast<__half2*>(Wt + (size_t)((bx + n) * rowMul + rowAdd) * K + by + 2 * l) = h;
    }
}

__global__ void __launch_bounds__(256) wconv_sq(
        const float* __restrict__ W0, const float* __restrict__ W1,
        const float* __restrict__ W2, const float* __restrict__ W3,
        __half* __restrict__ dqkv, __half* __restrict__ dwo) {
    const int z = blockIdx.z;
    const float* W = (z == 0) ? W0 : (z == 1) ? W1 : (z == 2) ? W2 : W3;
    __half* D = (z < 3) ? (dqkv + (size_t)z * 1024 * 1024) : dwo;
    wconv_body(W, D, 1024, 1024, 1, 0);
}
__global__ void __launch_bounds__(256) wconv_gu(
        const float* __restrict__ Wg, const float* __restrict__ Wu,
        __half* __restrict__ D) {
    const int z = blockIdx.z;
    wconv_body(z == 0 ? Wg : Wu, D, 1024, 4096, 2, z);
}
__global__ void __launch_bounds__(256) wconv_one(const float* __restrict__ W,
        __half* __restrict__ D, int K, int N) {
    wconv_body(W, D, K, N, 1, 0);
}

// ============================ rmsnorm -> fp16 ================================
__global__ void rmsnorm_fp16(const float* __restrict__ x, const float* __restrict__ w,
                             __half* __restrict__ o) {
    __shared__ float red[8];
    const int row = blockIdx.x;
    const float* xr = x + (size_t)row * DD;
    float vals[4];
    float ss = 0.f;
#pragma unroll
    for (int i = 0; i < 4; i++) {
        vals[i] = xr[threadIdx.x + i * 256];
        ss += vals[i] * vals[i];
    }
#pragma unroll
    for (int off = 16; off; off >>= 1) ss += __shfl_xor_sync(0xffffffffu, ss, off);
    if ((threadIdx.x & 31) == 0) red[threadIdx.x >> 5] = ss;
    __syncthreads();
    if (threadIdx.x < 32) {
        float s2 = (threadIdx.x < 8) ? red[threadIdx.x] : 0.f;
#pragma unroll
        for (int off = 4; off; off >>= 1) s2 += __shfl_xor_sync(0xffffffffu, s2, off);
        if (threadIdx.x == 0) red[0] = s2;
    }
    __syncthreads();
    const float rms = rsqrtf(red[0] * (1.0f / DD) + 1e-6f);
#pragma unroll
    for (int i = 0; i < 4; i++) {
        const int c = threadIdx.x + i * 256;
        o[(size_t)row * DD + c] = __float2half(vals[i] * rms * w[c]);
    }
}

// ================================= launch ====================================
extern "C" void kernel_launch(void* const* d_in, const int* in_sizes, int n_in,
                              void* d_out, int out_size) {
    const float* x   = (const float*)d_in[0];
    const float* rf  = (const float*)d_in[1];
    const float* anw = (const float*)d_in[3];
    const float* fnw = (const float*)d_in[4];
    const float* wq  = (const float*)d_in[5];
    const float* wk  = (const float*)d_in[6];
    const float* wv  = (const float*)d_in[7];
    const float* wo  = (const float*)d_in[8];
    const float* wg  = (const float*)d_in[9];
    const float* wu  = (const float*)d_in[10];
    const float* wd  = (const float*)d_in[11];
    float* out = (float*)d_out;

    __half *af, *uf, *qsh, *ksh, *vth;
    __half *wqkv, *wof, *wguf, *wdf;
    cudaGetSymbolAddress((void**)&af,  g_af);
    cudaGetSymbolAddress((void**)&uf,  g_uf);
    cudaGetSymbolAddress((void**)&qsh, g_qsh);
    cudaGetSymbolAddress((void**)&ksh, g_ksh);
    cudaGetSymbolAddress((void**)&vth, g_vth);
    cudaGetSymbolAddress((void**)&wqkv, g_wqkv);
    cudaGetSymbolAddress((void**)&wof, g_wo);
    cudaGetSymbolAddress((void**)&wguf, g_wgu);
    cudaGetSymbolAddress((void**)&wdf, g_wd);

    cudaFuncSetAttribute(hgemm1<0>, cudaFuncAttributeMaxDynamicSharedMemorySize, HG_DSM);
    cudaFuncSetAttribute(hgemm1<4>, cudaFuncAttributeMaxDynamicSharedMemorySize, HG_DSM);
    cudaFuncSetAttribute(hgemm1<5>, cudaFuncAttributeMaxDynamicSharedMemorySize, HG_DSM);
    cudaFuncSetAttribute(flash_attn, cudaFuncAttributeMaxDynamicSharedMemorySize, FA_DSM);

    // weight conversion: 3 launches
    wconv_sq<<<dim3(1024/64, 1024/64, 4), 256>>>(wq, wk, wv, wo, wqkv, wof);
    wconv_gu<<<dim3(4096/64, 1024/64, 2), 256>>>(wg, wu, wguf);
    wconv_one<<<dim3(1024/64, 4096/64), 256>>>(wd, wdf, 4096, 1024);

    // 1) attn rmsnorm -> fp16
    rmsnorm_fp16<<<TT, 256>>>(x, anw, af);
    // 2) merged QKV projection; rope fused (q scaled), V written transposed
    hgemm1<5><<<dim3(TT/256, 3072/128), 256, HG_DSM>>>(
        af, wqkv, rf, nullptr, qsh, ksh, vth, TT, 3072, 1024);
    // 3) fused flash attention -> fp16 attn out
    flash_attn<<<dim3(1, SS/128, BB*NH), 256, FA_DSM>>>(qsh, ksh, vth, af);
    // 4) output projection + residual
    hgemm1<0><<<dim3(TT/256, 1024/128), 256, HG_DSM>>>(
        af, wof, x, out, nullptr, nullptr, nullptr, TT, 1024, 1024);
    // 5) ffn rmsnorm
    rmsnorm_fp16<<<TT, 256>>>(out, fnw, af);
    // 6) fused gate+up (interleaved weights) -> silu(g)*u fp16
    hgemm1<4><<<dim3(TT/256, 8192/128), 256, HG_DSM>>>(
        af, wguf, nullptr, nullptr, uf, nullptr, nullptr, TT, 8192, 1024);
    // 7) down projection + residual
    hgemm1<0><<<dim3(TT/256, 1024/128), 256, HG_DSM>>>(
        uf, wdf, out, out, nullptr, nullptr, nullptr, TT, 1024, 4096);
}